// round 1
// baseline (speedup 1.0000x reference)
#include <cuda_runtime.h>
#include <math.h>

#define BB 2
#define SS 2048
#define HH 1024
#define NH 16
#define HD 64
#define BS (BB*SS)   // 4096
#define BH (BB*NH)   // 32

// Scratch (allocation-free: static device globals)
__device__ float d_q[(size_t)BS*HH];
__device__ float d_k[(size_t)BS*HH];
__device__ float d_v[(size_t)BS*HH];
__device__ float d_g[BS];
__device__ float d_p[BS];
__device__ float d_sc[(size_t)BH*SS*SS];   // 512 MB scores/probs

// ---------------------------------------------------------------------------
// Gate: g = sigmoid(X @ Wg + bg), p = (S-2)^(1-g)
// ---------------------------------------------------------------------------
__global__ __launch_bounds__(256) void gate_kernel(const float* __restrict__ X,
                                                   const float* __restrict__ Wg,
                                                   const float* __restrict__ bg,
                                                   float* __restrict__ g,
                                                   float* __restrict__ p) {
    int row = blockIdx.x;
    int tid = threadIdx.x;
    float4 xv = *(const float4*)(X + (size_t)row*HH + tid*4);
    float4 wv = *(const float4*)(Wg + tid*4);
    float s = xv.x*wv.x + xv.y*wv.y + xv.z*wv.z + xv.w*wv.w;
    __shared__ float red[256];
    red[tid] = s; __syncthreads();
    for (int off = 128; off > 0; off >>= 1) {
        if (tid < off) red[tid] += red[tid+off];
        __syncthreads();
    }
    if (tid == 0) {
        float z = red[0] + bg[0];
        float gg = 1.f / (1.f + expf(-z));
        g[row] = gg;
        p[row] = powf((float)(SS-2), 1.f - gg);
    }
}

// ---------------------------------------------------------------------------
// Shared micro-kernel: 128x64 tile, BK=16, 256 threads, 8x4 per thread
// ---------------------------------------------------------------------------
__device__ __forceinline__ void mma16(const float (*As)[128], const float (*Bs)[64],
                                      float acc[8][4], int ty, int tx) {
#pragma unroll
    for (int k = 0; k < 16; k++) {
        float4 a0 = *(const float4*)&As[k][ty*8];
        float4 a1 = *(const float4*)&As[k][ty*8+4];
        float4 b4 = *(const float4*)&Bs[k][tx*4];
        float aa[8] = {a0.x,a0.y,a0.z,a0.w,a1.x,a1.y,a1.z,a1.w};
        float bb[4] = {b4.x,b4.y,b4.z,b4.w};
#pragma unroll
        for (int i2 = 0; i2 < 8; i2++)
#pragma unroll
            for (int j2 = 0; j2 < 4; j2++)
                acc[i2][j2] = fmaf(aa[i2], bb[j2], acc[i2][j2]);
    }
}

// A-tile loader: 128 rows x 16 cols from row-major A (stride lda), transposed store
__device__ __forceinline__ void loadA(float (*As)[128], const float* __restrict__ A,
                                      size_t lda, int rowBase, int kk, int tid) {
#pragma unroll
    for (int l = 0; l < 2; l++) {
        int f = tid + l*256;
        int r = f >> 2, c4 = f & 3;
        float4 av = *(const float4*)(A + (size_t)(rowBase + r)*lda + kk + c4*4);
        As[c4*4+0][r] = av.x; As[c4*4+1][r] = av.y;
        As[c4*4+2][r] = av.z; As[c4*4+3][r] = av.w;
    }
}

// ---------------------------------------------------------------------------
// Projection GEMM: C[4096,1024] = A[4096,1024] @ W[1024,1024] + bias
// ---------------------------------------------------------------------------
__global__ __launch_bounds__(256) void gemm_proj(const float* __restrict__ A,
                                                 const float* __restrict__ W,
                                                 const float* __restrict__ bias,
                                                 float* __restrict__ C) {
    __shared__ float As[16][128];
    __shared__ float Bs[16][64];
    const int tid = threadIdx.x;
    const int tx = tid & 15, ty = tid >> 4;
    const int rowBase = blockIdx.y * 128;
    const int colBase = blockIdx.x * 64;
    float acc[8][4] = {};
    for (int kk = 0; kk < HH; kk += 16) {
        loadA(As, A, HH, rowBase, kk, tid);
        {
            int br = tid >> 4, bc4 = tid & 15;
            *(float4*)&Bs[br][bc4*4] =
                *(const float4*)(W + (size_t)(kk+br)*HH + colBase + bc4*4);
        }
        __syncthreads();
        mma16(As, Bs, acc, ty, tx);
        __syncthreads();
    }
    float4 bv = *(const float4*)(bias + colBase + tx*4);
#pragma unroll
    for (int i = 0; i < 8; i++) {
        float4 o = {acc[i][0]+bv.x, acc[i][1]+bv.y, acc[i][2]+bv.z, acc[i][3]+bv.w};
        *(float4*)(C + (size_t)(rowBase + ty*8 + i)*HH + colBase + tx*4) = o;
    }
}

// ---------------------------------------------------------------------------
// Scores: SC[bh][i][j] = (1/8) * sum_d Q[b,i,h*64+d] * K[b,j,h*64+d]
// ---------------------------------------------------------------------------
__global__ __launch_bounds__(256) void gemm_qk(const float* __restrict__ Q,
                                               const float* __restrict__ Km,
                                               float* __restrict__ SC) {
    const int bh = blockIdx.z;
    const int b = bh >> 4, h = bh & 15;
    const float* Ab = Q  + (size_t)b*SS*HH + h*HD;
    const float* Bb = Km + (size_t)b*SS*HH + h*HD;
    float* Cb = SC + (size_t)bh*SS*SS;
    __shared__ float As[16][128];
    __shared__ float Bs[16][64];
    const int tid = threadIdx.x;
    const int tx = tid & 15, ty = tid >> 4;
    const int iBase = blockIdx.y * 128;
    const int jBase = blockIdx.x * 64;
    float acc[8][4] = {};
    for (int kk = 0; kk < HD; kk += 16) {
        loadA(As, Ab, HH, iBase, kk, tid);
        {   // B tile: 64 key-rows x 16 d-cols, transposed store
            int r = tid >> 2, c4 = tid & 3;
            float4 bvv = *(const float4*)(Bb + (size_t)(jBase + r)*HH + kk + c4*4);
            Bs[c4*4+0][r] = bvv.x; Bs[c4*4+1][r] = bvv.y;
            Bs[c4*4+2][r] = bvv.z; Bs[c4*4+3][r] = bvv.w;
        }
        __syncthreads();
        mma16(As, Bs, acc, ty, tx);
        __syncthreads();
    }
#pragma unroll
    for (int i = 0; i < 8; i++) {
        float4 o = {acc[i][0]*0.125f, acc[i][1]*0.125f, acc[i][2]*0.125f, acc[i][3]*0.125f};
        *(float4*)(Cb + (size_t)(iBase + ty*8 + i)*SS + jBase + tx*4) = o;
    }
}

// ---------------------------------------------------------------------------
// Softmax with granularity-gate penalty, in-place on SC rows
// ---------------------------------------------------------------------------
__global__ __launch_bounds__(256) void softmax_kernel(float* __restrict__ SC,
                                                      const float* __restrict__ g,
                                                      const float* __restrict__ p) {
    const int i  = blockIdx.x;
    const int bh = blockIdx.y;
    const int b  = bh >> 4;
    float* row = SC + (size_t)bh*SS*SS + (size_t)i*SS;
    const float* gb = g + (size_t)b*SS;
    __shared__ float sv[SS];
    __shared__ float red[256];
    const int tid = threadIdx.x;
    const float gi = gb[i];
    const float pi = p[(size_t)b*SS + i];
    const float one_m = 1.f - gi;

    float lmax = -1e30f;
    for (int j = tid; j < SS; j += 256) {
        float gj = gb[j];
        float res = one_m * fmaxf(one_m - gj, 0.f) + gi * fminf(one_m + gj, 1.f);
        float scope = fminf(fmaxf(pi + 2.f - fabsf((float)(i - j)), 1e-32f), 1.f);
        float v = row[j] + logf(fmaxf(res * scope, 1e-32f));
        sv[j] = v;
        lmax = fmaxf(lmax, v);
    }
    red[tid] = lmax; __syncthreads();
    for (int off = 128; off > 0; off >>= 1) {
        if (tid < off) red[tid] = fmaxf(red[tid], red[tid+off]);
        __syncthreads();
    }
    const float m = red[0];
    __syncthreads();

    float lsum = 0.f;
    for (int j = tid; j < SS; j += 256) {
        float e = expf(sv[j] - m);
        sv[j] = e;
        lsum += e;
    }
    red[tid] = lsum; __syncthreads();
    for (int off = 128; off > 0; off >>= 1) {
        if (tid < off) red[tid] += red[tid+off];
        __syncthreads();
    }
    const float inv = 1.f / red[0];
    for (int j = tid; j < SS; j += 256)
        row[j] = sv[j] * inv;
}

// ---------------------------------------------------------------------------
// PV: O[b,i,h*64+d] = sum_j P[bh][i][j] * V[b,j,h*64+d]
// ---------------------------------------------------------------------------
__global__ __launch_bounds__(256) void gemm_pv(const float* __restrict__ SC,
                                               const float* __restrict__ V,
                                               float* __restrict__ O) {
    const int bh = blockIdx.z;
    const int b = bh >> 4, h = bh & 15;
    const float* P  = SC + (size_t)bh*SS*SS;
    const float* Vb = V  + (size_t)b*SS*HH + h*HD;
    float* Ob = O + (size_t)b*SS*HH + h*HD;
    __shared__ float As[16][128];
    __shared__ float Bs[16][64];
    const int tid = threadIdx.x;
    const int tx = tid & 15, ty = tid >> 4;
    const int iBase = blockIdx.y * 128;
    float acc[8][4] = {};
    for (int kk = 0; kk < SS; kk += 16) {
        loadA(As, P, SS, iBase, kk, tid);
        {
            int br = tid >> 4, bc4 = tid & 15;
            *(float4*)&Bs[br][bc4*4] =
                *(const float4*)(Vb + (size_t)(kk+br)*HH + bc4*4);
        }
        __syncthreads();
        mma16(As, Bs, acc, ty, tx);
        __syncthreads();
    }
#pragma unroll
    for (int i = 0; i < 8; i++) {
        float4 o = {acc[i][0], acc[i][1], acc[i][2], acc[i][3]};
        *(float4*)(Ob + (size_t)(iBase + ty*8 + i)*HH + tx*4) = o;
    }
}

// ---------------------------------------------------------------------------
extern "C" void kernel_launch(void* const* d_in, const int* in_sizes, int n_in,
                              void* d_out, int out_size) {
    const float* X  = (const float*)d_in[0];
    const float* Wq = (const float*)d_in[1];
    const float* bq = (const float*)d_in[2];
    const float* Wk = (const float*)d_in[3];
    const float* bk = (const float*)d_in[4];
    const float* Wv = (const float*)d_in[5];
    const float* bv = (const float*)d_in[6];
    const float* Wg = (const float*)d_in[7];
    const float* bg = (const float*)d_in[8];
    float* out = (float*)d_out;

    float *q, *k, *v, *g, *p, *sc;
    cudaGetSymbolAddress((void**)&q,  d_q);
    cudaGetSymbolAddress((void**)&k,  d_k);
    cudaGetSymbolAddress((void**)&v,  d_v);
    cudaGetSymbolAddress((void**)&g,  d_g);
    cudaGetSymbolAddress((void**)&p,  d_p);
    cudaGetSymbolAddress((void**)&sc, d_sc);

    gate_kernel<<<BS, 256>>>(X, Wg, bg, g, p);

    dim3 gp(HH/64, BS/128);                 // (16, 32)
    gemm_proj<<<gp, 256>>>(X, Wq, bq, q);
    gemm_proj<<<gp, 256>>>(X, Wk, bk, k);
    gemm_proj<<<gp, 256>>>(X, Wv, bv, v);

    dim3 gqk(SS/64, SS/128, BH);            // (32, 16, 32)
    gemm_qk<<<gqk, 256>>>(q, k, sc);

    dim3 gsm(SS, BH);                       // (2048, 32)
    softmax_kernel<<<gsm, 256>>>(sc, g, p);

    dim3 gpv(1, SS/128, BH);                // (1, 16, 32)
    gemm_pv<<<gpv, 256>>>(sc, v, out);
}

// round 3
// speedup vs baseline: 2.1566x; 2.1566x over previous
#include <cuda_runtime.h>
#include <math.h>
#include <stdint.h>

#define BB 2
#define SS 2048
#define HH 1024
#define NH 16
#define HD 64
#define BS (BB*SS)   // 4096
#define BH (BB*NH)   // 32

// Scratch (allocation-free: static device globals)
__device__ float d_q[(size_t)BS*HH];
__device__ float d_k[(size_t)BS*HH];
__device__ float d_v[(size_t)BS*HH];
__device__ float d_x[(size_t)BS*HH];   // tf32-rounded X
__device__ float d_w[(size_t)HH*HH];   // tf32-rounded weight (reused per proj)
__device__ float d_g[BS];
__device__ float d_p[BS];
__device__ float d_sc[(size_t)BH*SS*SS];   // 512 MB scores/probs

// ---------------------------------------------------------------------------
// helpers
// ---------------------------------------------------------------------------
__device__ __forceinline__ float rna_tf32(float x){
    uint32_t y;  // cvt.*.tf32 requires .b32 destination
    asm("cvt.rna.tf32.f32 %0, %1;" : "=r"(y) : "f"(x));
    return __uint_as_float(y);
}
__device__ __forceinline__ void cp16(uint32_t dst, const float* src){
    asm volatile("cp.async.cg.shared.global [%0], [%1], 16;" :: "r"(dst), "l"(src));
}
__device__ __forceinline__ void cp_commit(){ asm volatile("cp.async.commit_group;"); }
template<int N> __device__ __forceinline__ void cp_wait(){
    asm volatile("cp.async.wait_group %0;" :: "n"(N));
}
__device__ __forceinline__ void mma8(float* c, const uint32_t* a, const uint32_t* b){
    asm volatile("mma.sync.aligned.m16n8k8.row.col.f32.tf32.tf32.f32 "
        "{%0,%1,%2,%3}, {%4,%5,%6,%7}, {%8,%9}, {%0,%1,%2,%3};"
        : "+f"(c[0]),"+f"(c[1]),"+f"(c[2]),"+f"(c[3])
        : "r"(a[0]),"r"(a[1]),"r"(a[2]),"r"(a[3]), "r"(b[0]),"r"(b[1]));
}

// ---------------------------------------------------------------------------
// tf32 rounding pass (elementwise, float4)
// ---------------------------------------------------------------------------
__global__ __launch_bounds__(256) void round_kernel(const float4* __restrict__ src,
                                                    float4* __restrict__ dst, int n4){
    int i = blockIdx.x*256 + threadIdx.x;
    if (i < n4){
        float4 v = src[i];
        v.x = rna_tf32(v.x); v.y = rna_tf32(v.y);
        v.z = rna_tf32(v.z); v.w = rna_tf32(v.w);
        dst[i] = v;
    }
}

// ---------------------------------------------------------------------------
// Gate: g = sigmoid(X @ Wg + bg), p = (S-2)^(1-g)   (fp32 path)
// ---------------------------------------------------------------------------
__global__ __launch_bounds__(256) void gate_kernel(const float* __restrict__ X,
                                                   const float* __restrict__ Wg,
                                                   const float* __restrict__ bg,
                                                   float* __restrict__ g,
                                                   float* __restrict__ p) {
    int row = blockIdx.x;
    int tid = threadIdx.x;
    float4 xv = *(const float4*)(X + (size_t)row*HH + tid*4);
    float4 wv = *(const float4*)(Wg + tid*4);
    float s = xv.x*wv.x + xv.y*wv.y + xv.z*wv.z + xv.w*wv.w;
    __shared__ float red[256];
    red[tid] = s; __syncthreads();
    for (int off = 128; off > 0; off >>= 1) {
        if (tid < off) red[tid] += red[tid+off];
        __syncthreads();
    }
    if (tid == 0) {
        float z = red[0] + bg[0];
        float gg = 1.f / (1.f + expf(-z));
        g[row] = gg;
        p[row] = powf((float)(SS-2), 1.f - gg);
    }
}

// ---------------------------------------------------------------------------
// Unified tf32 tensor-core GEMM.
// BM=128, BK=32 fixed; 256 threads = 8 warps.
// BNK=true : B smem stored [n][k]  (B rows contiguous along k in gmem)
// BNK=false: B smem stored [k][n]  (B rows contiguous along n in gmem)
// EPI: 0 = +bias, rna-round (proj)   1 = *0.125 (qk)   2 = plain (pv)
// Batch offset (z): base + (z>>4)*so + (z&15)*si for A,B,C.
// ---------------------------------------------------------------------------
template<int BN, int WM, int WN, bool BNK, int EPI>
__global__ __launch_bounds__(256, 2) void gemm_tf32(
    const float* __restrict__ Aall, const float* __restrict__ Ball,
    const float* __restrict__ bias, float* __restrict__ Call,
    int lda, int ldb, int ldc, int Kdim,
    size_t soA, size_t siA, size_t soB, size_t siB, size_t soC, size_t siC)
{
    const int z = blockIdx.z;
    const float* A  = Aall + (size_t)(z>>4)*soA + (size_t)(z&15)*siA;
    const float* Bp = Ball + (size_t)(z>>4)*soB + (size_t)(z&15)*siB;
    float* C = Call + (size_t)(z>>4)*soC + (size_t)(z&15)*siC;

    constexpr int BM = 128, BK = 32;
    constexpr int ASTR = BK + 4;                       // 36 (conflict-free frags)
    constexpr int BSTR = BNK ? (BK + 4) : (BN + 4);
    constexpr int ASZ = BM * ASTR;
    constexpr int BSZ = BNK ? BN * (BK + 4) : BK * (BN + 4);
    extern __shared__ float smf[];
    float* Asm[2] = { smf, smf + ASZ };
    float* Bsm[2] = { smf + 2*ASZ, smf + 2*ASZ + BSZ };

    const int tid = threadIdx.x, lane = tid & 31, wid = tid >> 5;
    constexpr int NWN = BN / WN;
    const int wm = wid / NWN, wn = wid % NWN;
    constexpr int MT = WM / 16, NT = WN / 8;

    const int iBase = blockIdx.y * BM;
    const int jBase = blockIdx.x * BN;

    float acc[MT][NT][4] = {};

    auto loadA = [&](int s, int kk){
        uint32_t base = (uint32_t)__cvta_generic_to_shared(Asm[s]);
        #pragma unroll
        for (int i = 0; i < (BM*8)/256; i++){
            int f = tid + i*256;
            int r = f >> 3, c = (f & 7) * 4;
            cp16(base + (uint32_t)(r*ASTR + c)*4u, A + (size_t)(iBase + r)*lda + kk + c);
        }
    };
    auto loadB = [&](int s, int kk){
        uint32_t base = (uint32_t)__cvta_generic_to_shared(Bsm[s]);
        if constexpr (BNK){
            #pragma unroll
            for (int i = 0; i < (BN*8)/256; i++){
                int f = tid + i*256;
                int n = f >> 3, c = (f & 7) * 4;
                cp16(base + (uint32_t)(n*BSTR + c)*4u, Bp + (size_t)(jBase + n)*ldb + kk + c);
            }
        } else {
            #pragma unroll
            for (int i = 0; i < (BK*(BN/4))/256; i++){
                int f = tid + i*256;
                int k = f / (BN/4), c = (f % (BN/4)) * 4;
                cp16(base + (uint32_t)(k*BSTR + c)*4u, Bp + (size_t)(kk + k)*ldb + jBase + c);
            }
        }
    };

    loadA(0, 0); loadB(0, 0); cp_commit();
    const int nK = Kdim / BK;
    for (int kt = 0; kt < nK; kt++){
        const int cur = kt & 1;
        if (kt + 1 < nK){
            loadA(cur ^ 1, (kt+1)*BK); loadB(cur ^ 1, (kt+1)*BK);
            cp_commit(); cp_wait<1>();
        } else {
            cp_wait<0>();
        }
        __syncthreads();
        const float* As = Asm[cur];
        const float* Bs = Bsm[cur];
        #pragma unroll
        for (int ks = 0; ks < BK/8; ks++){
            uint32_t af[MT][4]; uint32_t bf[NT][2];
            #pragma unroll
            for (int mt = 0; mt < MT; mt++){
                int r0 = wm*WM + mt*16 + (lane >> 2);
                int c0 = ks*8 + (lane & 3);
                af[mt][0] = __float_as_uint(As[r0*ASTR + c0]);
                af[mt][1] = __float_as_uint(As[(r0+8)*ASTR + c0]);
                af[mt][2] = __float_as_uint(As[r0*ASTR + c0 + 4]);
                af[mt][3] = __float_as_uint(As[(r0+8)*ASTR + c0 + 4]);
            }
            #pragma unroll
            for (int nt = 0; nt < NT; nt++){
                int n = wn*WN + nt*8 + (lane >> 2);
                int k0 = ks*8 + (lane & 3);
                if constexpr (BNK){
                    bf[nt][0] = __float_as_uint(Bs[n*BSTR + k0]);
                    bf[nt][1] = __float_as_uint(Bs[n*BSTR + k0 + 4]);
                } else {
                    bf[nt][0] = __float_as_uint(Bs[k0*BSTR + n]);
                    bf[nt][1] = __float_as_uint(Bs[(k0+4)*BSTR + n]);
                }
            }
            #pragma unroll
            for (int mt = 0; mt < MT; mt++)
                #pragma unroll
                for (int nt = 0; nt < NT; nt++)
                    mma8(acc[mt][nt], af[mt], bf[nt]);
        }
        __syncthreads();
    }

    // epilogue
    #pragma unroll
    for (int mt = 0; mt < MT; mt++){
        int r0 = iBase + wm*WM + mt*16 + (lane >> 2);
        #pragma unroll
        for (int nt = 0; nt < NT; nt++){
            int c0 = jBase + wn*WN + nt*8 + 2*(lane & 3);
            float v0 = acc[mt][nt][0], v1 = acc[mt][nt][1];
            float v2 = acc[mt][nt][2], v3 = acc[mt][nt][3];
            if constexpr (EPI == 0){
                float b0 = __ldg(bias + c0), b1 = __ldg(bias + c0 + 1);
                v0 = rna_tf32(v0 + b0); v1 = rna_tf32(v1 + b1);
                v2 = rna_tf32(v2 + b0); v3 = rna_tf32(v3 + b1);
            } else if constexpr (EPI == 1){
                v0 *= 0.125f; v1 *= 0.125f; v2 *= 0.125f; v3 *= 0.125f;
            }
            float2 p0 = {v0, v1}, p1 = {v2, v3};
            *(float2*)(C + (size_t)r0*ldc + c0)     = p0;
            *(float2*)(C + (size_t)(r0+8)*ldc + c0) = p1;
        }
    }
}

// ---------------------------------------------------------------------------
// Softmax with multiplicative penalty (no logf): for pen <= 1,
// softmax(s + log(max(pen,1e-32))) == pen_cl * exp(s - max s) / sum.
// Output rna-rounded to tf32 for the PV tensor-core GEMM.
// ---------------------------------------------------------------------------
__global__ __launch_bounds__(256) void softmax_kernel(float* __restrict__ SC,
                                                      const float* __restrict__ g,
                                                      const float* __restrict__ p) {
    const int i  = blockIdx.x;
    const int bh = blockIdx.y;
    const int b  = bh >> 4;
    float* row = SC + (size_t)bh*SS*SS + (size_t)i*SS;
    const float* gb = g + (size_t)b*SS;
    __shared__ float sv[SS];
    __shared__ float red[256];
    const int tid = threadIdx.x;
    const float gi = gb[i];
    const float pi = p[(size_t)b*SS + i];
    const float one_m = 1.f - gi;

    float lmax = -1e30f;
    for (int j = tid; j < SS; j += 256) {
        float s = row[j];
        sv[j] = s;
        lmax = fmaxf(lmax, s);
    }
    red[tid] = lmax; __syncthreads();
    for (int off = 128; off > 0; off >>= 1) {
        if (tid < off) red[tid] = fmaxf(red[tid], red[tid+off]);
        __syncthreads();
    }
    const float m = red[0];
    __syncthreads();

    float lsum = 0.f;
    for (int j = tid; j < SS; j += 256) {
        float gj = gb[j];
        float res = one_m * fmaxf(one_m - gj, 0.f) + gi * fminf(one_m + gj, 1.f);
        float scope = fminf(fmaxf(pi + 2.f - fabsf((float)(i - j)), 1e-32f), 1.f);
        float pen = fmaxf(res * scope, 1e-32f);
        float t = pen * __expf(sv[j] - m);
        sv[j] = t;
        lsum += t;
    }
    red[tid] = lsum; __syncthreads();
    for (int off = 128; off > 0; off >>= 1) {
        if (tid < off) red[tid] += red[tid+off];
        __syncthreads();
    }
    const float inv = 1.f / red[0];
    for (int j = tid; j < SS; j += 256)
        row[j] = rna_tf32(sv[j] * inv);
}

// ---------------------------------------------------------------------------
extern "C" void kernel_launch(void* const* d_in, const int* in_sizes, int n_in,
                              void* d_out, int out_size) {
    const float* X  = (const float*)d_in[0];
    const float* Wq = (const float*)d_in[1];
    const float* bq = (const float*)d_in[2];
    const float* Wk = (const float*)d_in[3];
    const float* bk = (const float*)d_in[4];
    const float* Wv = (const float*)d_in[5];
    const float* bv = (const float*)d_in[6];
    const float* Wg = (const float*)d_in[7];
    const float* bg = (const float*)d_in[8];
    float* out = (float*)d_out;

    float *q, *k, *v, *x, *w, *g, *p, *sc;
    cudaGetSymbolAddress((void**)&q,  d_q);
    cudaGetSymbolAddress((void**)&k,  d_k);
    cudaGetSymbolAddress((void**)&v,  d_v);
    cudaGetSymbolAddress((void**)&x,  d_x);
    cudaGetSymbolAddress((void**)&w,  d_w);
    cudaGetSymbolAddress((void**)&g,  d_g);
    cudaGetSymbolAddress((void**)&p,  d_p);
    cudaGetSymbolAddress((void**)&sc, d_sc);

    // smem opt-in (idempotent, capture-safe)
    constexpr int SM_PROJ = 2*(128*36 + 32*132)*4;   // 70656
    constexpr int SM_QK   = 2*(128*36 + 128*36)*4;   // 73728
    constexpr int SM_PV   = 2*(128*36 + 32*68)*4;    // 54272
    cudaFuncSetAttribute(gemm_tf32<128,64,32,false,0>,
                         cudaFuncAttributeMaxDynamicSharedMemorySize, SM_PROJ);
    cudaFuncSetAttribute(gemm_tf32<128,64,32,true,1>,
                         cudaFuncAttributeMaxDynamicSharedMemorySize, SM_QK);
    cudaFuncSetAttribute(gemm_tf32<64,32,32,false,2>,
                         cudaFuncAttributeMaxDynamicSharedMemorySize, SM_PV);

    // round X once; gate uses original fp32 X
    round_kernel<<<(BS*HH/4 + 255)/256, 256>>>((const float4*)X, (float4*)x, BS*HH/4);
    gate_kernel<<<BS, 256>>>(X, Wg, bg, g, p);

    dim3 gp(HH/128, BS/128, 1);   // (8, 32)
    round_kernel<<<(HH*HH/4 + 255)/256, 256>>>((const float4*)Wq, (float4*)w, HH*HH/4);
    gemm_tf32<128,64,32,false,0><<<gp, 256, SM_PROJ>>>(x, w, bq, q,
        HH, HH, HH, HH, 0,0, 0,0, 0,0);
    round_kernel<<<(HH*HH/4 + 255)/256, 256>>>((const float4*)Wk, (float4*)w, HH*HH/4);
    gemm_tf32<128,64,32,false,0><<<gp, 256, SM_PROJ>>>(x, w, bk, k,
        HH, HH, HH, HH, 0,0, 0,0, 0,0);
    round_kernel<<<(HH*HH/4 + 255)/256, 256>>>((const float4*)Wv, (float4*)w, HH*HH/4);
    gemm_tf32<128,64,32,false,0><<<gp, 256, SM_PROJ>>>(x, w, bv, v,
        HH, HH, HH, HH, 0,0, 0,0, 0,0);

    // scores = Q K^T / 8
    dim3 gqk(SS/128, SS/128, BH);  // (16, 16, 32)
    gemm_tf32<128,64,32,true,1><<<gqk, 256, SM_QK>>>(q, k, nullptr, sc,
        HH, HH, SS, HD,
        (size_t)SS*HH, (size_t)HD,
        (size_t)SS*HH, (size_t)HD,
        (size_t)16*SS*SS, (size_t)SS*SS);

    dim3 gsm(SS, BH);
    softmax_kernel<<<gsm, 256>>>(sc, g, p);

    // ctx = P V
    dim3 gpv(1, SS/128, BH);       // (1, 16, 32)
    gemm_tf32<64,32,32,false,2><<<gpv, 256, SM_PV>>>(sc, v, nullptr, out,
        SS, HH, HH, SS,
        (size_t)16*SS*SS, (size_t)SS*SS,
        (size_t)SS*HH, (size_t)HD,
        (size_t)SS*HH, (size_t)HD);
}

// round 4
// speedup vs baseline: 3.8639x; 1.7917x over previous
#include <cuda_runtime.h>
#include <math.h>
#include <stdint.h>

#define BB 2
#define SS 2048
#define HH 1024
#define NH 16
#define HD 64
#define BS (BB*SS)   // 4096
#define BH (BB*NH)   // 32

// Scratch (allocation-free: static device globals)
__device__ float d_q[(size_t)BS*HH];
__device__ float d_k[(size_t)BS*HH];
__device__ float d_v[(size_t)BS*HH];
__device__ float d_x[(size_t)BS*HH];   // tf32-rounded X
__device__ float d_w[(size_t)HH*HH];   // tf32-rounded weight (reused per proj)
__device__ float d_g[BS];
__device__ float d_p[BS];

// ---------------------------------------------------------------------------
// helpers
// ---------------------------------------------------------------------------
__device__ __forceinline__ float rna_tf32(float x){
    uint32_t y;  // cvt.*.tf32 requires .b32 destination
    asm("cvt.rna.tf32.f32 %0, %1;" : "=r"(y) : "f"(x));
    return __uint_as_float(y);
}
__device__ __forceinline__ void cp16(uint32_t dst, const float* src){
    asm volatile("cp.async.cg.shared.global [%0], [%1], 16;" :: "r"(dst), "l"(src));
}
__device__ __forceinline__ void cp_commit(){ asm volatile("cp.async.commit_group;"); }
template<int N> __device__ __forceinline__ void cp_wait(){
    asm volatile("cp.async.wait_group %0;" :: "n"(N));
}
__device__ __forceinline__ void mma8(float* c, const uint32_t* a, const uint32_t* b){
    asm volatile("mma.sync.aligned.m16n8k8.row.col.f32.tf32.tf32.f32 "
        "{%0,%1,%2,%3}, {%4,%5,%6,%7}, {%8,%9}, {%0,%1,%2,%3};"
        : "+f"(c[0]),"+f"(c[1]),"+f"(c[2]),"+f"(c[3])
        : "r"(a[0]),"r"(a[1]),"r"(a[2]),"r"(a[3]), "r"(b[0]),"r"(b[1]));
}

// ---------------------------------------------------------------------------
// tf32 rounding pass (elementwise, float4)
// ---------------------------------------------------------------------------
__global__ __launch_bounds__(256) void round_kernel(const float4* __restrict__ src,
                                                    float4* __restrict__ dst, int n4){
    int i = blockIdx.x*256 + threadIdx.x;
    if (i < n4){
        float4 v = src[i];
        v.x = rna_tf32(v.x); v.y = rna_tf32(v.y);
        v.z = rna_tf32(v.z); v.w = rna_tf32(v.w);
        dst[i] = v;
    }
}

// ---------------------------------------------------------------------------
// Gate: g = sigmoid(X @ Wg + bg), p = (S-2)^(1-g)   (fp32 path)
// ---------------------------------------------------------------------------
__global__ __launch_bounds__(256) void gate_kernel(const float* __restrict__ X,
                                                   const float* __restrict__ Wg,
                                                   const float* __restrict__ bg,
                                                   float* __restrict__ g,
                                                   float* __restrict__ p) {
    int row = blockIdx.x;
    int tid = threadIdx.x;
    float4 xv = *(const float4*)(X + (size_t)row*HH + tid*4);
    float4 wv = *(const float4*)(Wg + tid*4);
    float s = xv.x*wv.x + xv.y*wv.y + xv.z*wv.z + xv.w*wv.w;
    __shared__ float red[256];
    red[tid] = s; __syncthreads();
    for (int off = 128; off > 0; off >>= 1) {
        if (tid < off) red[tid] += red[tid+off];
        __syncthreads();
    }
    if (tid == 0) {
        float z = red[0] + bg[0];
        float gg = 1.f / (1.f + expf(-z));
        g[row] = gg;
        p[row] = powf((float)(SS-2), 1.f - gg);
    }
}

// ---------------------------------------------------------------------------
// tf32 tensor-core GEMM for the projections (same as R3, EPI 0 only).
// C[4096,1024] = A @ W + bias, rna-rounded output.
// ---------------------------------------------------------------------------
template<int BN, int WM, int WN>
__global__ __launch_bounds__(256, 2) void gemm_proj(
    const float* __restrict__ A, const float* __restrict__ Bp,
    const float* __restrict__ bias, float* __restrict__ C)
{
    constexpr int BM = 128, BK = 32;
    constexpr int ASTR = BK + 4;
    constexpr int BSTR = BN + 4;
    constexpr int ASZ = BM * ASTR;
    constexpr int BSZ = BK * BSTR;
    extern __shared__ float smf[];
    float* Asm[2] = { smf, smf + ASZ };
    float* Bsm[2] = { smf + 2*ASZ, smf + 2*ASZ + BSZ };

    const int tid = threadIdx.x, lane = tid & 31, wid = tid >> 5;
    constexpr int NWN = BN / WN;
    const int wm = wid / NWN, wn = wid % NWN;
    constexpr int MT = WM / 16, NT = WN / 8;

    const int iBase = blockIdx.y * BM;
    const int jBase = blockIdx.x * BN;

    float acc[MT][NT][4] = {};

    auto loadA = [&](int s, int kk){
        uint32_t base = (uint32_t)__cvta_generic_to_shared(Asm[s]);
        #pragma unroll
        for (int i = 0; i < (BM*8)/256; i++){
            int f = tid + i*256;
            int r = f >> 3, c = (f & 7) * 4;
            cp16(base + (uint32_t)(r*ASTR + c)*4u, A + (size_t)(iBase + r)*HH + kk + c);
        }
    };
    auto loadB = [&](int s, int kk){
        uint32_t base = (uint32_t)__cvta_generic_to_shared(Bsm[s]);
        #pragma unroll
        for (int i = 0; i < (BK*(BN/4))/256; i++){
            int f = tid + i*256;
            int k = f / (BN/4), c = (f % (BN/4)) * 4;
            cp16(base + (uint32_t)(k*BSTR + c)*4u, Bp + (size_t)(kk + k)*HH + jBase + c);
        }
    };

    loadA(0, 0); loadB(0, 0); cp_commit();
    const int nK = HH / BK;
    for (int kt = 0; kt < nK; kt++){
        const int cur = kt & 1;
        if (kt + 1 < nK){
            loadA(cur ^ 1, (kt+1)*BK); loadB(cur ^ 1, (kt+1)*BK);
            cp_commit(); cp_wait<1>();
        } else {
            cp_wait<0>();
        }
        __syncthreads();
        const float* As = Asm[cur];
        const float* Bs = Bsm[cur];
        #pragma unroll
        for (int ks = 0; ks < BK/8; ks++){
            uint32_t af[MT][4]; uint32_t bf[NT][2];
            #pragma unroll
            for (int mt = 0; mt < MT; mt++){
                int r0 = wm*WM + mt*16 + (lane >> 2);
                int c0 = ks*8 + (lane & 3);
                af[mt][0] = __float_as_uint(As[r0*ASTR + c0]);
                af[mt][1] = __float_as_uint(As[(r0+8)*ASTR + c0]);
                af[mt][2] = __float_as_uint(As[r0*ASTR + c0 + 4]);
                af[mt][3] = __float_as_uint(As[(r0+8)*ASTR + c0 + 4]);
            }
            #pragma unroll
            for (int nt = 0; nt < NT; nt++){
                int n = wn*WN + nt*8 + (lane >> 2);
                int k0 = ks*8 + (lane & 3);
                bf[nt][0] = __float_as_uint(Bs[k0*BSTR + n]);
                bf[nt][1] = __float_as_uint(Bs[(k0+4)*BSTR + n]);
            }
            #pragma unroll
            for (int mt = 0; mt < MT; mt++)
                #pragma unroll
                for (int nt = 0; nt < NT; nt++)
                    mma8(acc[mt][nt], af[mt], bf[nt]);
        }
        __syncthreads();
    }

    #pragma unroll
    for (int mt = 0; mt < MT; mt++){
        int r0 = iBase + wm*WM + mt*16 + (lane >> 2);
        #pragma unroll
        for (int nt = 0; nt < NT; nt++){
            int c0 = jBase + wn*WN + nt*8 + 2*(lane & 3);
            float b0 = __ldg(bias + c0), b1 = __ldg(bias + c0 + 1);
            float2 p0 = { rna_tf32(acc[mt][nt][0] + b0), rna_tf32(acc[mt][nt][1] + b1) };
            float2 p1 = { rna_tf32(acc[mt][nt][2] + b0), rna_tf32(acc[mt][nt][3] + b1) };
            *(float2*)(C + (size_t)r0*HH + c0)     = p0;
            *(float2*)(C + (size_t)(r0+8)*HH + c0) = p1;
        }
    }
}

// ---------------------------------------------------------------------------
// Fused flash attention: QK^T -> online softmax (multiplicative penalty) -> PV
// Grid (SS/128, BH). 256 threads = 8 warps; warp w owns rows [16w, 16w+16).
// Q tile resident; K/V tiles double-buffered cp.async; P passes to the PV mma
// via quad shuffles (C-fragment -> A-fragment layout), no smem round-trip.
// ---------------------------------------------------------------------------
#define QSTR 68
#define VSTR 72

__device__ __forceinline__ float penexp(float om, float gi, float pi, int i,
                                        float gj, int j, float se){
    float res = om * fmaxf(om - gj, 0.f) + gi * fminf(om + gj, 1.f);
    float scope = fminf(fmaxf(pi + 2.f - fabsf((float)(i - j)), 1e-32f), 1.f);
    float pen = fmaxf(res * scope, 1e-32f);
    return pen * __expf(se);
}

__global__ __launch_bounds__(256) void attn_fused(
    const float* __restrict__ Q, const float* __restrict__ Kg,
    const float* __restrict__ Vg, const float* __restrict__ g,
    const float* __restrict__ p, float* __restrict__ out)
{
    const int bh = blockIdx.y, b = bh >> 4, h = bh & 15;
    const int iBase = blockIdx.x * 128;
    const int tid = threadIdx.x, lane = tid & 31, wid = tid >> 5;

    extern __shared__ float sm[];
    float* Qs  = sm;                      // 128*68
    float* Ks0 = Qs  + 128*QSTR;          // 2 x 128*68
    float* Vs0 = Ks0 + 2*128*QSTR;        // 2 x 128*72
    float* gs  = Vs0 + 2*128*VSTR;        // 2048

    const float* Qp = Q  + (size_t)b*SS*HH + h*HD;
    const float* Kp = Kg + (size_t)b*SS*HH + h*HD;
    const float* Vp = Vg + (size_t)b*SS*HH + h*HD;

    // prologue loads: Q tile, g row, K0/V0  (all in cp.async group 0)
    {
        uint32_t qb = (uint32_t)__cvta_generic_to_shared(Qs);
        #pragma unroll
        for (int l = 0; l < 8; l++){
            int f = tid + l*256;
            int r = f >> 4, c4 = f & 15;
            cp16(qb + (uint32_t)(r*QSTR + c4*4)*4u, Qp + (size_t)(iBase + r)*HH + c4*4);
        }
        uint32_t gb = (uint32_t)__cvta_generic_to_shared(gs);
        #pragma unroll
        for (int l = 0; l < 2; l++){
            int f = tid + l*256;
            cp16(gb + (uint32_t)f*16u, g + (size_t)b*SS + f*4);
        }
    }
    auto loadK = [&](int s, int j0){
        uint32_t kb = (uint32_t)__cvta_generic_to_shared(Ks0 + s*128*QSTR);
        #pragma unroll
        for (int l = 0; l < 8; l++){
            int f = tid + l*256;
            int r = f >> 4, c4 = f & 15;
            cp16(kb + (uint32_t)(r*QSTR + c4*4)*4u, Kp + (size_t)(j0 + r)*HH + c4*4);
        }
    };
    auto loadV = [&](int s, int j0){
        uint32_t vb = (uint32_t)__cvta_generic_to_shared(Vs0 + s*128*VSTR);
        #pragma unroll
        for (int l = 0; l < 8; l++){
            int f = tid + l*256;
            int r = f >> 4, c4 = f & 15;
            cp16(vb + (uint32_t)(r*VSTR + c4*4)*4u, Vp + (size_t)(j0 + r)*HH + c4*4);
        }
    };
    loadK(0, 0); loadV(0, 0); cp_commit();

    const int lr0 = wid*16 + (lane >> 2);    // local row in tile
    const int lr1 = lr0 + 8;
    const int i0 = iBase + lr0, i1 = iBase + lr1;
    const float gi0 = __ldg(g + (size_t)b*SS + i0);
    const float gi1 = __ldg(g + (size_t)b*SS + i1);
    const float pi0 = __ldg(p + (size_t)b*SS + i0);
    const float pi1 = __ldg(p + (size_t)b*SS + i1);
    const float om0 = 1.f - gi0, om1 = 1.f - gi1;

    float m0 = -1e30f, m1 = -1e30f, l0 = 0.f, l1 = 0.f;
    float oacc[8][4] = {};

    const int q = lane & 3;
    const int basel = lane & 28;
    const int src0 = basel | (q >> 1);
    const int src2 = src0 + 2;

    for (int jt = 0; jt < 16; jt++){
        const int cur = jt & 1;
        if (jt + 1 < 16){
            loadK(cur ^ 1, (jt+1)*128); loadV(cur ^ 1, (jt+1)*128);
            cp_commit(); cp_wait<1>();
        } else {
            cp_wait<0>();
        }
        __syncthreads();
        const float* Ks = Ks0 + cur*128*QSTR;
        const float* Vs = Vs0 + cur*128*VSTR;
        const int jBase = jt*128;

        // --- S = Q K^T (raw, scale folded later) ---
        float sacc[16][4];
        #pragma unroll
        for (int nt = 0; nt < 16; nt++){
            sacc[nt][0]=0.f; sacc[nt][1]=0.f; sacc[nt][2]=0.f; sacc[nt][3]=0.f;
        }
        #pragma unroll
        for (int ks = 0; ks < 8; ks++){
            const int kk = ks*8 + q;
            uint32_t af[4];
            af[0] = __float_as_uint(Qs[lr0*QSTR + kk]);
            af[1] = __float_as_uint(Qs[lr1*QSTR + kk]);
            af[2] = __float_as_uint(Qs[lr0*QSTR + kk + 4]);
            af[3] = __float_as_uint(Qs[lr1*QSTR + kk + 4]);
            #pragma unroll
            for (int nt = 0; nt < 16; nt++){
                const int n = nt*8 + (lane >> 2);
                uint32_t bf[2];
                bf[0] = __float_as_uint(Ks[n*QSTR + kk]);
                bf[1] = __float_as_uint(Ks[n*QSTR + kk + 4]);
                mma8(sacc[nt], af, bf);
            }
        }

        // --- online softmax ---
        float tm0 = -1e30f, tm1 = -1e30f;
        #pragma unroll
        for (int nt = 0; nt < 16; nt++){
            tm0 = fmaxf(tm0, fmaxf(sacc[nt][0], sacc[nt][1]));
            tm1 = fmaxf(tm1, fmaxf(sacc[nt][2], sacc[nt][3]));
        }
        tm0 = fmaxf(tm0, __shfl_xor_sync(0xffffffffu, tm0, 1));
        tm0 = fmaxf(tm0, __shfl_xor_sync(0xffffffffu, tm0, 2));
        tm1 = fmaxf(tm1, __shfl_xor_sync(0xffffffffu, tm1, 1));
        tm1 = fmaxf(tm1, __shfl_xor_sync(0xffffffffu, tm1, 2));
        tm0 *= 0.125f; tm1 *= 0.125f;
        const float m0n = fmaxf(m0, tm0), m1n = fmaxf(m1, tm1);
        const float f0 = __expf(m0 - m0n), f1 = __expf(m1 - m1n);
        m0 = m0n; m1 = m1n;
        l0 *= f0; l1 *= f1;
        #pragma unroll
        for (int dn = 0; dn < 8; dn++){
            oacc[dn][0] *= f0; oacc[dn][1] *= f0;
            oacc[dn][2] *= f1; oacc[dn][3] *= f1;
        }
        float rs0 = 0.f, rs1 = 0.f;
        #pragma unroll
        for (int nt = 0; nt < 16; nt++){
            const int j0 = jBase + nt*8 + 2*q;
            const int j1 = j0 + 1;
            const float gj0 = gs[j0], gj1 = gs[j1];
            float t00 = penexp(om0, gi0, pi0, i0, gj0, j0, sacc[nt][0]*0.125f - m0);
            float t01 = penexp(om0, gi0, pi0, i0, gj1, j1, sacc[nt][1]*0.125f - m0);
            float t10 = penexp(om1, gi1, pi1, i1, gj0, j0, sacc[nt][2]*0.125f - m1);
            float t11 = penexp(om1, gi1, pi1, i1, gj1, j1, sacc[nt][3]*0.125f - m1);
            sacc[nt][0] = t00; sacc[nt][1] = t01;
            sacc[nt][2] = t10; sacc[nt][3] = t11;
            rs0 += t00 + t01; rs1 += t10 + t11;
        }
        rs0 += __shfl_xor_sync(0xffffffffu, rs0, 1);
        rs0 += __shfl_xor_sync(0xffffffffu, rs0, 2);
        rs1 += __shfl_xor_sync(0xffffffffu, rs1, 1);
        rs1 += __shfl_xor_sync(0xffffffffu, rs1, 2);
        l0 += rs0; l1 += rs1;

        // --- O += P V : quad-shuffle C-frag -> A-frag, then mma over d ---
        #pragma unroll
        for (int kc = 0; kc < 16; kc++){
            float x0 = __shfl_sync(0xffffffffu, sacc[kc][0], src0);
            float x1 = __shfl_sync(0xffffffffu, sacc[kc][1], src0);
            float y0 = __shfl_sync(0xffffffffu, sacc[kc][0], src2);
            float y1 = __shfl_sync(0xffffffffu, sacc[kc][1], src2);
            float z0 = __shfl_sync(0xffffffffu, sacc[kc][2], src0);
            float z1 = __shfl_sync(0xffffffffu, sacc[kc][3], src0);
            float w0 = __shfl_sync(0xffffffffu, sacc[kc][2], src2);
            float w1 = __shfl_sync(0xffffffffu, sacc[kc][3], src2);
            const bool odd = (q & 1);
            uint32_t af[4];
            af[0] = __float_as_uint(rna_tf32(odd ? x1 : x0));  // (r0, q)
            af[1] = __float_as_uint(rna_tf32(odd ? z1 : z0));  // (r1, q)
            af[2] = __float_as_uint(rna_tf32(odd ? y1 : y0));  // (r0, q+4)
            af[3] = __float_as_uint(rna_tf32(odd ? w1 : w0));  // (r1, q+4)
            const int kb = kc*8 + q;
            #pragma unroll
            for (int dn = 0; dn < 8; dn++){
                const int d0 = dn*8 + (lane >> 2);
                uint32_t bf[2];
                bf[0] = __float_as_uint(Vs[kb*VSTR + d0]);
                bf[1] = __float_as_uint(Vs[(kb+4)*VSTR + d0]);
                mma8(oacc[dn], af, bf);
            }
        }
        __syncthreads();
    }

    // epilogue
    const float inv0 = 1.f / l0, inv1 = 1.f / l1;
    float* op = out + (size_t)b*SS*HH + h*HD;
    #pragma unroll
    for (int dn = 0; dn < 8; dn++){
        const int c0 = dn*8 + 2*q;
        float2 o0 = { oacc[dn][0]*inv0, oacc[dn][1]*inv0 };
        float2 o1 = { oacc[dn][2]*inv1, oacc[dn][3]*inv1 };
        *(float2*)(op + (size_t)(iBase + lr0)*HH + c0) = o0;
        *(float2*)(op + (size_t)(iBase + lr1)*HH + c0) = o1;
    }
}

// ---------------------------------------------------------------------------
extern "C" void kernel_launch(void* const* d_in, const int* in_sizes, int n_in,
                              void* d_out, int out_size) {
    const float* X  = (const float*)d_in[0];
    const float* Wq = (const float*)d_in[1];
    const float* bq = (const float*)d_in[2];
    const float* Wk = (const float*)d_in[3];
    const float* bk = (const float*)d_in[4];
    const float* Wv = (const float*)d_in[5];
    const float* bv = (const float*)d_in[6];
    const float* Wg = (const float*)d_in[7];
    const float* bg = (const float*)d_in[8];
    float* out = (float*)d_out;

    float *q, *k, *v, *x, *w, *g, *p;
    cudaGetSymbolAddress((void**)&q,  d_q);
    cudaGetSymbolAddress((void**)&k,  d_k);
    cudaGetSymbolAddress((void**)&v,  d_v);
    cudaGetSymbolAddress((void**)&x,  d_x);
    cudaGetSymbolAddress((void**)&w,  d_w);
    cudaGetSymbolAddress((void**)&g,  d_g);
    cudaGetSymbolAddress((void**)&p,  d_p);

    constexpr int SM_PROJ = 2*(128*36 + 32*132)*4;                 // 70656
    constexpr int SM_ATTN = (128*QSTR + 2*128*QSTR + 2*128*VSTR + 2048)*4;  // 186368
    cudaFuncSetAttribute(gemm_proj<128,64,32>,
                         cudaFuncAttributeMaxDynamicSharedMemorySize, SM_PROJ);
    cudaFuncSetAttribute(attn_fused,
                         cudaFuncAttributeMaxDynamicSharedMemorySize, SM_ATTN);

    round_kernel<<<(BS*HH/4 + 255)/256, 256>>>((const float4*)X, (float4*)x, BS*HH/4);
    gate_kernel<<<BS, 256>>>(X, Wg, bg, g, p);

    dim3 gp(HH/128, BS/128);
    round_kernel<<<(HH*HH/4 + 255)/256, 256>>>((const float4*)Wq, (float4*)w, HH*HH/4);
    gemm_proj<128,64,32><<<gp, 256, SM_PROJ>>>(x, w, bq, q);
    round_kernel<<<(HH*HH/4 + 255)/256, 256>>>((const float4*)Wk, (float4*)w, HH*HH/4);
    gemm_proj<128,64,32><<<gp, 256, SM_PROJ>>>(x, w, bk, k);
    round_kernel<<<(HH*HH/4 + 255)/256, 256>>>((const float4*)Wv, (float4*)w, HH*HH/4);
    gemm_proj<128,64,32><<<gp, 256, SM_PROJ>>>(x, w, bv, v);

    dim3 ga(SS/128, BH);   // (16, 32)
    attn_fused<<<ga, 256, SM_ATTN>>>(q, k, v, g, p, out);
}

// round 5
// speedup vs baseline: 3.9384x; 1.0193x over previous
#include <cuda_runtime.h>
#include <math.h>
#include <stdint.h>

#define BB 2
#define SS 2048
#define HH 1024
#define NH 16
#define HD 64
#define BS (BB*SS)   // 4096
#define BH (BB*NH)   // 32

// Scratch (allocation-free: static device globals)
__device__ float d_q[(size_t)BS*HH];
__device__ float d_k[(size_t)BS*HH];
__device__ float d_v[(size_t)BS*HH];
__device__ float d_x[(size_t)BS*HH];       // tf32-rounded X
__device__ float d_w[(size_t)3*HH*HH];     // tf32-rounded Wq|Wk|Wv
__device__ float d_g[BS];
__device__ float d_p[BS];

// ---------------------------------------------------------------------------
// helpers
// ---------------------------------------------------------------------------
__device__ __forceinline__ float rna_tf32(float x){
    uint32_t y;  // cvt.*.tf32 requires .b32 destination
    asm("cvt.rna.tf32.f32 %0, %1;" : "=r"(y) : "f"(x));
    return __uint_as_float(y);
}
__device__ __forceinline__ void cp16(uint32_t dst, const float* src){
    asm volatile("cp.async.cg.shared.global [%0], [%1], 16;" :: "r"(dst), "l"(src));
}
__device__ __forceinline__ void cp_commit(){ asm volatile("cp.async.commit_group;"); }
template<int N> __device__ __forceinline__ void cp_wait(){
    asm volatile("cp.async.wait_group %0;" :: "n"(N));
}
__device__ __forceinline__ void mma8(float* c, const uint32_t* a, const uint32_t* b){
    asm volatile("mma.sync.aligned.m16n8k8.row.col.f32.tf32.tf32.f32 "
        "{%0,%1,%2,%3}, {%4,%5,%6,%7}, {%8,%9}, {%0,%1,%2,%3};"
        : "+f"(c[0]),"+f"(c[1]),"+f"(c[2]),"+f"(c[3])
        : "r"(a[0]),"r"(a[1]),"r"(a[2]),"r"(a[3]), "r"(b[0]),"r"(b[1]));
}

// ---------------------------------------------------------------------------
// tf32 rounding pass (elementwise, float4)
// ---------------------------------------------------------------------------
__global__ __launch_bounds__(256) void round_kernel(const float4* __restrict__ src,
                                                    float4* __restrict__ dst, int n4){
    int i = blockIdx.x*256 + threadIdx.x;
    if (i < n4){
        float4 v = src[i];
        v.x = rna_tf32(v.x); v.y = rna_tf32(v.y);
        v.z = rna_tf32(v.z); v.w = rna_tf32(v.w);
        dst[i] = v;
    }
}

// ---------------------------------------------------------------------------
// Gate: g = sigmoid(X @ Wg + bg), p = (S-2)^(1-g)   (fp32 path)
// ---------------------------------------------------------------------------
__global__ __launch_bounds__(256) void gate_kernel(const float* __restrict__ X,
                                                   const float* __restrict__ Wg,
                                                   const float* __restrict__ bg,
                                                   float* __restrict__ g,
                                                   float* __restrict__ p) {
    int row = blockIdx.x;
    int tid = threadIdx.x;
    float4 xv = *(const float4*)(X + (size_t)row*HH + tid*4);
    float4 wv = *(const float4*)(Wg + tid*4);
    float s = xv.x*wv.x + xv.y*wv.y + xv.z*wv.z + xv.w*wv.w;
    __shared__ float red[256];
    red[tid] = s; __syncthreads();
    for (int off = 128; off > 0; off >>= 1) {
        if (tid < off) red[tid] += red[tid+off];
        __syncthreads();
    }
    if (tid == 0) {
        float z = red[0] + bg[0];
        float gg = 1.f / (1.f + expf(-z));
        g[row] = gg;
        p[row] = powf((float)(SS-2), 1.f - gg);
    }
}

// ---------------------------------------------------------------------------
// Merged tf32 QKV projection: z selects (W, bias, C).
// C[4096,1024] = X @ W + bias, rna-rounded output.
// ---------------------------------------------------------------------------
template<int BN, int WM, int WN>
__global__ __launch_bounds__(256, 2) void gemm_proj(
    const float* __restrict__ A, const float* __restrict__ Wall,
    const float* __restrict__ b0, const float* __restrict__ b1,
    const float* __restrict__ b2,
    float* __restrict__ C0, float* __restrict__ C1, float* __restrict__ C2)
{
    const int z = blockIdx.z;
    const float* Bp = Wall + (size_t)z*HH*HH;
    const float* bias = (z == 0) ? b0 : (z == 1) ? b1 : b2;
    float* C = (z == 0) ? C0 : (z == 1) ? C1 : C2;

    constexpr int BM = 128, BK = 32;
    constexpr int ASTR = BK + 4;
    constexpr int BSTR = BN + 4;
    constexpr int ASZ = BM * ASTR;
    constexpr int BSZ = BK * BSTR;
    extern __shared__ float smf[];
    float* Asm[2] = { smf, smf + ASZ };
    float* Bsm[2] = { smf + 2*ASZ, smf + 2*ASZ + BSZ };

    const int tid = threadIdx.x, lane = tid & 31, wid = tid >> 5;
    constexpr int NWN = BN / WN;
    const int wm = wid / NWN, wn = wid % NWN;
    constexpr int MT = WM / 16, NT = WN / 8;

    const int iBase = blockIdx.y * BM;
    const int jBase = blockIdx.x * BN;

    float acc[MT][NT][4] = {};

    auto loadA = [&](int s, int kk){
        uint32_t base = (uint32_t)__cvta_generic_to_shared(Asm[s]);
        #pragma unroll
        for (int i = 0; i < (BM*8)/256; i++){
            int f = tid + i*256;
            int r = f >> 3, c = (f & 7) * 4;
            cp16(base + (uint32_t)(r*ASTR + c)*4u, A + (size_t)(iBase + r)*HH + kk + c);
        }
    };
    auto loadB = [&](int s, int kk){
        uint32_t base = (uint32_t)__cvta_generic_to_shared(Bsm[s]);
        #pragma unroll
        for (int i = 0; i < (BK*(BN/4))/256; i++){
            int f = tid + i*256;
            int k = f / (BN/4), c = (f % (BN/4)) * 4;
            cp16(base + (uint32_t)(k*BSTR + c)*4u, Bp + (size_t)(kk + k)*HH + jBase + c);
        }
    };

    loadA(0, 0); loadB(0, 0); cp_commit();
    const int nK = HH / BK;
    for (int kt = 0; kt < nK; kt++){
        const int cur = kt & 1;
        if (kt + 1 < nK){
            loadA(cur ^ 1, (kt+1)*BK); loadB(cur ^ 1, (kt+1)*BK);
            cp_commit(); cp_wait<1>();
        } else {
            cp_wait<0>();
        }
        __syncthreads();
        const float* As = Asm[cur];
        const float* Bs = Bsm[cur];
        #pragma unroll
        for (int ks = 0; ks < BK/8; ks++){
            uint32_t af[MT][4]; uint32_t bf[NT][2];
            #pragma unroll
            for (int mt = 0; mt < MT; mt++){
                int r0 = wm*WM + mt*16 + (lane >> 2);
                int c0 = ks*8 + (lane & 3);
                af[mt][0] = __float_as_uint(As[r0*ASTR + c0]);
                af[mt][1] = __float_as_uint(As[(r0+8)*ASTR + c0]);
                af[mt][2] = __float_as_uint(As[r0*ASTR + c0 + 4]);
                af[mt][3] = __float_as_uint(As[(r0+8)*ASTR + c0 + 4]);
            }
            #pragma unroll
            for (int nt = 0; nt < NT; nt++){
                int n = wn*WN + nt*8 + (lane >> 2);
                int k0 = ks*8 + (lane & 3);
                bf[nt][0] = __float_as_uint(Bs[k0*BSTR + n]);
                bf[nt][1] = __float_as_uint(Bs[(k0+4)*BSTR + n]);
            }
            #pragma unroll
            for (int mt = 0; mt < MT; mt++)
                #pragma unroll
                for (int nt = 0; nt < NT; nt++)
                    mma8(acc[mt][nt], af[mt], bf[nt]);
        }
        __syncthreads();
    }

    #pragma unroll
    for (int mt = 0; mt < MT; mt++){
        int r0 = iBase + wm*WM + mt*16 + (lane >> 2);
        #pragma unroll
        for (int nt = 0; nt < NT; nt++){
            int c0 = jBase + wn*WN + nt*8 + 2*(lane & 3);
            float bb0 = __ldg(bias + c0), bb1 = __ldg(bias + c0 + 1);
            float2 p0 = { rna_tf32(acc[mt][nt][0] + bb0), rna_tf32(acc[mt][nt][1] + bb1) };
            float2 p1 = { rna_tf32(acc[mt][nt][2] + bb0), rna_tf32(acc[mt][nt][3] + bb1) };
            *(float2*)(C + (size_t)r0*HH + c0)     = p0;
            *(float2*)(C + (size_t)(r0+8)*HH + c0) = p1;
        }
    }
}

// ---------------------------------------------------------------------------
// Fused flash attention, j-tile = 64 for 2 CTAs/SM.
// Grid (SS/128, BH). 256 threads = 8 warps; warp w owns rows [16w, 16w+16).
// Q tile resident; K/V 64-row tiles double-buffered; P -> PV mma via quad
// shuffles (C-fragment -> A-fragment layout), no smem round-trip.
// ---------------------------------------------------------------------------
#define QSTR 68
#define KSTR 68
#define VSTR 72
#define JT   64
#define NJT  (SS/JT)   // 32

__device__ __forceinline__ float penexp(float om, float gi, float pi, int i,
                                        float gj, int j, float se){
    float res = om * fmaxf(om - gj, 0.f) + gi * fminf(om + gj, 1.f);
    float scope = fminf(fmaxf(pi + 2.f - fabsf((float)(i - j)), 1e-32f), 1.f);
    float pen = fmaxf(res * scope, 1e-32f);
    return pen * __expf(se);
}

__global__ __launch_bounds__(256, 2) void attn_fused(
    const float* __restrict__ Q, const float* __restrict__ Kg,
    const float* __restrict__ Vg, const float* __restrict__ g,
    const float* __restrict__ p, float* __restrict__ out)
{
    const int bh = blockIdx.y, b = bh >> 4, h = bh & 15;
    const int iBase = blockIdx.x * 128;
    const int tid = threadIdx.x, lane = tid & 31, wid = tid >> 5;

    extern __shared__ float sm[];
    float* Qs  = sm;                      // 128*68
    float* Ks0 = Qs  + 128*QSTR;          // 2 x 64*68
    float* Vs0 = Ks0 + 2*JT*KSTR;         // 2 x 64*72
    float* gs  = Vs0 + 2*JT*VSTR;         // 2048

    const float* Qp = Q  + (size_t)b*SS*HH + h*HD;
    const float* Kp = Kg + (size_t)b*SS*HH + h*HD;
    const float* Vp = Vg + (size_t)b*SS*HH + h*HD;

    // prologue loads: Q tile, g row, K0/V0
    {
        uint32_t qb = (uint32_t)__cvta_generic_to_shared(Qs);
        #pragma unroll
        for (int l = 0; l < 8; l++){
            int f = tid + l*256;
            int r = f >> 4, c4 = f & 15;
            cp16(qb + (uint32_t)(r*QSTR + c4*4)*4u, Qp + (size_t)(iBase + r)*HH + c4*4);
        }
        uint32_t gb = (uint32_t)__cvta_generic_to_shared(gs);
        #pragma unroll
        for (int l = 0; l < 2; l++){
            int f = tid + l*256;
            cp16(gb + (uint32_t)f*16u, g + (size_t)b*SS + f*4);
        }
    }
    auto loadK = [&](int s, int j0){
        uint32_t kb = (uint32_t)__cvta_generic_to_shared(Ks0 + s*JT*KSTR);
        #pragma unroll
        for (int l = 0; l < 4; l++){
            int f = tid + l*256;
            int r = f >> 4, c4 = f & 15;
            cp16(kb + (uint32_t)(r*KSTR + c4*4)*4u, Kp + (size_t)(j0 + r)*HH + c4*4);
        }
    };
    auto loadV = [&](int s, int j0){
        uint32_t vb = (uint32_t)__cvta_generic_to_shared(Vs0 + s*JT*VSTR);
        #pragma unroll
        for (int l = 0; l < 4; l++){
            int f = tid + l*256;
            int r = f >> 4, c4 = f & 15;
            cp16(vb + (uint32_t)(r*VSTR + c4*4)*4u, Vp + (size_t)(j0 + r)*HH + c4*4);
        }
    };
    loadK(0, 0); loadV(0, 0); cp_commit();

    const int lr0 = wid*16 + (lane >> 2);    // local row in tile
    const int lr1 = lr0 + 8;
    const int i0 = iBase + lr0, i1 = iBase + lr1;
    const float gi0 = __ldg(g + (size_t)b*SS + i0);
    const float gi1 = __ldg(g + (size_t)b*SS + i1);
    const float pi0 = __ldg(p + (size_t)b*SS + i0);
    const float pi1 = __ldg(p + (size_t)b*SS + i1);
    const float om0 = 1.f - gi0, om1 = 1.f - gi1;

    float m0 = -1e30f, m1 = -1e30f, l0 = 0.f, l1 = 0.f;
    float oacc[8][4] = {};

    const int q = lane & 3;
    const int basel = lane & 28;
    const int src0 = basel | (q >> 1);
    const int src2 = src0 + 2;

    for (int jt = 0; jt < NJT; jt++){
        const int cur = jt & 1;
        if (jt + 1 < NJT){
            loadK(cur ^ 1, (jt+1)*JT); loadV(cur ^ 1, (jt+1)*JT);
            cp_commit(); cp_wait<1>();
        } else {
            cp_wait<0>();
        }
        __syncthreads();
        const float* Ks = Ks0 + cur*JT*KSTR;
        const float* Vs = Vs0 + cur*JT*VSTR;
        const int jBase = jt*JT;

        // --- S = Q K^T (raw, scale folded later) ---
        float sacc[8][4];
        #pragma unroll
        for (int nt = 0; nt < 8; nt++){
            sacc[nt][0]=0.f; sacc[nt][1]=0.f; sacc[nt][2]=0.f; sacc[nt][3]=0.f;
        }
        #pragma unroll
        for (int ks = 0; ks < 8; ks++){
            const int kk = ks*8 + q;
            uint32_t af[4];
            af[0] = __float_as_uint(Qs[lr0*QSTR + kk]);
            af[1] = __float_as_uint(Qs[lr1*QSTR + kk]);
            af[2] = __float_as_uint(Qs[lr0*QSTR + kk + 4]);
            af[3] = __float_as_uint(Qs[lr1*QSTR + kk + 4]);
            #pragma unroll
            for (int nt = 0; nt < 8; nt++){
                const int n = nt*8 + (lane >> 2);
                uint32_t bf[2];
                bf[0] = __float_as_uint(Ks[n*KSTR + kk]);
                bf[1] = __float_as_uint(Ks[n*KSTR + kk + 4]);
                mma8(sacc[nt], af, bf);
            }
        }

        // --- online softmax ---
        float tm0 = -1e30f, tm1 = -1e30f;
        #pragma unroll
        for (int nt = 0; nt < 8; nt++){
            tm0 = fmaxf(tm0, fmaxf(sacc[nt][0], sacc[nt][1]));
            tm1 = fmaxf(tm1, fmaxf(sacc[nt][2], sacc[nt][3]));
        }
        tm0 = fmaxf(tm0, __shfl_xor_sync(0xffffffffu, tm0, 1));
        tm0 = fmaxf(tm0, __shfl_xor_sync(0xffffffffu, tm0, 2));
        tm1 = fmaxf(tm1, __shfl_xor_sync(0xffffffffu, tm1, 1));
        tm1 = fmaxf(tm1, __shfl_xor_sync(0xffffffffu, tm1, 2));
        tm0 *= 0.125f; tm1 *= 0.125f;
        const float m0n = fmaxf(m0, tm0), m1n = fmaxf(m1, tm1);
        const float f0 = __expf(m0 - m0n), f1 = __expf(m1 - m1n);
        m0 = m0n; m1 = m1n;
        l0 *= f0; l1 *= f1;
        #pragma unroll
        for (int dn = 0; dn < 8; dn++){
            oacc[dn][0] *= f0; oacc[dn][1] *= f0;
            oacc[dn][2] *= f1; oacc[dn][3] *= f1;
        }
        float rs0 = 0.f, rs1 = 0.f;
        #pragma unroll
        for (int nt = 0; nt < 8; nt++){
            const int j0 = jBase + nt*8 + 2*q;
            const int j1 = j0 + 1;
            const float gj0 = gs[j0], gj1 = gs[j1];
            float t00 = penexp(om0, gi0, pi0, i0, gj0, j0, sacc[nt][0]*0.125f - m0);
            float t01 = penexp(om0, gi0, pi0, i0, gj1, j1, sacc[nt][1]*0.125f - m0);
            float t10 = penexp(om1, gi1, pi1, i1, gj0, j0, sacc[nt][2]*0.125f - m1);
            float t11 = penexp(om1, gi1, pi1, i1, gj1, j1, sacc[nt][3]*0.125f - m1);
            sacc[nt][0] = t00; sacc[nt][1] = t01;
            sacc[nt][2] = t10; sacc[nt][3] = t11;
            rs0 += t00 + t01; rs1 += t10 + t11;
        }
        rs0 += __shfl_xor_sync(0xffffffffu, rs0, 1);
        rs0 += __shfl_xor_sync(0xffffffffu, rs0, 2);
        rs1 += __shfl_xor_sync(0xffffffffu, rs1, 1);
        rs1 += __shfl_xor_sync(0xffffffffu, rs1, 2);
        l0 += rs0; l1 += rs1;

        // --- O += P V : quad-shuffle C-frag -> A-frag, then mma over d ---
        #pragma unroll
        for (int kc = 0; kc < 8; kc++){
            float x0 = __shfl_sync(0xffffffffu, sacc[kc][0], src0);
            float x1 = __shfl_sync(0xffffffffu, sacc[kc][1], src0);
            float y0 = __shfl_sync(0xffffffffu, sacc[kc][0], src2);
            float y1 = __shfl_sync(0xffffffffu, sacc[kc][1], src2);
            float z0 = __shfl_sync(0xffffffffu, sacc[kc][2], src0);
            float z1 = __shfl_sync(0xffffffffu, sacc[kc][3], src0);
            float w0 = __shfl_sync(0xffffffffu, sacc[kc][2], src2);
            float w1 = __shfl_sync(0xffffffffu, sacc[kc][3], src2);
            const bool odd = (q & 1);
            uint32_t af[4];
            af[0] = __float_as_uint(rna_tf32(odd ? x1 : x0));  // (r0, q)
            af[1] = __float_as_uint(rna_tf32(odd ? z1 : z0));  // (r1, q)
            af[2] = __float_as_uint(rna_tf32(odd ? y1 : y0));  // (r0, q+4)
            af[3] = __float_as_uint(rna_tf32(odd ? w1 : w0));  // (r1, q+4)
            const int kb = kc*8 + q;
            #pragma unroll
            for (int dn = 0; dn < 8; dn++){
                const int d0 = dn*8 + (lane >> 2);
                uint32_t bf[2];
                bf[0] = __float_as_uint(Vs[kb*VSTR + d0]);
                bf[1] = __float_as_uint(Vs[(kb+4)*VSTR + d0]);
                mma8(oacc[dn], af, bf);
            }
        }
        __syncthreads();
    }

    // epilogue
    const float inv0 = 1.f / l0, inv1 = 1.f / l1;
    float* op = out + (size_t)b*SS*HH + h*HD;
    #pragma unroll
    for (int dn = 0; dn < 8; dn++){
        const int c0 = dn*8 + 2*q;
        float2 o0 = { oacc[dn][0]*inv0, oacc[dn][1]*inv0 };
        float2 o1 = { oacc[dn][2]*inv1, oacc[dn][3]*inv1 };
        *(float2*)(op + (size_t)(iBase + lr0)*HH + c0) = o0;
        *(float2*)(op + (size_t)(iBase + lr1)*HH + c0) = o1;
    }
}

// ---------------------------------------------------------------------------
extern "C" void kernel_launch(void* const* d_in, const int* in_sizes, int n_in,
                              void* d_out, int out_size) {
    const float* X  = (const float*)d_in[0];
    const float* Wq = (const float*)d_in[1];
    const float* bq = (const float*)d_in[2];
    const float* Wk = (const float*)d_in[3];
    const float* bk = (const float*)d_in[4];
    const float* Wv = (const float*)d_in[5];
    const float* bv = (const float*)d_in[6];
    const float* Wg = (const float*)d_in[7];
    const float* bg = (const float*)d_in[8];
    float* out = (float*)d_out;

    float *q, *k, *v, *x, *w, *g, *p;
    cudaGetSymbolAddress((void**)&q,  d_q);
    cudaGetSymbolAddress((void**)&k,  d_k);
    cudaGetSymbolAddress((void**)&v,  d_v);
    cudaGetSymbolAddress((void**)&x,  d_x);
    cudaGetSymbolAddress((void**)&w,  d_w);
    cudaGetSymbolAddress((void**)&g,  d_g);
    cudaGetSymbolAddress((void**)&p,  d_p);

    constexpr int SM_PROJ = 2*(128*36 + 32*132)*4;                           // 70656
    constexpr int SM_ATTN = (128*QSTR + 2*JT*KSTR + 2*JT*VSTR + 2048)*4;     // 114688
    cudaFuncSetAttribute(gemm_proj<128,64,32>,
                         cudaFuncAttributeMaxDynamicSharedMemorySize, SM_PROJ);
    cudaFuncSetAttribute(attn_fused,
                         cudaFuncAttributeMaxDynamicSharedMemorySize, SM_ATTN);

    // rounding passes (independent buffers, no serialization with GEMMs)
    round_kernel<<<(BS*HH/4 + 255)/256, 256>>>((const float4*)X, (float4*)x, BS*HH/4);
    round_kernel<<<(HH*HH/4 + 255)/256, 256>>>((const float4*)Wq, (float4*)(w),          HH*HH/4);
    round_kernel<<<(HH*HH/4 + 255)/256, 256>>>((const float4*)Wk, (float4*)(w + (size_t)HH*HH),   HH*HH/4);
    round_kernel<<<(HH*HH/4 + 255)/256, 256>>>((const float4*)Wv, (float4*)(w + (size_t)2*HH*HH), HH*HH/4);
    gate_kernel<<<BS, 256>>>(X, Wg, bg, g, p);

    // one merged QKV projection launch
    dim3 gp(HH/128, BS/128, 3);   // (8, 32, 3)
    gemm_proj<128,64,32><<<gp, 256, SM_PROJ>>>(x, w, bq, bk, bv, q, k, v);

    dim3 ga(SS/128, BH);   // (16, 32)
    attn_fused<<<ga, 256, SM_ATTN>>>(q, k, v, g, p, out);
}

// round 6
// speedup vs baseline: 4.5428x; 1.1535x over previous
#include <cuda_runtime.h>
#include <math.h>
#include <stdint.h>

#define BB 2
#define SS 2048
#define HH 1024
#define NH 16
#define HD 64
#define BS (BB*SS)   // 4096
#define BH (BB*NH)   // 32

// Scratch (allocation-free: static device globals)
__device__ float d_q[(size_t)BS*HH];
__device__ float d_k[(size_t)BS*HH];
__device__ float d_v[(size_t)BS*HH];
__device__ float d_x[(size_t)BS*HH];       // tf32-rounded X
__device__ float d_w[(size_t)3*HH*HH];     // tf32-rounded Wq|Wk|Wv
__device__ float d_g[BS];
__device__ float d_p[BS];

// ---------------------------------------------------------------------------
// helpers
// ---------------------------------------------------------------------------
__device__ __forceinline__ float rna_tf32(float x){
    uint32_t y;  // cvt.*.tf32 requires .b32 destination
    asm("cvt.rna.tf32.f32 %0, %1;" : "=r"(y) : "f"(x));
    return __uint_as_float(y);
}
__device__ __forceinline__ void cp16(uint32_t dst, const float* src){
    asm volatile("cp.async.cg.shared.global [%0], [%1], 16;" :: "r"(dst), "l"(src));
}
__device__ __forceinline__ void cp_commit(){ asm volatile("cp.async.commit_group;"); }
template<int N> __device__ __forceinline__ void cp_wait(){
    asm volatile("cp.async.wait_group %0;" :: "n"(N));
}
__device__ __forceinline__ void mma8(float* c, const uint32_t* a, const uint32_t* b){
    asm volatile("mma.sync.aligned.m16n8k8.row.col.f32.tf32.tf32.f32 "
        "{%0,%1,%2,%3}, {%4,%5,%6,%7}, {%8,%9}, {%0,%1,%2,%3};"
        : "+f"(c[0]),"+f"(c[1]),"+f"(c[2]),"+f"(c[3])
        : "r"(a[0]),"r"(a[1]),"r"(a[2]),"r"(a[3]), "r"(b[0]),"r"(b[1]));
}

// ---------------------------------------------------------------------------
// tf32 rounding passes
// ---------------------------------------------------------------------------
__global__ __launch_bounds__(256) void round_kernel(const float4* __restrict__ src,
                                                    float4* __restrict__ dst, int n4){
    int i = blockIdx.x*256 + threadIdx.x;
    if (i < n4){
        float4 v = src[i];
        v.x = rna_tf32(v.x); v.y = rna_tf32(v.y);
        v.z = rna_tf32(v.z); v.w = rna_tf32(v.w);
        dst[i] = v;
    }
}

// one launch for the three weight matrices (z selects source)
__global__ __launch_bounds__(256) void round3_kernel(const float4* __restrict__ s0,
                                                     const float4* __restrict__ s1,
                                                     const float4* __restrict__ s2,
                                                     float4* __restrict__ dst, int n4){
    int z = blockIdx.z;
    const float4* src = (z == 0) ? s0 : (z == 1) ? s1 : s2;
    int i = blockIdx.x*256 + threadIdx.x;
    if (i < n4){
        float4 v = src[i];
        v.x = rna_tf32(v.x); v.y = rna_tf32(v.y);
        v.z = rna_tf32(v.z); v.w = rna_tf32(v.w);
        dst[(size_t)z*n4 + i] = v;
    }
}

// ---------------------------------------------------------------------------
// Gate: g = sigmoid(X @ Wg + bg), p = (S-2)^(1-g)   (fp32 path)
// ---------------------------------------------------------------------------
__global__ __launch_bounds__(256) void gate_kernel(const float* __restrict__ X,
                                                   const float* __restrict__ Wg,
                                                   const float* __restrict__ bg,
                                                   float* __restrict__ g,
                                                   float* __restrict__ p) {
    int row = blockIdx.x;
    int tid = threadIdx.x;
    float4 xv = *(const float4*)(X + (size_t)row*HH + tid*4);
    float4 wv = *(const float4*)(Wg + tid*4);
    float s = xv.x*wv.x + xv.y*wv.y + xv.z*wv.z + xv.w*wv.w;
    __shared__ float red[256];
    red[tid] = s; __syncthreads();
    for (int off = 128; off > 0; off >>= 1) {
        if (tid < off) red[tid] += red[tid+off];
        __syncthreads();
    }
    if (tid == 0) {
        float z = red[0] + bg[0];
        float gg = 1.f / (1.f + expf(-z));
        g[row] = gg;
        p[row] = powf((float)(SS-2), 1.f - gg);
    }
}

// ---------------------------------------------------------------------------
// Merged tf32 QKV projection: z selects (W, bias, C).
// ---------------------------------------------------------------------------
template<int BN, int WM, int WN>
__global__ __launch_bounds__(256, 2) void gemm_proj(
    const float* __restrict__ A, const float* __restrict__ Wall,
    const float* __restrict__ b0, const float* __restrict__ b1,
    const float* __restrict__ b2,
    float* __restrict__ C0, float* __restrict__ C1, float* __restrict__ C2)
{
    const int z = blockIdx.z;
    const float* Bp = Wall + (size_t)z*HH*HH;
    const float* bias = (z == 0) ? b0 : (z == 1) ? b1 : b2;
    float* C = (z == 0) ? C0 : (z == 1) ? C1 : C2;

    constexpr int BM = 128, BK = 32;
    constexpr int ASTR = BK + 4;
    constexpr int BSTR = BN + 4;
    constexpr int ASZ = BM * ASTR;
    constexpr int BSZ = BK * BSTR;
    extern __shared__ float smf[];
    float* Asm[2] = { smf, smf + ASZ };
    float* Bsm[2] = { smf + 2*ASZ, smf + 2*ASZ + BSZ };

    const int tid = threadIdx.x, lane = tid & 31, wid = tid >> 5;
    constexpr int NWN = BN / WN;
    const int wm = wid / NWN, wn = wid % NWN;
    constexpr int MT = WM / 16, NT = WN / 8;

    const int iBase = blockIdx.y * BM;
    const int jBase = blockIdx.x * BN;

    float acc[MT][NT][4] = {};

    auto loadA = [&](int s, int kk){
        uint32_t base = (uint32_t)__cvta_generic_to_shared(Asm[s]);
        #pragma unroll
        for (int i = 0; i < (BM*8)/256; i++){
            int f = tid + i*256;
            int r = f >> 3, c = (f & 7) * 4;
            cp16(base + (uint32_t)(r*ASTR + c)*4u, A + (size_t)(iBase + r)*HH + kk + c);
        }
    };
    auto loadB = [&](int s, int kk){
        uint32_t base = (uint32_t)__cvta_generic_to_shared(Bsm[s]);
        #pragma unroll
        for (int i = 0; i < (BK*(BN/4))/256; i++){
            int f = tid + i*256;
            int k = f / (BN/4), c = (f % (BN/4)) * 4;
            cp16(base + (uint32_t)(k*BSTR + c)*4u, Bp + (size_t)(kk + k)*HH + jBase + c);
        }
    };

    loadA(0, 0); loadB(0, 0); cp_commit();
    const int nK = HH / BK;
    for (int kt = 0; kt < nK; kt++){
        const int cur = kt & 1;
        if (kt + 1 < nK){
            loadA(cur ^ 1, (kt+1)*BK); loadB(cur ^ 1, (kt+1)*BK);
            cp_commit(); cp_wait<1>();
        } else {
            cp_wait<0>();
        }
        __syncthreads();
        const float* As = Asm[cur];
        const float* Bs = Bsm[cur];
        #pragma unroll
        for (int ks = 0; ks < BK/8; ks++){
            uint32_t af[MT][4]; uint32_t bf[NT][2];
            #pragma unroll
            for (int mt = 0; mt < MT; mt++){
                int r0 = wm*WM + mt*16 + (lane >> 2);
                int c0 = ks*8 + (lane & 3);
                af[mt][0] = __float_as_uint(As[r0*ASTR + c0]);
                af[mt][1] = __float_as_uint(As[(r0+8)*ASTR + c0]);
                af[mt][2] = __float_as_uint(As[r0*ASTR + c0 + 4]);
                af[mt][3] = __float_as_uint(As[(r0+8)*ASTR + c0 + 4]);
            }
            #pragma unroll
            for (int nt = 0; nt < NT; nt++){
                int n = wn*WN + nt*8 + (lane >> 2);
                int k0 = ks*8 + (lane & 3);
                bf[nt][0] = __float_as_uint(Bs[k0*BSTR + n]);
                bf[nt][1] = __float_as_uint(Bs[(k0+4)*BSTR + n]);
            }
            #pragma unroll
            for (int mt = 0; mt < MT; mt++)
                #pragma unroll
                for (int nt = 0; nt < NT; nt++)
                    mma8(acc[mt][nt], af[mt], bf[nt]);
        }
        __syncthreads();
    }

    #pragma unroll
    for (int mt = 0; mt < MT; mt++){
        int r0 = iBase + wm*WM + mt*16 + (lane >> 2);
        #pragma unroll
        for (int nt = 0; nt < NT; nt++){
            int c0 = jBase + wn*WN + nt*8 + 2*(lane & 3);
            float bb0 = __ldg(bias + c0), bb1 = __ldg(bias + c0 + 1);
            float2 p0 = { rna_tf32(acc[mt][nt][0] + bb0), rna_tf32(acc[mt][nt][1] + bb1) };
            float2 p1 = { rna_tf32(acc[mt][nt][2] + bb0), rna_tf32(acc[mt][nt][3] + bb1) };
            *(float2*)(C + (size_t)r0*HH + c0)     = p0;
            *(float2*)(C + (size_t)(r0+8)*HH + c0) = p1;
        }
    }
}

// ---------------------------------------------------------------------------
// Fused flash attention with per-warp band skipping.
// scope = clamp(pi+2-|i-j|, 1e-32, 1): outside |i-j| < pi+2 the penalty is
// 1e-32 -> contribution ~1e-24 of in-band mass. A warp skips a j-tile's whole
// compute body when the tile is outside the union band of its 16 rows.
// Loads / syncs stay unconditional (pipeline + barrier structure intact).
// ---------------------------------------------------------------------------
#define QSTR 68
#define KSTR 68
#define VSTR 72
#define JT   64
#define NJT  (SS/JT)   // 32

__device__ __forceinline__ float penexp(float om, float gi, float pi, int i,
                                        float gj, int j, float se){
    float res = om * fmaxf(om - gj, 0.f) + gi * fminf(om + gj, 1.f);
    float scope = fminf(fmaxf(pi + 2.f - fabsf((float)(i - j)), 1e-32f), 1.f);
    float pen = fmaxf(res * scope, 1e-32f);
    return pen * __expf(se);
}

__global__ __launch_bounds__(256, 2) void attn_fused(
    const float* __restrict__ Q, const float* __restrict__ Kg,
    const float* __restrict__ Vg, const float* __restrict__ g,
    const float* __restrict__ p, float* __restrict__ out)
{
    const int bh = blockIdx.y, b = bh >> 4, h = bh & 15;
    const int iBase = blockIdx.x * 128;
    const int tid = threadIdx.x, lane = tid & 31, wid = tid >> 5;

    extern __shared__ float sm[];
    float* Qs  = sm;                      // 128*68
    float* Ks0 = Qs  + 128*QSTR;          // 2 x 64*68
    float* Vs0 = Ks0 + 2*JT*KSTR;         // 2 x 64*72
    float* gs  = Vs0 + 2*JT*VSTR;         // 2048

    const float* Qp = Q  + (size_t)b*SS*HH + h*HD;
    const float* Kp = Kg + (size_t)b*SS*HH + h*HD;
    const float* Vp = Vg + (size_t)b*SS*HH + h*HD;

    // prologue loads: Q tile, g row, K0/V0
    {
        uint32_t qb = (uint32_t)__cvta_generic_to_shared(Qs);
        #pragma unroll
        for (int l = 0; l < 8; l++){
            int f = tid + l*256;
            int r = f >> 4, c4 = f & 15;
            cp16(qb + (uint32_t)(r*QSTR + c4*4)*4u, Qp + (size_t)(iBase + r)*HH + c4*4);
        }
        uint32_t gb = (uint32_t)__cvta_generic_to_shared(gs);
        #pragma unroll
        for (int l = 0; l < 2; l++){
            int f = tid + l*256;
            cp16(gb + (uint32_t)f*16u, g + (size_t)b*SS + f*4);
        }
    }
    auto loadK = [&](int s, int j0){
        uint32_t kb = (uint32_t)__cvta_generic_to_shared(Ks0 + s*JT*KSTR);
        #pragma unroll
        for (int l = 0; l < 4; l++){
            int f = tid + l*256;
            int r = f >> 4, c4 = f & 15;
            cp16(kb + (uint32_t)(r*KSTR + c4*4)*4u, Kp + (size_t)(j0 + r)*HH + c4*4);
        }
    };
    auto loadV = [&](int s, int j0){
        uint32_t vb = (uint32_t)__cvta_generic_to_shared(Vs0 + s*JT*VSTR);
        #pragma unroll
        for (int l = 0; l < 4; l++){
            int f = tid + l*256;
            int r = f >> 4, c4 = f & 15;
            cp16(vb + (uint32_t)(r*VSTR + c4*4)*4u, Vp + (size_t)(j0 + r)*HH + c4*4);
        }
    };
    loadK(0, 0); loadV(0, 0); cp_commit();

    const int lr0 = wid*16 + (lane >> 2);    // local row in tile
    const int lr1 = lr0 + 8;
    const int i0 = iBase + lr0, i1 = iBase + lr1;
    const float gi0 = __ldg(g + (size_t)b*SS + i0);
    const float gi1 = __ldg(g + (size_t)b*SS + i1);
    const float pi0 = __ldg(p + (size_t)b*SS + i0);
    const float pi1 = __ldg(p + (size_t)b*SS + i1);
    const float om0 = 1.f - gi0, om1 = 1.f - gi1;

    // per-warp band: tiles fully outside [blo, bhi] contribute pen=1e-32 only
    float wlo = fminf((float)i0 - pi0, (float)i1 - pi1);
    float whi = fmaxf((float)i0 + pi0, (float)i1 + pi1);
    #pragma unroll
    for (int off = 16; off > 0; off >>= 1){
        wlo = fminf(wlo, __shfl_xor_sync(0xffffffffu, wlo, off));
        whi = fmaxf(whi, __shfl_xor_sync(0xffffffffu, whi, off));
    }
    const int blo = (int)floorf(wlo) - 3;
    const int bhi = (int)ceilf(whi) + 3;

    float m0 = -1e30f, m1 = -1e30f, l0 = 0.f, l1 = 0.f;
    float oacc[8][4] = {};

    const int q = lane & 3;
    const int basel = lane & 28;
    const int src0 = basel | (q >> 1);
    const int src2 = src0 + 2;

    for (int jt = 0; jt < NJT; jt++){
        const int cur = jt & 1;
        if (jt + 1 < NJT){
            loadK(cur ^ 1, (jt+1)*JT); loadV(cur ^ 1, (jt+1)*JT);
            cp_commit(); cp_wait<1>();
        } else {
            cp_wait<0>();
        }
        __syncthreads();
        const int jBase = jt*JT;
        const bool active = (jBase + JT - 1 >= blo) && (jBase <= bhi);
        if (active){
            const float* Ks = Ks0 + cur*JT*KSTR;
            const float* Vs = Vs0 + cur*JT*VSTR;

            // --- S = Q K^T (raw, scale folded later) ---
            float sacc[8][4];
            #pragma unroll
            for (int nt = 0; nt < 8; nt++){
                sacc[nt][0]=0.f; sacc[nt][1]=0.f; sacc[nt][2]=0.f; sacc[nt][3]=0.f;
            }
            #pragma unroll
            for (int ks = 0; ks < 8; ks++){
                const int kk = ks*8 + q;
                uint32_t af[4];
                af[0] = __float_as_uint(Qs[lr0*QSTR + kk]);
                af[1] = __float_as_uint(Qs[lr1*QSTR + kk]);
                af[2] = __float_as_uint(Qs[lr0*QSTR + kk + 4]);
                af[3] = __float_as_uint(Qs[lr1*QSTR + kk + 4]);
                #pragma unroll
                for (int nt = 0; nt < 8; nt++){
                    const int n = nt*8 + (lane >> 2);
                    uint32_t bf[2];
                    bf[0] = __float_as_uint(Ks[n*KSTR + kk]);
                    bf[1] = __float_as_uint(Ks[n*KSTR + kk + 4]);
                    mma8(sacc[nt], af, bf);
                }
            }

            // --- online softmax ---
            float tm0 = -1e30f, tm1 = -1e30f;
            #pragma unroll
            for (int nt = 0; nt < 8; nt++){
                tm0 = fmaxf(tm0, fmaxf(sacc[nt][0], sacc[nt][1]));
                tm1 = fmaxf(tm1, fmaxf(sacc[nt][2], sacc[nt][3]));
            }
            tm0 = fmaxf(tm0, __shfl_xor_sync(0xffffffffu, tm0, 1));
            tm0 = fmaxf(tm0, __shfl_xor_sync(0xffffffffu, tm0, 2));
            tm1 = fmaxf(tm1, __shfl_xor_sync(0xffffffffu, tm1, 1));
            tm1 = fmaxf(tm1, __shfl_xor_sync(0xffffffffu, tm1, 2));
            tm0 *= 0.125f; tm1 *= 0.125f;
            const float m0n = fmaxf(m0, tm0), m1n = fmaxf(m1, tm1);
            const float f0 = __expf(m0 - m0n), f1 = __expf(m1 - m1n);
            m0 = m0n; m1 = m1n;
            l0 *= f0; l1 *= f1;
            #pragma unroll
            for (int dn = 0; dn < 8; dn++){
                oacc[dn][0] *= f0; oacc[dn][1] *= f0;
                oacc[dn][2] *= f1; oacc[dn][3] *= f1;
            }
            float rs0 = 0.f, rs1 = 0.f;
            #pragma unroll
            for (int nt = 0; nt < 8; nt++){
                const int j0 = jBase + nt*8 + 2*q;
                const int j1 = j0 + 1;
                const float gj0 = gs[j0], gj1 = gs[j1];
                float t00 = penexp(om0, gi0, pi0, i0, gj0, j0, sacc[nt][0]*0.125f - m0);
                float t01 = penexp(om0, gi0, pi0, i0, gj1, j1, sacc[nt][1]*0.125f - m0);
                float t10 = penexp(om1, gi1, pi1, i1, gj0, j0, sacc[nt][2]*0.125f - m1);
                float t11 = penexp(om1, gi1, pi1, i1, gj1, j1, sacc[nt][3]*0.125f - m1);
                sacc[nt][0] = t00; sacc[nt][1] = t01;
                sacc[nt][2] = t10; sacc[nt][3] = t11;
                rs0 += t00 + t01; rs1 += t10 + t11;
            }
            rs0 += __shfl_xor_sync(0xffffffffu, rs0, 1);
            rs0 += __shfl_xor_sync(0xffffffffu, rs0, 2);
            rs1 += __shfl_xor_sync(0xffffffffu, rs1, 1);
            rs1 += __shfl_xor_sync(0xffffffffu, rs1, 2);
            l0 += rs0; l1 += rs1;

            // --- O += P V : quad-shuffle C-frag -> A-frag, then mma over d ---
            #pragma unroll
            for (int kc = 0; kc < 8; kc++){
                float x0 = __shfl_sync(0xffffffffu, sacc[kc][0], src0);
                float x1 = __shfl_sync(0xffffffffu, sacc[kc][1], src0);
                float y0 = __shfl_sync(0xffffffffu, sacc[kc][0], src2);
                float y1 = __shfl_sync(0xffffffffu, sacc[kc][1], src2);
                float z0 = __shfl_sync(0xffffffffu, sacc[kc][2], src0);
                float z1 = __shfl_sync(0xffffffffu, sacc[kc][3], src0);
                float w0 = __shfl_sync(0xffffffffu, sacc[kc][2], src2);
                float w1 = __shfl_sync(0xffffffffu, sacc[kc][3], src2);
                const bool odd = (q & 1);
                uint32_t af[4];
                af[0] = __float_as_uint(rna_tf32(odd ? x1 : x0));  // (r0, q)
                af[1] = __float_as_uint(rna_tf32(odd ? z1 : z0));  // (r1, q)
                af[2] = __float_as_uint(rna_tf32(odd ? y1 : y0));  // (r0, q+4)
                af[3] = __float_as_uint(rna_tf32(odd ? w1 : w0));  // (r1, q+4)
                const int kb = kc*8 + q;
                #pragma unroll
                for (int dn = 0; dn < 8; dn++){
                    const int d0 = dn*8 + (lane >> 2);
                    uint32_t bf[2];
                    bf[0] = __float_as_uint(Vs[kb*VSTR + d0]);
                    bf[1] = __float_as_uint(Vs[(kb+4)*VSTR + d0]);
                    mma8(oacc[dn], af, bf);
                }
            }
        }
        __syncthreads();
    }

    // epilogue
    const float inv0 = 1.f / l0, inv1 = 1.f / l1;
    float* op = out + (size_t)b*SS*HH + h*HD;
    #pragma unroll
    for (int dn = 0; dn < 8; dn++){
        const int c0 = dn*8 + 2*q;
        float2 o0 = { oacc[dn][0]*inv0, oacc[dn][1]*inv0 };
        float2 o1 = { oacc[dn][2]*inv1, oacc[dn][3]*inv1 };
        *(float2*)(op + (size_t)(iBase + lr0)*HH + c0) = o0;
        *(float2*)(op + (size_t)(iBase + lr1)*HH + c0) = o1;
    }
}

// ---------------------------------------------------------------------------
extern "C" void kernel_launch(void* const* d_in, const int* in_sizes, int n_in,
                              void* d_out, int out_size) {
    const float* X  = (const float*)d_in[0];
    const float* Wq = (const float*)d_in[1];
    const float* bq = (const float*)d_in[2];
    const float* Wk = (const float*)d_in[3];
    const float* bk = (const float*)d_in[4];
    const float* Wv = (const float*)d_in[5];
    const float* bv = (const float*)d_in[6];
    const float* Wg = (const float*)d_in[7];
    const float* bg = (const float*)d_in[8];
    float* out = (float*)d_out;

    float *q, *k, *v, *x, *w, *g, *p;
    cudaGetSymbolAddress((void**)&q,  d_q);
    cudaGetSymbolAddress((void**)&k,  d_k);
    cudaGetSymbolAddress((void**)&v,  d_v);
    cudaGetSymbolAddress((void**)&x,  d_x);
    cudaGetSymbolAddress((void**)&w,  d_w);
    cudaGetSymbolAddress((void**)&g,  d_g);
    cudaGetSymbolAddress((void**)&p,  d_p);

    constexpr int SM_PROJ = 2*(128*36 + 32*132)*4;                           // 70656
    constexpr int SM_ATTN = (128*QSTR + 2*JT*KSTR + 2*JT*VSTR + 2048)*4;     // 114688
    cudaFuncSetAttribute(gemm_proj<128,64,32>,
                         cudaFuncAttributeMaxDynamicSharedMemorySize, SM_PROJ);
    cudaFuncSetAttribute(attn_fused,
                         cudaFuncAttributeMaxDynamicSharedMemorySize, SM_ATTN);

    // rounding passes
    round_kernel<<<(BS*HH/4 + 255)/256, 256>>>((const float4*)X, (float4*)x, BS*HH/4);
    dim3 gr((HH*HH/4 + 255)/256, 1, 3);
    round3_kernel<<<gr, 256>>>((const float4*)Wq, (const float4*)Wk,
                               (const float4*)Wv, (float4*)w, HH*HH/4);
    gate_kernel<<<BS, 256>>>(X, Wg, bg, g, p);

    // one merged QKV projection launch
    dim3 gp(HH/128, BS/128, 3);   // (8, 32, 3)
    gemm_proj<128,64,32><<<gp, 256, SM_PROJ>>>(x, w, bq, bk, bv, q, k, v);

    dim3 ga(SS/128, BH);   // (16, 32)
    attn_fused<<<ga, 256, SM_ATTN>>>(q, k, v, g, p, out);
}

// round 7
// speedup vs baseline: 5.3014x; 1.1670x over previous
#include <cuda_runtime.h>
#include <math.h>
#include <stdint.h>

#define BB 2
#define SS 2048
#define HH 1024
#define NH 16
#define HD 64
#define BS (BB*SS)   // 4096
#define BH (BB*NH)   // 32

// Scratch (allocation-free: static device globals)
__device__ float d_q[(size_t)BS*HH];
__device__ float d_k[(size_t)BS*HH];
__device__ float d_v[(size_t)BS*HH];
__device__ float d_x[(size_t)BS*HH];       // tf32-rounded X
__device__ float d_w[(size_t)3*HH*HH];     // tf32-rounded Wq|Wk|Wv
__device__ float d_g[BS];
__device__ float d_p[BS];
__device__ int   d_perm[BS];               // bucketed query order per batch

// ---------------------------------------------------------------------------
// helpers
// ---------------------------------------------------------------------------
__device__ __forceinline__ float rna_tf32(float x){
    uint32_t y;  // cvt.*.tf32 requires .b32 destination
    asm("cvt.rna.tf32.f32 %0, %1;" : "=r"(y) : "f"(x));
    return __uint_as_float(y);
}
__device__ __forceinline__ void cp16(uint32_t dst, const float* src){
    asm volatile("cp.async.cg.shared.global [%0], [%1], 16;" :: "r"(dst), "l"(src));
}
__device__ __forceinline__ void cp_commit(){ asm volatile("cp.async.commit_group;"); }
template<int N> __device__ __forceinline__ void cp_wait(){
    asm volatile("cp.async.wait_group %0;" :: "n"(N));
}
__device__ __forceinline__ void mma8(float* c, const uint32_t* a, const uint32_t* b){
    asm volatile("mma.sync.aligned.m16n8k8.row.col.f32.tf32.tf32.f32 "
        "{%0,%1,%2,%3}, {%4,%5,%6,%7}, {%8,%9}, {%0,%1,%2,%3};"
        : "+f"(c[0]),"+f"(c[1]),"+f"(c[2]),"+f"(c[3])
        : "r"(a[0]),"r"(a[1]),"r"(a[2]),"r"(a[3]), "r"(b[0]),"r"(b[1]));
}

// ---------------------------------------------------------------------------
// tf32 rounding passes
// ---------------------------------------------------------------------------
__global__ __launch_bounds__(256) void round_kernel(const float4* __restrict__ src,
                                                    float4* __restrict__ dst, int n4){
    int i = blockIdx.x*256 + threadIdx.x;
    if (i < n4){
        float4 v = src[i];
        v.x = rna_tf32(v.x); v.y = rna_tf32(v.y);
        v.z = rna_tf32(v.z); v.w = rna_tf32(v.w);
        dst[i] = v;
    }
}

__global__ __launch_bounds__(256) void round3_kernel(const float4* __restrict__ s0,
                                                     const float4* __restrict__ s1,
                                                     const float4* __restrict__ s2,
                                                     float4* __restrict__ dst, int n4){
    int z = blockIdx.z;
    const float4* src = (z == 0) ? s0 : (z == 1) ? s1 : s2;
    int i = blockIdx.x*256 + threadIdx.x;
    if (i < n4){
        float4 v = src[i];
        v.x = rna_tf32(v.x); v.y = rna_tf32(v.y);
        v.z = rna_tf32(v.z); v.w = rna_tf32(v.w);
        dst[(size_t)z*n4 + i] = v;
    }
}

// ---------------------------------------------------------------------------
// Gate: g = sigmoid(X @ Wg + bg), p = (S-2)^(1-g)   (fp32 path)
// ---------------------------------------------------------------------------
__global__ __launch_bounds__(256) void gate_kernel(const float* __restrict__ X,
                                                   const float* __restrict__ Wg,
                                                   const float* __restrict__ bg,
                                                   float* __restrict__ g,
                                                   float* __restrict__ p) {
    int row = blockIdx.x;
    int tid = threadIdx.x;
    float4 xv = *(const float4*)(X + (size_t)row*HH + tid*4);
    float4 wv = *(const float4*)(Wg + tid*4);
    float s = xv.x*wv.x + xv.y*wv.y + xv.z*wv.z + xv.w*wv.w;
    __shared__ float red[256];
    red[tid] = s; __syncthreads();
    for (int off = 128; off > 0; off >>= 1) {
        if (tid < off) red[tid] += red[tid+off];
        __syncthreads();
    }
    if (tid == 0) {
        float z = red[0] + bg[0];
        float gg = 1.f / (1.f + expf(-z));
        g[row] = gg;
        p[row] = powf((float)(SS-2), 1.f - gg);
    }
}

// ---------------------------------------------------------------------------
// Query ordering: stable counting sort of each batch's 2048 rows into
// 4 pi-buckets (narrow bands first), preserving i-order within buckets.
// Grid: BB CTAs x 256 threads; each thread owns 8 consecutive rows.
// ---------------------------------------------------------------------------
__global__ __launch_bounds__(256) void order_kernel(const float* __restrict__ p,
                                                    int* __restrict__ perm){
    const int b = blockIdx.x, tid = threadIdx.x;
    const float* pb = p + (size_t)b*SS;
    __shared__ uint8_t bk[SS];
    __shared__ int sc[1024];           // [bucket][thread] counts -> inclusive scan
    int myc[4] = {0,0,0,0};
    #pragma unroll
    for (int e = 0; e < 8; e++){
        int i = tid*8 + e;
        float pi = pb[i];
        int k = (pi < 96.f) ? 0 : (pi < 288.f) ? 1 : (pi < 800.f) ? 2 : 3;
        bk[i] = (uint8_t)k; myc[k]++;
    }
    #pragma unroll
    for (int k = 0; k < 4; k++) sc[k*256 + tid] = myc[k];
    __syncthreads();
    // Hillis-Steele inclusive scan over the flattened 1024 counts
    for (int off = 1; off < 1024; off <<= 1){
        int v[4];
        #pragma unroll
        for (int k = 0; k < 4; k++){
            int idx = k*256 + tid;
            v[k] = (idx >= off) ? sc[idx - off] : 0;
        }
        __syncthreads();
        #pragma unroll
        for (int k = 0; k < 4; k++) sc[k*256 + tid] += v[k];
        __syncthreads();
    }
    int base[4];
    #pragma unroll
    for (int k = 0; k < 4; k++) base[k] = sc[k*256 + tid] - myc[k];  // exclusive
    #pragma unroll
    for (int e = 0; e < 8; e++){
        int i = tid*8 + e;
        int k = bk[i];
        perm[(size_t)b*SS + base[k]++] = i;
    }
}

// ---------------------------------------------------------------------------
// Merged tf32 QKV projection: z selects (W, bias, C).
// ---------------------------------------------------------------------------
template<int BN, int WM, int WN>
__global__ __launch_bounds__(256, 2) void gemm_proj(
    const float* __restrict__ A, const float* __restrict__ Wall,
    const float* __restrict__ b0, const float* __restrict__ b1,
    const float* __restrict__ b2,
    float* __restrict__ C0, float* __restrict__ C1, float* __restrict__ C2)
{
    const int z = blockIdx.z;
    const float* Bp = Wall + (size_t)z*HH*HH;
    const float* bias = (z == 0) ? b0 : (z == 1) ? b1 : b2;
    float* C = (z == 0) ? C0 : (z == 1) ? C1 : C2;

    constexpr int BM = 128, BK = 32;
    constexpr int ASTR = BK + 4;
    constexpr int BSTR = BN + 4;
    constexpr int ASZ = BM * ASTR;
    constexpr int BSZ = BK * BSTR;
    extern __shared__ float smf[];
    float* Asm[2] = { smf, smf + ASZ };
    float* Bsm[2] = { smf + 2*ASZ, smf + 2*ASZ + BSZ };

    const int tid = threadIdx.x, lane = tid & 31, wid = tid >> 5;
    constexpr int NWN = BN / WN;
    const int wm = wid / NWN, wn = wid % NWN;
    constexpr int MT = WM / 16, NT = WN / 8;

    const int iBase = blockIdx.y * BM;
    const int jBase = blockIdx.x * BN;

    float acc[MT][NT][4] = {};

    auto loadA = [&](int s, int kk){
        uint32_t base = (uint32_t)__cvta_generic_to_shared(Asm[s]);
        #pragma unroll
        for (int i = 0; i < (BM*8)/256; i++){
            int f = tid + i*256;
            int r = f >> 3, c = (f & 7) * 4;
            cp16(base + (uint32_t)(r*ASTR + c)*4u, A + (size_t)(iBase + r)*HH + kk + c);
        }
    };
    auto loadB = [&](int s, int kk){
        uint32_t base = (uint32_t)__cvta_generic_to_shared(Bsm[s]);
        #pragma unroll
        for (int i = 0; i < (BK*(BN/4))/256; i++){
            int f = tid + i*256;
            int k = f / (BN/4), c = (f % (BN/4)) * 4;
            cp16(base + (uint32_t)(k*BSTR + c)*4u, Bp + (size_t)(kk + k)*HH + jBase + c);
        }
    };

    loadA(0, 0); loadB(0, 0); cp_commit();
    const int nK = HH / BK;
    for (int kt = 0; kt < nK; kt++){
        const int cur = kt & 1;
        if (kt + 1 < nK){
            loadA(cur ^ 1, (kt+1)*BK); loadB(cur ^ 1, (kt+1)*BK);
            cp_commit(); cp_wait<1>();
        } else {
            cp_wait<0>();
        }
        __syncthreads();
        const float* As = Asm[cur];
        const float* Bs = Bsm[cur];
        #pragma unroll
        for (int ks = 0; ks < BK/8; ks++){
            uint32_t af[MT][4]; uint32_t bf[NT][2];
            #pragma unroll
            for (int mt = 0; mt < MT; mt++){
                int r0 = wm*WM + mt*16 + (lane >> 2);
                int c0 = ks*8 + (lane & 3);
                af[mt][0] = __float_as_uint(As[r0*ASTR + c0]);
                af[mt][1] = __float_as_uint(As[(r0+8)*ASTR + c0]);
                af[mt][2] = __float_as_uint(As[r0*ASTR + c0 + 4]);
                af[mt][3] = __float_as_uint(As[(r0+8)*ASTR + c0 + 4]);
            }
            #pragma unroll
            for (int nt = 0; nt < NT; nt++){
                int n = wn*WN + nt*8 + (lane >> 2);
                int k0 = ks*8 + (lane & 3);
                bf[nt][0] = __float_as_uint(Bs[k0*BSTR + n]);
                bf[nt][1] = __float_as_uint(Bs[(k0+4)*BSTR + n]);
            }
            #pragma unroll
            for (int mt = 0; mt < MT; mt++)
                #pragma unroll
                for (int nt = 0; nt < NT; nt++)
                    mma8(acc[mt][nt], af[mt], bf[nt]);
        }
        __syncthreads();
    }

    #pragma unroll
    for (int mt = 0; mt < MT; mt++){
        int r0 = iBase + wm*WM + mt*16 + (lane >> 2);
        #pragma unroll
        for (int nt = 0; nt < NT; nt++){
            int c0 = jBase + wn*WN + nt*8 + 2*(lane & 3);
            float bb0 = __ldg(bias + c0), bb1 = __ldg(bias + c0 + 1);
            float2 p0 = { rna_tf32(acc[mt][nt][0] + bb0), rna_tf32(acc[mt][nt][1] + bb1) };
            float2 p1 = { rna_tf32(acc[mt][nt][2] + bb0), rna_tf32(acc[mt][nt][3] + bb1) };
            *(float2*)(C + (size_t)r0*HH + c0)     = p0;
            *(float2*)(C + (size_t)(r0+8)*HH + c0) = p1;
        }
    }
}

// ---------------------------------------------------------------------------
// Fused flash attention with query reordering + per-warp band skipping.
// Queries are processed in perm order (rows grouped by band width), so each
// warp's union band stays tight. Outputs scatter back to original rows.
// Loads / syncs stay unconditional (pipeline + barrier structure intact).
// ---------------------------------------------------------------------------
#define QSTR 68
#define KSTR 68
#define VSTR 72
#define JT   64
#define NJT  (SS/JT)   // 32

__device__ __forceinline__ float penexp(float om, float gi, float pi, int i,
                                        float gj, int j, float se){
    float res = om * fmaxf(om - gj, 0.f) + gi * fminf(om + gj, 1.f);
    float scope = fminf(fmaxf(pi + 2.f - fabsf((float)(i - j)), 1e-32f), 1.f);
    float pen = fmaxf(res * scope, 1e-32f);
    return pen * __expf(se);
}

__global__ __launch_bounds__(256, 2) void attn_fused(
    const float* __restrict__ Q, const float* __restrict__ Kg,
    const float* __restrict__ Vg, const float* __restrict__ g,
    const float* __restrict__ p, const int* __restrict__ perm,
    float* __restrict__ out)
{
    const int bh = blockIdx.y, b = bh >> 4, h = bh & 15;
    const int iBase = blockIdx.x * 128;
    const int tid = threadIdx.x, lane = tid & 31, wid = tid >> 5;

    extern __shared__ float sm[];
    float* Qs  = sm;                      // 128*68
    float* Ks0 = Qs  + 128*QSTR;          // 2 x 64*68
    float* Vs0 = Ks0 + 2*JT*KSTR;         // 2 x 64*72
    float* gs  = Vs0 + 2*JT*VSTR;         // 2048

    const float* Qp = Q  + (size_t)b*SS*HH + h*HD;
    const float* Kp = Kg + (size_t)b*SS*HH + h*HD;
    const float* Vp = Vg + (size_t)b*SS*HH + h*HD;
    const int* pm = perm + (size_t)b*SS;

    // prologue loads: Q tile (gathered through perm), g row, K0/V0
    {
        uint32_t qb = (uint32_t)__cvta_generic_to_shared(Qs);
        #pragma unroll
        for (int l = 0; l < 8; l++){
            int f = tid + l*256;
            int r = f >> 4, c4 = f & 15;
            int pr = __ldg(pm + iBase + r);
            cp16(qb + (uint32_t)(r*QSTR + c4*4)*4u, Qp + (size_t)pr*HH + c4*4);
        }
        uint32_t gb = (uint32_t)__cvta_generic_to_shared(gs);
        #pragma unroll
        for (int l = 0; l < 2; l++){
            int f = tid + l*256;
            cp16(gb + (uint32_t)f*16u, g + (size_t)b*SS + f*4);
        }
    }
    auto loadK = [&](int s, int j0){
        uint32_t kb = (uint32_t)__cvta_generic_to_shared(Ks0 + s*JT*KSTR);
        #pragma unroll
        for (int l = 0; l < 4; l++){
            int f = tid + l*256;
            int r = f >> 4, c4 = f & 15;
            cp16(kb + (uint32_t)(r*KSTR + c4*4)*4u, Kp + (size_t)(j0 + r)*HH + c4*4);
        }
    };
    auto loadV = [&](int s, int j0){
        uint32_t vb = (uint32_t)__cvta_generic_to_shared(Vs0 + s*JT*VSTR);
        #pragma unroll
        for (int l = 0; l < 4; l++){
            int f = tid + l*256;
            int r = f >> 4, c4 = f & 15;
            cp16(vb + (uint32_t)(r*VSTR + c4*4)*4u, Vp + (size_t)(j0 + r)*HH + c4*4);
        }
    };
    loadK(0, 0); loadV(0, 0); cp_commit();

    const int lr0 = wid*16 + (lane >> 2);    // local row in tile (perm position)
    const int lr1 = lr0 + 8;
    const int ri0 = __ldg(pm + iBase + lr0); // actual sequence rows
    const int ri1 = __ldg(pm + iBase + lr1);
    const float gi0 = __ldg(g + (size_t)b*SS + ri0);
    const float gi1 = __ldg(g + (size_t)b*SS + ri1);
    const float pi0 = __ldg(p + (size_t)b*SS + ri0);
    const float pi1 = __ldg(p + (size_t)b*SS + ri1);
    const float om0 = 1.f - gi0, om1 = 1.f - gi1;

    // per-warp band: tiles fully outside [blo, bhi] contribute pen=1e-32 only
    float wlo = fminf((float)ri0 - pi0, (float)ri1 - pi1);
    float whi = fmaxf((float)ri0 + pi0, (float)ri1 + pi1);
    #pragma unroll
    for (int off = 16; off > 0; off >>= 1){
        wlo = fminf(wlo, __shfl_xor_sync(0xffffffffu, wlo, off));
        whi = fmaxf(whi, __shfl_xor_sync(0xffffffffu, whi, off));
    }
    const int blo = (int)floorf(wlo) - 3;
    const int bhi = (int)ceilf(whi) + 3;

    float m0 = -1e30f, m1 = -1e30f, l0 = 0.f, l1 = 0.f;
    float oacc[8][4] = {};

    const int q = lane & 3;
    const int basel = lane & 28;
    const int src0 = basel | (q >> 1);
    const int src2 = src0 + 2;

    for (int jt = 0; jt < NJT; jt++){
        const int cur = jt & 1;
        if (jt + 1 < NJT){
            loadK(cur ^ 1, (jt+1)*JT); loadV(cur ^ 1, (jt+1)*JT);
            cp_commit(); cp_wait<1>();
        } else {
            cp_wait<0>();
        }
        __syncthreads();
        const int jBase = jt*JT;
        const bool active = (jBase + JT - 1 >= blo) && (jBase <= bhi);
        if (active){
            const float* Ks = Ks0 + cur*JT*KSTR;
            const float* Vs = Vs0 + cur*JT*VSTR;

            // --- S = Q K^T (raw, scale folded later) ---
            float sacc[8][4];
            #pragma unroll
            for (int nt = 0; nt < 8; nt++){
                sacc[nt][0]=0.f; sacc[nt][1]=0.f; sacc[nt][2]=0.f; sacc[nt][3]=0.f;
            }
            #pragma unroll
            for (int ks = 0; ks < 8; ks++){
                const int kk = ks*8 + q;
                uint32_t af[4];
                af[0] = __float_as_uint(Qs[lr0*QSTR + kk]);
                af[1] = __float_as_uint(Qs[lr1*QSTR + kk]);
                af[2] = __float_as_uint(Qs[lr0*QSTR + kk + 4]);
                af[3] = __float_as_uint(Qs[lr1*QSTR + kk + 4]);
                #pragma unroll
                for (int nt = 0; nt < 8; nt++){
                    const int n = nt*8 + (lane >> 2);
                    uint32_t bf[2];
                    bf[0] = __float_as_uint(Ks[n*KSTR + kk]);
                    bf[1] = __float_as_uint(Ks[n*KSTR + kk + 4]);
                    mma8(sacc[nt], af, bf);
                }
            }

            // --- online softmax ---
            float tm0 = -1e30f, tm1 = -1e30f;
            #pragma unroll
            for (int nt = 0; nt < 8; nt++){
                tm0 = fmaxf(tm0, fmaxf(sacc[nt][0], sacc[nt][1]));
                tm1 = fmaxf(tm1, fmaxf(sacc[nt][2], sacc[nt][3]));
            }
            tm0 = fmaxf(tm0, __shfl_xor_sync(0xffffffffu, tm0, 1));
            tm0 = fmaxf(tm0, __shfl_xor_sync(0xffffffffu, tm0, 2));
            tm1 = fmaxf(tm1, __shfl_xor_sync(0xffffffffu, tm1, 1));
            tm1 = fmaxf(tm1, __shfl_xor_sync(0xffffffffu, tm1, 2));
            tm0 *= 0.125f; tm1 *= 0.125f;
            const float m0n = fmaxf(m0, tm0), m1n = fmaxf(m1, tm1);
            const float f0 = __expf(m0 - m0n), f1 = __expf(m1 - m1n);
            m0 = m0n; m1 = m1n;
            l0 *= f0; l1 *= f1;
            #pragma unroll
            for (int dn = 0; dn < 8; dn++){
                oacc[dn][0] *= f0; oacc[dn][1] *= f0;
                oacc[dn][2] *= f1; oacc[dn][3] *= f1;
            }
            float rs0 = 0.f, rs1 = 0.f;
            #pragma unroll
            for (int nt = 0; nt < 8; nt++){
                const int j0 = jBase + nt*8 + 2*q;
                const int j1 = j0 + 1;
                const float gj0 = gs[j0], gj1 = gs[j1];
                float t00 = penexp(om0, gi0, pi0, ri0, gj0, j0, sacc[nt][0]*0.125f - m0);
                float t01 = penexp(om0, gi0, pi0, ri0, gj1, j1, sacc[nt][1]*0.125f - m0);
                float t10 = penexp(om1, gi1, pi1, ri1, gj0, j0, sacc[nt][2]*0.125f - m1);
                float t11 = penexp(om1, gi1, pi1, ri1, gj1, j1, sacc[nt][3]*0.125f - m1);
                sacc[nt][0] = t00; sacc[nt][1] = t01;
                sacc[nt][2] = t10; sacc[nt][3] = t11;
                rs0 += t00 + t01; rs1 += t10 + t11;
            }
            rs0 += __shfl_xor_sync(0xffffffffu, rs0, 1);
            rs0 += __shfl_xor_sync(0xffffffffu, rs0, 2);
            rs1 += __shfl_xor_sync(0xffffffffu, rs1, 1);
            rs1 += __shfl_xor_sync(0xffffffffu, rs1, 2);
            l0 += rs0; l1 += rs1;

            // --- O += P V : quad-shuffle C-frag -> A-frag, then mma over d ---
            #pragma unroll
            for (int kc = 0; kc < 8; kc++){
                float x0 = __shfl_sync(0xffffffffu, sacc[kc][0], src0);
                float x1 = __shfl_sync(0xffffffffu, sacc[kc][1], src0);
                float y0 = __shfl_sync(0xffffffffu, sacc[kc][0], src2);
                float y1 = __shfl_sync(0xffffffffu, sacc[kc][1], src2);
                float z0 = __shfl_sync(0xffffffffu, sacc[kc][2], src0);
                float z1 = __shfl_sync(0xffffffffu, sacc[kc][3], src0);
                float w0 = __shfl_sync(0xffffffffu, sacc[kc][2], src2);
                float w1 = __shfl_sync(0xffffffffu, sacc[kc][3], src2);
                const bool odd = (q & 1);
                uint32_t af[4];
                af[0] = __float_as_uint(rna_tf32(odd ? x1 : x0));  // (r0, q)
                af[1] = __float_as_uint(rna_tf32(odd ? z1 : z0));  // (r1, q)
                af[2] = __float_as_uint(rna_tf32(odd ? y1 : y0));  // (r0, q+4)
                af[3] = __float_as_uint(rna_tf32(odd ? w1 : w0));  // (r1, q+4)
                const int kb = kc*8 + q;
                #pragma unroll
                for (int dn = 0; dn < 8; dn++){
                    const int d0 = dn*8 + (lane >> 2);
                    uint32_t bf[2];
                    bf[0] = __float_as_uint(Vs[kb*VSTR + d0]);
                    bf[1] = __float_as_uint(Vs[(kb+4)*VSTR + d0]);
                    mma8(oacc[dn], af, bf);
                }
            }
        }
        __syncthreads();
    }

    // epilogue: scatter to original rows
    const float inv0 = 1.f / l0, inv1 = 1.f / l1;
    float* op = out + (size_t)b*SS*HH + h*HD;
    #pragma unroll
    for (int dn = 0; dn < 8; dn++){
        const int c0 = dn*8 + 2*q;
        float2 o0 = { oacc[dn][0]*inv0, oacc[dn][1]*inv0 };
        float2 o1 = { oacc[dn][2]*inv1, oacc[dn][3]*inv1 };
        *(float2*)(op + (size_t)ri0*HH + c0) = o0;
        *(float2*)(op + (size_t)ri1*HH + c0) = o1;
    }
}

// ---------------------------------------------------------------------------
extern "C" void kernel_launch(void* const* d_in, const int* in_sizes, int n_in,
                              void* d_out, int out_size) {
    const float* X  = (const float*)d_in[0];
    const float* Wq = (const float*)d_in[1];
    const float* bq = (const float*)d_in[2];
    const float* Wk = (const float*)d_in[3];
    const float* bk = (const float*)d_in[4];
    const float* Wv = (const float*)d_in[5];
    const float* bv = (const float*)d_in[6];
    const float* Wg = (const float*)d_in[7];
    const float* bg = (const float*)d_in[8];
    float* out = (float*)d_out;

    float *q, *k, *v, *x, *w, *g, *p;
    int *perm;
    cudaGetSymbolAddress((void**)&q,  d_q);
    cudaGetSymbolAddress((void**)&k,  d_k);
    cudaGetSymbolAddress((void**)&v,  d_v);
    cudaGetSymbolAddress((void**)&x,  d_x);
    cudaGetSymbolAddress((void**)&w,  d_w);
    cudaGetSymbolAddress((void**)&g,  d_g);
    cudaGetSymbolAddress((void**)&p,  d_p);
    cudaGetSymbolAddress((void**)&perm, d_perm);

    constexpr int SM_PROJ = 2*(128*36 + 32*132)*4;                           // 70656
    constexpr int SM_ATTN = (128*QSTR + 2*JT*KSTR + 2*JT*VSTR + 2048)*4;     // 114688
    cudaFuncSetAttribute(gemm_proj<128,64,32>,
                         cudaFuncAttributeMaxDynamicSharedMemorySize, SM_PROJ);
    cudaFuncSetAttribute(attn_fused,
                         cudaFuncAttributeMaxDynamicSharedMemorySize, SM_ATTN);

    // rounding passes + gate + query ordering
    round_kernel<<<(BS*HH/4 + 255)/256, 256>>>((const float4*)X, (float4*)x, BS*HH/4);
    dim3 gr((HH*HH/4 + 255)/256, 1, 3);
    round3_kernel<<<gr, 256>>>((const float4*)Wq, (const float4*)Wk,
                               (const float4*)Wv, (float4*)w, HH*HH/4);
    gate_kernel<<<BS, 256>>>(X, Wg, bg, g, p);
    order_kernel<<<BB, 256>>>(p, perm);

    // one merged QKV projection launch
    dim3 gp(HH/128, BS/128, 3);   // (8, 32, 3)
    gemm_proj<128,64,32><<<gp, 256, SM_PROJ>>>(x, w, bq, bk, bv, q, k, v);

    dim3 ga(SS/128, BH);   // (16, 32)
    attn_fused<<<ga, 256, SM_ATTN>>>(q, k, v, g, p, perm, out);
}

// round 8
// speedup vs baseline: 8.0375x; 1.5161x over previous
#include <cuda_runtime.h>
#include <cuda_fp16.h>
#include <math.h>
#include <stdint.h>

#define BB 2
#define SS 2048
#define HH 1024
#define NH 16
#define HD 64
#define BS (BB*SS)   // 4096
#define BH (BB*NH)   // 32

// Scratch (allocation-free: static device globals)
__device__ __half d_q[(size_t)BS*HH];
__device__ __half d_k[(size_t)BS*HH];
__device__ __half d_vt[(size_t)HH*BS];     // V transposed: [d][token]
__device__ __half d_x[(size_t)BS*HH];      // fp16 X
__device__ __half d_w[(size_t)3*HH*HH];    // fp16 W^T (per z: [n][k])
__device__ float  d_g[BS];
__device__ float  d_p[BS];
__device__ int    d_perm[BS];              // bucketed query order per batch

// ---------------------------------------------------------------------------
// helpers
// ---------------------------------------------------------------------------
__device__ __forceinline__ void cp16(uint32_t dst, const void* src){
    asm volatile("cp.async.cg.shared.global [%0], [%1], 16;" :: "r"(dst), "l"(src));
}
__device__ __forceinline__ void cp_commit(){ asm volatile("cp.async.commit_group;"); }
template<int N> __device__ __forceinline__ void cp_wait(){
    asm volatile("cp.async.wait_group %0;" :: "n"(N));
}
__device__ __forceinline__ void mma16(float* c, const uint32_t* a, const uint32_t* b){
    asm volatile("mma.sync.aligned.m16n8k16.row.col.f32.f16.f16.f32 "
        "{%0,%1,%2,%3}, {%4,%5,%6,%7}, {%8,%9}, {%0,%1,%2,%3};"
        : "+f"(c[0]),"+f"(c[1]),"+f"(c[2]),"+f"(c[3])
        : "r"(a[0]),"r"(a[1]),"r"(a[2]),"r"(a[3]), "r"(b[0]),"r"(b[1]));
}
__device__ __forceinline__ uint32_t packh2(float a, float b){
    __half2 h = __floats2half2_rn(a, b);
    return *reinterpret_cast<uint32_t*>(&h);
}

// ---------------------------------------------------------------------------
// X fp32 -> fp16
// ---------------------------------------------------------------------------
__global__ __launch_bounds__(256) void cvtx_kernel(const float4* __restrict__ src,
                                                   uint2* __restrict__ dst, int n4){
    int i = blockIdx.x*256 + threadIdx.x;
    if (i < n4){
        float4 v = src[i];
        uint2 o = { packh2(v.x, v.y), packh2(v.z, v.w) };
        dst[i] = o;
    }
}

// ---------------------------------------------------------------------------
// W fp32 [k][n] -> fp16 W^T [n][k], tiled; z selects source. block (32,8)
// ---------------------------------------------------------------------------
__global__ __launch_bounds__(256) void tconv_kernel(const float* __restrict__ s0,
                                                    const float* __restrict__ s1,
                                                    const float* __restrict__ s2,
                                                    __half* __restrict__ dst){
    const int z = blockIdx.z;
    const float* W = (z == 0) ? s0 : (z == 1) ? s1 : s2;
    __shared__ float ts[32][33];
    const int n0 = blockIdx.x*32, k0 = blockIdx.y*32;
    const int tx = threadIdx.x, ty = threadIdx.y;
    #pragma unroll
    for (int yy = 0; yy < 4; yy++){
        int k = k0 + ty + yy*8;
        ts[ty + yy*8][tx] = W[(size_t)k*HH + n0 + tx];
    }
    __syncthreads();
    #pragma unroll
    for (int yy = 0; yy < 4; yy++){
        int n = n0 + ty + yy*8;
        dst[(size_t)z*HH*HH + (size_t)n*HH + k0 + tx] = __float2half_rn(ts[tx][ty + yy*8]);
    }
}

// ---------------------------------------------------------------------------
// Gate: g = sigmoid(X @ Wg + bg), p = (S-2)^(1-g)   (fp32 path)
// ---------------------------------------------------------------------------
__global__ __launch_bounds__(256) void gate_kernel(const float* __restrict__ X,
                                                   const float* __restrict__ Wg,
                                                   const float* __restrict__ bg,
                                                   float* __restrict__ g,
                                                   float* __restrict__ p) {
    int row = blockIdx.x;
    int tid = threadIdx.x;
    float4 xv = *(const float4*)(X + (size_t)row*HH + tid*4);
    float4 wv = *(const float4*)(Wg + tid*4);
    float s = xv.x*wv.x + xv.y*wv.y + xv.z*wv.z + xv.w*wv.w;
    __shared__ float red[256];
    red[tid] = s; __syncthreads();
    for (int off = 128; off > 0; off >>= 1) {
        if (tid < off) red[tid] += red[tid+off];
        __syncthreads();
    }
    if (tid == 0) {
        float z = red[0] + bg[0];
        float gg = 1.f / (1.f + expf(-z));
        g[row] = gg;
        p[row] = powf((float)(SS-2), 1.f - gg);
    }
}

// ---------------------------------------------------------------------------
// Query ordering: stable counting sort into 4 pi-buckets per batch.
// ---------------------------------------------------------------------------
__global__ __launch_bounds__(256) void order_kernel(const float* __restrict__ p,
                                                    int* __restrict__ perm){
    const int b = blockIdx.x, tid = threadIdx.x;
    const float* pb = p + (size_t)b*SS;
    __shared__ uint8_t bk[SS];
    __shared__ int sc[1024];
    int myc[4] = {0,0,0,0};
    #pragma unroll
    for (int e = 0; e < 8; e++){
        int i = tid*8 + e;
        float pi = pb[i];
        int k = (pi < 96.f) ? 0 : (pi < 288.f) ? 1 : (pi < 800.f) ? 2 : 3;
        bk[i] = (uint8_t)k; myc[k]++;
    }
    #pragma unroll
    for (int k = 0; k < 4; k++) sc[k*256 + tid] = myc[k];
    __syncthreads();
    for (int off = 1; off < 1024; off <<= 1){
        int v[4];
        #pragma unroll
        for (int k = 0; k < 4; k++){
            int idx = k*256 + tid;
            v[k] = (idx >= off) ? sc[idx - off] : 0;
        }
        __syncthreads();
        #pragma unroll
        for (int k = 0; k < 4; k++) sc[k*256 + tid] += v[k];
        __syncthreads();
    }
    int base[4];
    #pragma unroll
    for (int k = 0; k < 4; k++) base[k] = sc[k*256 + tid] - myc[k];
    #pragma unroll
    for (int e = 0; e < 8; e++){
        int i = tid*8 + e;
        int k = bk[i];
        perm[(size_t)b*SS + base[k]++] = i;
    }
}

// ---------------------------------------------------------------------------
// Merged fp16 QKV projection. z selects (W^T slice, bias, output).
// z=0,1: C half [token][1024]. z=2: V^T half [d][token].
// BM=128, BN=128, BK=32, 8 warps (2x4), WM=64, WN=32.
// ---------------------------------------------------------------------------
#define PSTR 40   // smem row stride in halves (32 + 8 pad)

__global__ __launch_bounds__(256, 2) void gemm_proj(
    const __half* __restrict__ A, const __half* __restrict__ Wall,
    const float* __restrict__ b0, const float* __restrict__ b1,
    const float* __restrict__ b2,
    __half* __restrict__ C0, __half* __restrict__ C1, __half* __restrict__ Vt)
{
    const int z = blockIdx.z;
    const __half* Bp = Wall + (size_t)z*HH*HH;
    const float* bias = (z == 0) ? b0 : (z == 1) ? b1 : b2;

    extern __shared__ __half smh[];
    __half* Asm[2] = { smh, smh + 128*PSTR };
    __half* Bsm[2] = { smh + 2*128*PSTR, smh + 3*128*PSTR };

    const int tid = threadIdx.x, lane = tid & 31, wid = tid >> 5;
    const int wm = wid >> 2, wn = wid & 3;
    const int gq = lane & 3, gr = lane >> 2;

    const int iBase = blockIdx.y * 128;
    const int jBase = blockIdx.x * 128;

    float acc[4][4][4] = {};

    auto loadA = [&](int s, int kk){
        uint32_t base = (uint32_t)__cvta_generic_to_shared(Asm[s]);
        #pragma unroll
        for (int i = 0; i < 2; i++){
            int f = tid + i*256;
            int r = f >> 2, c8 = (f & 3) * 8;
            cp16(base + (uint32_t)(r*PSTR + c8)*2u, A + (size_t)(iBase + r)*HH + kk + c8);
        }
    };
    auto loadB = [&](int s, int kk){
        uint32_t base = (uint32_t)__cvta_generic_to_shared(Bsm[s]);
        #pragma unroll
        for (int i = 0; i < 2; i++){
            int f = tid + i*256;
            int n = f >> 2, c8 = (f & 3) * 8;
            cp16(base + (uint32_t)(n*PSTR + c8)*2u, Bp + (size_t)(jBase + n)*HH + kk + c8);
        }
    };

    loadA(0, 0); loadB(0, 0); cp_commit();
    const int nK = HH / 32;
    for (int kt = 0; kt < nK; kt++){
        const int cur = kt & 1;
        if (kt + 1 < nK){
            loadA(cur ^ 1, (kt+1)*32); loadB(cur ^ 1, (kt+1)*32);
            cp_commit(); cp_wait<1>();
        } else {
            cp_wait<0>();
        }
        __syncthreads();
        const __half* As = Asm[cur];
        const __half* Bs = Bsm[cur];
        #pragma unroll
        for (int ks = 0; ks < 2; ks++){
            const int k0 = ks*16 + 2*gq;
            uint32_t af[4][4]; uint32_t bf[4][2];
            #pragma unroll
            for (int mt = 0; mt < 4; mt++){
                int r0 = wm*64 + mt*16 + gr;
                af[mt][0] = *(const uint32_t*)&As[r0*PSTR + k0];
                af[mt][1] = *(const uint32_t*)&As[(r0+8)*PSTR + k0];
                af[mt][2] = *(const uint32_t*)&As[r0*PSTR + k0 + 8];
                af[mt][3] = *(const uint32_t*)&As[(r0+8)*PSTR + k0 + 8];
            }
            #pragma unroll
            for (int nt = 0; nt < 4; nt++){
                int n = wn*32 + nt*8 + gr;
                bf[nt][0] = *(const uint32_t*)&Bs[n*PSTR + k0];
                bf[nt][1] = *(const uint32_t*)&Bs[n*PSTR + k0 + 8];
            }
            #pragma unroll
            for (int mt = 0; mt < 4; mt++)
                #pragma unroll
                for (int nt = 0; nt < 4; nt++)
                    mma16(acc[mt][nt], af[mt], bf[nt]);
        }
        __syncthreads();
    }

    // epilogue
    #pragma unroll
    for (int mt = 0; mt < 4; mt++){
        int r0 = iBase + wm*64 + mt*16 + gr;
        int r1 = r0 + 8;
        #pragma unroll
        for (int nt = 0; nt < 4; nt++){
            int c0 = jBase + wn*32 + nt*8 + 2*gq;
            float bb0 = __ldg(bias + c0), bb1 = __ldg(bias + c0 + 1);
            float v0 = acc[mt][nt][0] + bb0, v1 = acc[mt][nt][1] + bb1;
            float v2 = acc[mt][nt][2] + bb0, v3 = acc[mt][nt][3] + bb1;
            if (z == 2){
                Vt[(size_t)c0*BS + r0]     = __float2half_rn(v0);
                Vt[(size_t)(c0+1)*BS + r0] = __float2half_rn(v1);
                Vt[(size_t)c0*BS + r1]     = __float2half_rn(v2);
                Vt[(size_t)(c0+1)*BS + r1] = __float2half_rn(v3);
            } else {
                __half* C = (z == 0) ? C0 : C1;
                uint32_t p0 = packh2(v0, v1), p1 = packh2(v2, v3);
                *(uint32_t*)(C + (size_t)r0*HH + c0) = p0;
                *(uint32_t*)(C + (size_t)r1*HH + c0) = p1;
            }
        }
    }
}

// ---------------------------------------------------------------------------
// Fused fp16 flash attention with query reordering + per-warp band skipping.
// Q/K half [token][d]; V half [d][token] (transposed). S and O accumulate fp32.
// P passes to PV mma via direct C-frag -> A-frag packing (no shuffles).
// ---------------------------------------------------------------------------
#define QSTR 72   // halves
#define JT   64
#define NJT  (SS/JT)   // 32

__device__ __forceinline__ float penexp(float om, float gi, float pi, int i,
                                        float gj, int j, float se){
    float res = om * fmaxf(om - gj, 0.f) + gi * fminf(om + gj, 1.f);
    float scope = fminf(fmaxf(pi + 2.f - fabsf((float)(i - j)), 1e-32f), 1.f);
    float pen = fmaxf(res * scope, 1e-32f);
    return pen * __expf(se);
}

__global__ __launch_bounds__(256, 2) void attn_fused(
    const __half* __restrict__ Q, const __half* __restrict__ Kg,
    const __half* __restrict__ Vt, const float* __restrict__ g,
    const float* __restrict__ p, const int* __restrict__ perm,
    float* __restrict__ out)
{
    const int bh = blockIdx.y, b = bh >> 4, h = bh & 15;
    const int iBase = blockIdx.x * 128;
    const int tid = threadIdx.x, lane = tid & 31, wid = tid >> 5;

    extern __shared__ __half smh[];
    __half* Qs  = smh;                    // 128*72
    __half* Ks0 = Qs  + 128*QSTR;         // 2 x 64*72
    __half* Vs0 = Ks0 + 2*JT*QSTR;        // 2 x 64*72   ([d][j])
    float*  gs  = (float*)(Vs0 + 2*JT*QSTR);  // 2048 floats

    const __half* Qp = Q  + (size_t)b*SS*HH + h*HD;
    const __half* Kp = Kg + (size_t)b*SS*HH + h*HD;
    const int* pm = perm + (size_t)b*SS;

    // prologue loads: Q tile (gathered through perm), g row, K0/V0
    {
        uint32_t qb = (uint32_t)__cvta_generic_to_shared(Qs);
        #pragma unroll
        for (int l = 0; l < 4; l++){
            int f = tid + l*256;
            int r = f >> 3, c8 = (f & 7) * 8;
            int pr = __ldg(pm + iBase + r);
            cp16(qb + (uint32_t)(r*QSTR + c8)*2u, Qp + (size_t)pr*HH + c8);
        }
        uint32_t gb = (uint32_t)__cvta_generic_to_shared(gs);
        #pragma unroll
        for (int l = 0; l < 2; l++){
            int f = tid + l*256;
            cp16(gb + (uint32_t)f*16u, g + (size_t)b*SS + f*4);
        }
    }
    auto loadK = [&](int s, int j0){
        uint32_t kb = (uint32_t)__cvta_generic_to_shared(Ks0 + s*JT*QSTR);
        #pragma unroll
        for (int l = 0; l < 2; l++){
            int f = tid + l*256;
            int r = f >> 3, c8 = (f & 7) * 8;
            cp16(kb + (uint32_t)(r*QSTR + c8)*2u, Kp + (size_t)(j0 + r)*HH + c8);
        }
    };
    auto loadV = [&](int s, int j0){
        uint32_t vb = (uint32_t)__cvta_generic_to_shared(Vs0 + s*JT*QSTR);
        #pragma unroll
        for (int l = 0; l < 2; l++){
            int f = tid + l*256;
            int d = f >> 3, c8 = (f & 7) * 8;   // d-row, token chunk
            cp16(vb + (uint32_t)(d*QSTR + c8)*2u,
                 Vt + (size_t)(h*HD + d)*BS + b*SS + j0 + c8);
        }
    };
    loadK(0, 0); loadV(0, 0); cp_commit();

    const int gq = lane & 3, gr = lane >> 2;
    const int lr0 = wid*16 + gr;
    const int lr1 = lr0 + 8;
    const int ri0 = __ldg(pm + iBase + lr0);
    const int ri1 = __ldg(pm + iBase + lr1);
    const float gi0 = __ldg(g + (size_t)b*SS + ri0);
    const float gi1 = __ldg(g + (size_t)b*SS + ri1);
    const float pi0 = __ldg(p + (size_t)b*SS + ri0);
    const float pi1 = __ldg(p + (size_t)b*SS + ri1);
    const float om0 = 1.f - gi0, om1 = 1.f - gi1;

    float wlo = fminf((float)ri0 - pi0, (float)ri1 - pi1);
    float whi = fmaxf((float)ri0 + pi0, (float)ri1 + pi1);
    #pragma unroll
    for (int off = 16; off > 0; off >>= 1){
        wlo = fminf(wlo, __shfl_xor_sync(0xffffffffu, wlo, off));
        whi = fmaxf(whi, __shfl_xor_sync(0xffffffffu, whi, off));
    }
    const int blo = (int)floorf(wlo) - 3;
    const int bhi = (int)ceilf(whi) + 3;

    float m0 = -1e30f, m1 = -1e30f, l0 = 0.f, l1 = 0.f;
    float oacc[8][4] = {};

    for (int jt = 0; jt < NJT; jt++){
        const int cur = jt & 1;
        if (jt + 1 < NJT){
            loadK(cur ^ 1, (jt+1)*JT); loadV(cur ^ 1, (jt+1)*JT);
            cp_commit(); cp_wait<1>();
        } else {
            cp_wait<0>();
        }
        __syncthreads();
        const int jBase = jt*JT;
        const bool active = (jBase + JT - 1 >= blo) && (jBase <= bhi);
        if (active){
            const __half* Ks = Ks0 + cur*JT*QSTR;
            const __half* Vs = Vs0 + cur*JT*QSTR;

            // --- S = Q K^T ---
            float sacc[8][4];
            #pragma unroll
            for (int nt = 0; nt < 8; nt++){
                sacc[nt][0]=0.f; sacc[nt][1]=0.f; sacc[nt][2]=0.f; sacc[nt][3]=0.f;
            }
            #pragma unroll
            for (int ks = 0; ks < 4; ks++){
                const int k0 = ks*16 + 2*gq;
                uint32_t af[4];
                af[0] = *(const uint32_t*)&Qs[lr0*QSTR + k0];
                af[1] = *(const uint32_t*)&Qs[lr1*QSTR + k0];
                af[2] = *(const uint32_t*)&Qs[lr0*QSTR + k0 + 8];
                af[3] = *(const uint32_t*)&Qs[lr1*QSTR + k0 + 8];
                #pragma unroll
                for (int nt = 0; nt < 8; nt++){
                    const int n = nt*8 + gr;
                    uint32_t bf[2];
                    bf[0] = *(const uint32_t*)&Ks[n*QSTR + k0];
                    bf[1] = *(const uint32_t*)&Ks[n*QSTR + k0 + 8];
                    mma16(sacc[nt], af, bf);
                }
            }

            // --- online softmax ---
            float tm0 = -1e30f, tm1 = -1e30f;
            #pragma unroll
            for (int nt = 0; nt < 8; nt++){
                tm0 = fmaxf(tm0, fmaxf(sacc[nt][0], sacc[nt][1]));
                tm1 = fmaxf(tm1, fmaxf(sacc[nt][2], sacc[nt][3]));
            }
            tm0 = fmaxf(tm0, __shfl_xor_sync(0xffffffffu, tm0, 1));
            tm0 = fmaxf(tm0, __shfl_xor_sync(0xffffffffu, tm0, 2));
            tm1 = fmaxf(tm1, __shfl_xor_sync(0xffffffffu, tm1, 1));
            tm1 = fmaxf(tm1, __shfl_xor_sync(0xffffffffu, tm1, 2));
            tm0 *= 0.125f; tm1 *= 0.125f;
            const float m0n = fmaxf(m0, tm0), m1n = fmaxf(m1, tm1);
            const float f0 = __expf(m0 - m0n), f1 = __expf(m1 - m1n);
            m0 = m0n; m1 = m1n;
            l0 *= f0; l1 *= f1;
            #pragma unroll
            for (int dn = 0; dn < 8; dn++){
                oacc[dn][0] *= f0; oacc[dn][1] *= f0;
                oacc[dn][2] *= f1; oacc[dn][3] *= f1;
            }
            float rs0 = 0.f, rs1 = 0.f;
            #pragma unroll
            for (int nt = 0; nt < 8; nt++){
                const int j0 = jBase + nt*8 + 2*gq;
                const int j1 = j0 + 1;
                const float gj0 = gs[j0], gj1 = gs[j1];
                float t00 = penexp(om0, gi0, pi0, ri0, gj0, j0, sacc[nt][0]*0.125f - m0);
                float t01 = penexp(om0, gi0, pi0, ri0, gj1, j1, sacc[nt][1]*0.125f - m0);
                float t10 = penexp(om1, gi1, pi1, ri1, gj0, j0, sacc[nt][2]*0.125f - m1);
                float t11 = penexp(om1, gi1, pi1, ri1, gj1, j1, sacc[nt][3]*0.125f - m1);
                sacc[nt][0] = t00; sacc[nt][1] = t01;
                sacc[nt][2] = t10; sacc[nt][3] = t11;
                rs0 += t00 + t01; rs1 += t10 + t11;
            }
            rs0 += __shfl_xor_sync(0xffffffffu, rs0, 1);
            rs0 += __shfl_xor_sync(0xffffffffu, rs0, 2);
            rs1 += __shfl_xor_sync(0xffffffffu, rs1, 1);
            rs1 += __shfl_xor_sync(0xffffffffu, rs1, 2);
            l0 += rs0; l1 += rs1;

            // --- O += P V : C-frag pairs map directly onto fp16 A-frags ---
            #pragma unroll
            for (int kc = 0; kc < 4; kc++){
                uint32_t af[4];
                af[0] = packh2(sacc[2*kc][0],   sacc[2*kc][1]);
                af[1] = packh2(sacc[2*kc][2],   sacc[2*kc][3]);
                af[2] = packh2(sacc[2*kc+1][0], sacc[2*kc+1][1]);
                af[3] = packh2(sacc[2*kc+1][2], sacc[2*kc+1][3]);
                const int kb = kc*16 + 2*gq;
                #pragma unroll
                for (int dn = 0; dn < 8; dn++){
                    const int d0 = dn*8 + gr;
                    uint32_t bf[2];
                    bf[0] = *(const uint32_t*)&Vs[d0*QSTR + kb];
                    bf[1] = *(const uint32_t*)&Vs[d0*QSTR + kb + 8];
                    mma16(oacc[dn], af, bf);
                }
            }
        }
        __syncthreads();
    }

    // epilogue: scatter to original rows (fp32 output)
    const float inv0 = 1.f / l0, inv1 = 1.f / l1;
    float* op = out + (size_t)b*SS*HH + h*HD;
    #pragma unroll
    for (int dn = 0; dn < 8; dn++){
        const int c0 = dn*8 + 2*gq;
        float2 o0 = { oacc[dn][0]*inv0, oacc[dn][1]*inv0 };
        float2 o1 = { oacc[dn][2]*inv1, oacc[dn][3]*inv1 };
        *(float2*)(op + (size_t)ri0*HH + c0) = o0;
        *(float2*)(op + (size_t)ri1*HH + c0) = o1;
    }
}

// ---------------------------------------------------------------------------
extern "C" void kernel_launch(void* const* d_in, const int* in_sizes, int n_in,
                              void* d_out, int out_size) {
    const float* X  = (const float*)d_in[0];
    const float* Wq = (const float*)d_in[1];
    const float* bq = (const float*)d_in[2];
    const float* Wk = (const float*)d_in[3];
    const float* bk = (const float*)d_in[4];
    const float* Wv = (const float*)d_in[5];
    const float* bv = (const float*)d_in[6];
    const float* Wg = (const float*)d_in[7];
    const float* bg = (const float*)d_in[8];
    float* out = (float*)d_out;

    __half *q, *k, *vt, *x, *w;
    float *g, *p;
    int *perm;
    cudaGetSymbolAddress((void**)&q,  d_q);
    cudaGetSymbolAddress((void**)&k,  d_k);
    cudaGetSymbolAddress((void**)&vt, d_vt);
    cudaGetSymbolAddress((void**)&x,  d_x);
    cudaGetSymbolAddress((void**)&w,  d_w);
    cudaGetSymbolAddress((void**)&g,  d_g);
    cudaGetSymbolAddress((void**)&p,  d_p);
    cudaGetSymbolAddress((void**)&perm, d_perm);

    constexpr int SM_PROJ = 4*128*PSTR*2;                                    // 40960
    constexpr int SM_ATTN = (128*QSTR + 2*JT*QSTR + 2*JT*QSTR)*2 + SS*4;     // 63488
    cudaFuncSetAttribute(gemm_proj,
                         cudaFuncAttributeMaxDynamicSharedMemorySize, SM_PROJ);
    cudaFuncSetAttribute(attn_fused,
                         cudaFuncAttributeMaxDynamicSharedMemorySize, SM_ATTN);

    // prep: converts + gate + ordering
    cvtx_kernel<<<(BS*HH/4 + 255)/256, 256>>>((const float4*)X, (uint2*)x, BS*HH/4);
    dim3 gt(HH/32, HH/32, 3);
    tconv_kernel<<<gt, dim3(32,8)>>>(Wq, Wk, Wv, w);
    gate_kernel<<<BS, 256>>>(X, Wg, bg, g, p);
    order_kernel<<<BB, 256>>>(p, perm);

    // merged QKV projection
    dim3 gp(HH/128, BS/128, 3);   // (8, 32, 3)
    gemm_proj<<<gp, 256, SM_PROJ>>>(x, w, bq, bk, bv, q, k, vt);

    dim3 ga(SS/128, BH);   // (16, 32)
    attn_fused<<<ga, 256, SM_ATTN>>>(q, k, vt, g, p, perm, out);
}

// round 9
// speedup vs baseline: 8.2745x; 1.0295x over previous
#include <cuda_runtime.h>
#include <cuda_fp16.h>
#include <math.h>
#include <stdint.h>

#define BB 2
#define SS 2048
#define HH 1024
#define NH 16
#define HD 64
#define BS (BB*SS)   // 4096
#define BH (BB*NH)   // 32

// Scratch (allocation-free: static device globals)
__device__ __half d_q[(size_t)BS*HH];
__device__ __half d_k[(size_t)BS*HH];
__device__ __half d_vt[(size_t)HH*BS];     // V transposed: [d][token]
__device__ __half d_x[(size_t)BS*HH];      // fp16 X
__device__ __half d_w[(size_t)3*HH*HH];    // fp16 W^T (per z: [n][k])
__device__ float  d_g[BS];
__device__ float  d_p[BS];
__device__ int    d_perm[BS];              // bucketed query order per batch

// ---------------------------------------------------------------------------
// helpers
// ---------------------------------------------------------------------------
__device__ __forceinline__ void cp16(uint32_t dst, const void* src){
    asm volatile("cp.async.cg.shared.global [%0], [%1], 16;" :: "r"(dst), "l"(src));
}
__device__ __forceinline__ void cp_commit(){ asm volatile("cp.async.commit_group;"); }
template<int N> __device__ __forceinline__ void cp_wait(){
    asm volatile("cp.async.wait_group %0;" :: "n"(N));
}
__device__ __forceinline__ void mma16(float* c, const uint32_t* a, const uint32_t* b){
    asm volatile("mma.sync.aligned.m16n8k16.row.col.f32.f16.f16.f32 "
        "{%0,%1,%2,%3}, {%4,%5,%6,%7}, {%8,%9}, {%0,%1,%2,%3};"
        : "+f"(c[0]),"+f"(c[1]),"+f"(c[2]),"+f"(c[3])
        : "r"(a[0]),"r"(a[1]),"r"(a[2]),"r"(a[3]), "r"(b[0]),"r"(b[1]));
}
__device__ __forceinline__ uint32_t packh2(float a, float b){
    __half2 h = __floats2half2_rn(a, b);
    return *reinterpret_cast<uint32_t*>(&h);
}

// ---------------------------------------------------------------------------
// W fp32 [k][n] -> fp16 W^T [n][k], tiled; z selects source. block (32,8)
// ---------------------------------------------------------------------------
__global__ __launch_bounds__(256) void tconv_kernel(const float* __restrict__ s0,
                                                    const float* __restrict__ s1,
                                                    const float* __restrict__ s2,
                                                    __half* __restrict__ dst){
    const int z = blockIdx.z;
    const float* W = (z == 0) ? s0 : (z == 1) ? s1 : s2;
    __shared__ float ts[32][33];
    const int n0 = blockIdx.x*32, k0 = blockIdx.y*32;
    const int tx = threadIdx.x, ty = threadIdx.y;
    #pragma unroll
    for (int yy = 0; yy < 4; yy++){
        int k = k0 + ty + yy*8;
        ts[ty + yy*8][tx] = W[(size_t)k*HH + n0 + tx];
    }
    __syncthreads();
    #pragma unroll
    for (int yy = 0; yy < 4; yy++){
        int n = n0 + ty + yy*8;
        dst[(size_t)z*HH*HH + (size_t)n*HH + k0 + tx] = __float2half_rn(ts[tx][ty + yy*8]);
    }
}

// ---------------------------------------------------------------------------
// Gate + X convert: g = sigmoid(X @ Wg + bg), p = (S-2)^(1-g),
// plus fp16 copy of X (fused — gate already touches every element).
// ---------------------------------------------------------------------------
__global__ __launch_bounds__(256) void gate_kernel(const float* __restrict__ X,
                                                   const float* __restrict__ Wg,
                                                   const float* __restrict__ bg,
                                                   float* __restrict__ g,
                                                   float* __restrict__ p,
                                                   __half* __restrict__ xh) {
    int row = blockIdx.x;
    int tid = threadIdx.x;
    float4 xv = *(const float4*)(X + (size_t)row*HH + tid*4);
    float4 wv = *(const float4*)(Wg + tid*4);
    // fused fp16 convert
    uint2 o = { packh2(xv.x, xv.y), packh2(xv.z, xv.w) };
    *(uint2*)(xh + (size_t)row*HH + tid*4) = o;

    float s = xv.x*wv.x + xv.y*wv.y + xv.z*wv.z + xv.w*wv.w;
    __shared__ float red[256];
    red[tid] = s; __syncthreads();
    for (int off = 128; off > 0; off >>= 1) {
        if (tid < off) red[tid] += red[tid+off];
        __syncthreads();
    }
    if (tid == 0) {
        float z = red[0] + bg[0];
        float gg = 1.f / (1.f + expf(-z));
        g[row] = gg;
        p[row] = powf((float)(SS-2), 1.f - gg);
    }
}

// ---------------------------------------------------------------------------
// Query ordering: stable counting sort into 4 pi-buckets per batch.
// ---------------------------------------------------------------------------
__global__ __launch_bounds__(256) void order_kernel(const float* __restrict__ p,
                                                    int* __restrict__ perm){
    const int b = blockIdx.x, tid = threadIdx.x;
    const float* pb = p + (size_t)b*SS;
    __shared__ uint8_t bk[SS];
    __shared__ int sc[1024];
    int myc[4] = {0,0,0,0};
    #pragma unroll
    for (int e = 0; e < 8; e++){
        int i = tid*8 + e;
        float pi = pb[i];
        int k = (pi < 96.f) ? 0 : (pi < 288.f) ? 1 : (pi < 800.f) ? 2 : 3;
        bk[i] = (uint8_t)k; myc[k]++;
    }
    #pragma unroll
    for (int k = 0; k < 4; k++) sc[k*256 + tid] = myc[k];
    __syncthreads();
    for (int off = 1; off < 1024; off <<= 1){
        int v[4];
        #pragma unroll
        for (int k = 0; k < 4; k++){
            int idx = k*256 + tid;
            v[k] = (idx >= off) ? sc[idx - off] : 0;
        }
        __syncthreads();
        #pragma unroll
        for (int k = 0; k < 4; k++) sc[k*256 + tid] += v[k];
        __syncthreads();
    }
    int base[4];
    #pragma unroll
    for (int k = 0; k < 4; k++) base[k] = sc[k*256 + tid] - myc[k];
    #pragma unroll
    for (int e = 0; e < 8; e++){
        int i = tid*8 + e;
        int k = bk[i];
        perm[(size_t)b*SS + base[k]++] = i;
    }
}

// ---------------------------------------------------------------------------
// Merged fp16 QKV projection. z selects (W^T slice, bias, output).
// z=0,1: C half [token][1024]. z=2: V^T half [d][token].
// ---------------------------------------------------------------------------
#define PSTR 40   // smem row stride in halves (32 + 8 pad)

__global__ __launch_bounds__(256, 2) void gemm_proj(
    const __half* __restrict__ A, const __half* __restrict__ Wall,
    const float* __restrict__ b0, const float* __restrict__ b1,
    const float* __restrict__ b2,
    __half* __restrict__ C0, __half* __restrict__ C1, __half* __restrict__ Vt)
{
    const int z = blockIdx.z;
    const __half* Bp = Wall + (size_t)z*HH*HH;
    const float* bias = (z == 0) ? b0 : (z == 1) ? b1 : b2;

    extern __shared__ __half smh[];
    __half* Asm[2] = { smh, smh + 128*PSTR };
    __half* Bsm[2] = { smh + 2*128*PSTR, smh + 3*128*PSTR };

    const int tid = threadIdx.x, lane = tid & 31, wid = tid >> 5;
    const int wm = wid >> 2, wn = wid & 3;
    const int gq = lane & 3, gr = lane >> 2;

    const int iBase = blockIdx.y * 128;
    const int jBase = blockIdx.x * 128;

    float acc[4][4][4] = {};

    auto loadA = [&](int s, int kk){
        uint32_t base = (uint32_t)__cvta_generic_to_shared(Asm[s]);
        #pragma unroll
        for (int i = 0; i < 2; i++){
            int f = tid + i*256;
            int r = f >> 2, c8 = (f & 3) * 8;
            cp16(base + (uint32_t)(r*PSTR + c8)*2u, A + (size_t)(iBase + r)*HH + kk + c8);
        }
    };
    auto loadB = [&](int s, int kk){
        uint32_t base = (uint32_t)__cvta_generic_to_shared(Bsm[s]);
        #pragma unroll
        for (int i = 0; i < 2; i++){
            int f = tid + i*256;
            int n = f >> 2, c8 = (f & 3) * 8;
            cp16(base + (uint32_t)(n*PSTR + c8)*2u, Bp + (size_t)(jBase + n)*HH + kk + c8);
        }
    };

    loadA(0, 0); loadB(0, 0); cp_commit();
    const int nK = HH / 32;
    for (int kt = 0; kt < nK; kt++){
        const int cur = kt & 1;
        if (kt + 1 < nK){
            loadA(cur ^ 1, (kt+1)*32); loadB(cur ^ 1, (kt+1)*32);
            cp_commit(); cp_wait<1>();
        } else {
            cp_wait<0>();
        }
        __syncthreads();
        const __half* As = Asm[cur];
        const __half* Bs = Bsm[cur];
        #pragma unroll
        for (int ks = 0; ks < 2; ks++){
            const int k0 = ks*16 + 2*gq;
            uint32_t af[4][4]; uint32_t bf[4][2];
            #pragma unroll
            for (int mt = 0; mt < 4; mt++){
                int r0 = wm*64 + mt*16 + gr;
                af[mt][0] = *(const uint32_t*)&As[r0*PSTR + k0];
                af[mt][1] = *(const uint32_t*)&As[(r0+8)*PSTR + k0];
                af[mt][2] = *(const uint32_t*)&As[r0*PSTR + k0 + 8];
                af[mt][3] = *(const uint32_t*)&As[(r0+8)*PSTR + k0 + 8];
            }
            #pragma unroll
            for (int nt = 0; nt < 4; nt++){
                int n = wn*32 + nt*8 + gr;
                bf[nt][0] = *(const uint32_t*)&Bs[n*PSTR + k0];
                bf[nt][1] = *(const uint32_t*)&Bs[n*PSTR + k0 + 8];
            }
            #pragma unroll
            for (int mt = 0; mt < 4; mt++)
                #pragma unroll
                for (int nt = 0; nt < 4; nt++)
                    mma16(acc[mt][nt], af[mt], bf[nt]);
        }
        __syncthreads();
    }

    // epilogue
    #pragma unroll
    for (int mt = 0; mt < 4; mt++){
        int r0 = iBase + wm*64 + mt*16 + gr;
        int r1 = r0 + 8;
        #pragma unroll
        for (int nt = 0; nt < 4; nt++){
            int c0 = jBase + wn*32 + nt*8 + 2*gq;
            float bb0 = __ldg(bias + c0), bb1 = __ldg(bias + c0 + 1);
            float v0 = acc[mt][nt][0] + bb0, v1 = acc[mt][nt][1] + bb1;
            float v2 = acc[mt][nt][2] + bb0, v3 = acc[mt][nt][3] + bb1;
            if (z == 2){
                Vt[(size_t)c0*BS + r0]     = __float2half_rn(v0);
                Vt[(size_t)(c0+1)*BS + r0] = __float2half_rn(v1);
                Vt[(size_t)c0*BS + r1]     = __float2half_rn(v2);
                Vt[(size_t)(c0+1)*BS + r1] = __float2half_rn(v3);
            } else {
                __half* C = (z == 0) ? C0 : C1;
                uint32_t p0 = packh2(v0, v1), p1 = packh2(v2, v3);
                *(uint32_t*)(C + (size_t)r0*HH + c0) = p0;
                *(uint32_t*)(C + (size_t)r1*HH + c0) = p1;
            }
        }
    }
}

// ---------------------------------------------------------------------------
// Fused fp16 flash attention: query reordering + CTA-band j-loop + per-warp skip.
// The j-loop covers only the CTA's union band (loads/barriers for tiles no
// warp will touch are eliminated); within it, per-warp active check as before.
// ---------------------------------------------------------------------------
#define QSTR 72   // halves
#define JT   64
#define NJT  (SS/JT)   // 32

__device__ __forceinline__ float penexp(float om, float gi, float pi, int i,
                                        float gj, int j, float se){
    float res = om * fmaxf(om - gj, 0.f) + gi * fminf(om + gj, 1.f);
    float scope = fminf(fmaxf(pi + 2.f - fabsf((float)(i - j)), 1e-32f), 1.f);
    float pen = fmaxf(res * scope, 1e-32f);
    return pen * __expf(se);
}

__global__ __launch_bounds__(256, 2) void attn_fused(
    const __half* __restrict__ Q, const __half* __restrict__ Kg,
    const __half* __restrict__ Vt, const float* __restrict__ g,
    const float* __restrict__ p, const int* __restrict__ perm,
    float* __restrict__ out)
{
    const int bh = blockIdx.y, b = bh >> 4, h = bh & 15;
    const int iBase = blockIdx.x * 128;
    const int tid = threadIdx.x, lane = tid & 31, wid = tid >> 5;

    extern __shared__ __half smh[];
    __half* Qs  = smh;                    // 128*72
    __half* Ks0 = Qs  + 128*QSTR;         // 2 x 64*72
    __half* Vs0 = Ks0 + 2*JT*QSTR;        // 2 x 64*72   ([d][j])
    float*  gs  = (float*)(Vs0 + 2*JT*QSTR);  // 2048 floats
    __shared__ int bandLo[8], bandHi[8];

    const __half* Qp = Q  + (size_t)b*SS*HH + h*HD;
    const __half* Kp = Kg + (size_t)b*SS*HH + h*HD;
    const int* pm = perm + (size_t)b*SS;

    // prologue: Q tile (gathered through perm) + g row   (group 0)
    {
        uint32_t qb = (uint32_t)__cvta_generic_to_shared(Qs);
        #pragma unroll
        for (int l = 0; l < 4; l++){
            int f = tid + l*256;
            int r = f >> 3, c8 = (f & 7) * 8;
            int pr = __ldg(pm + iBase + r);
            cp16(qb + (uint32_t)(r*QSTR + c8)*2u, Qp + (size_t)pr*HH + c8);
        }
        uint32_t gb = (uint32_t)__cvta_generic_to_shared(gs);
        #pragma unroll
        for (int l = 0; l < 2; l++){
            int f = tid + l*256;
            cp16(gb + (uint32_t)f*16u, g + (size_t)b*SS + f*4);
        }
        cp_commit();
    }
    auto loadK = [&](int s, int j0){
        uint32_t kb = (uint32_t)__cvta_generic_to_shared(Ks0 + s*JT*QSTR);
        #pragma unroll
        for (int l = 0; l < 2; l++){
            int f = tid + l*256;
            int r = f >> 3, c8 = (f & 7) * 8;
            cp16(kb + (uint32_t)(r*QSTR + c8)*2u, Kp + (size_t)(j0 + r)*HH + c8);
        }
    };
    auto loadV = [&](int s, int j0){
        uint32_t vb = (uint32_t)__cvta_generic_to_shared(Vs0 + s*JT*QSTR);
        #pragma unroll
        for (int l = 0; l < 2; l++){
            int f = tid + l*256;
            int d = f >> 3, c8 = (f & 7) * 8;   // d-row, token chunk
            cp16(vb + (uint32_t)(d*QSTR + c8)*2u,
                 Vt + (size_t)(h*HD + d)*BS + b*SS + j0 + c8);
        }
    };

    const int gq = lane & 3, gr = lane >> 2;
    const int lr0 = wid*16 + gr;
    const int lr1 = lr0 + 8;
    const int ri0 = __ldg(pm + iBase + lr0);
    const int ri1 = __ldg(pm + iBase + lr1);
    const float gi0 = __ldg(g + (size_t)b*SS + ri0);
    const float gi1 = __ldg(g + (size_t)b*SS + ri1);
    const float pi0 = __ldg(p + (size_t)b*SS + ri0);
    const float pi1 = __ldg(p + (size_t)b*SS + ri1);
    const float om0 = 1.f - gi0, om1 = 1.f - gi1;

    // per-warp band
    float wlo = fminf((float)ri0 - pi0, (float)ri1 - pi1);
    float whi = fmaxf((float)ri0 + pi0, (float)ri1 + pi1);
    #pragma unroll
    for (int off = 16; off > 0; off >>= 1){
        wlo = fminf(wlo, __shfl_xor_sync(0xffffffffu, wlo, off));
        whi = fmaxf(whi, __shfl_xor_sync(0xffffffffu, whi, off));
    }
    const int blo = (int)floorf(wlo) - 3;
    const int bhi = (int)ceilf(whi) + 3;

    // CTA band reduce
    if (lane == 0){ bandLo[wid] = blo; bandHi[wid] = bhi; }
    __syncthreads();
    int cLo = bandLo[0], cHi = bandHi[0];
    #pragma unroll
    for (int wI = 1; wI < 8; wI++){
        cLo = min(cLo, bandLo[wI]); cHi = max(cHi, bandHi[wI]);
    }
    const int jtLo = (cLo <= 0) ? 0 : min(NJT-1, cLo / JT);
    const int jtHi = min(NJT-1, max(0, cHi) / JT);

    loadK(0, jtLo*JT); loadV(0, jtLo*JT); cp_commit();   // group 1

    float m0 = -1e30f, m1 = -1e30f, l0 = 0.f, l1 = 0.f;
    float oacc[8][4] = {};

    for (int jt = jtLo; jt <= jtHi; jt++){
        const int cur = (jt - jtLo) & 1;
        if (jt + 1 <= jtHi){
            loadK(cur ^ 1, (jt+1)*JT); loadV(cur ^ 1, (jt+1)*JT);
            cp_commit(); cp_wait<1>();
        } else {
            cp_wait<0>();
        }
        __syncthreads();
        const int jBase = jt*JT;
        const bool active = (jBase + JT - 1 >= blo) && (jBase <= bhi);
        if (active){
            const __half* Ks = Ks0 + cur*JT*QSTR;
            const __half* Vs = Vs0 + cur*JT*QSTR;

            // --- S = Q K^T ---
            float sacc[8][4];
            #pragma unroll
            for (int nt = 0; nt < 8; nt++){
                sacc[nt][0]=0.f; sacc[nt][1]=0.f; sacc[nt][2]=0.f; sacc[nt][3]=0.f;
            }
            #pragma unroll
            for (int ks = 0; ks < 4; ks++){
                const int k0 = ks*16 + 2*gq;
                uint32_t af[4];
                af[0] = *(const uint32_t*)&Qs[lr0*QSTR + k0];
                af[1] = *(const uint32_t*)&Qs[lr1*QSTR + k0];
                af[2] = *(const uint32_t*)&Qs[lr0*QSTR + k0 + 8];
                af[3] = *(const uint32_t*)&Qs[lr1*QSTR + k0 + 8];
                #pragma unroll
                for (int nt = 0; nt < 8; nt++){
                    const int n = nt*8 + gr;
                    uint32_t bf[2];
                    bf[0] = *(const uint32_t*)&Ks[n*QSTR + k0];
                    bf[1] = *(const uint32_t*)&Ks[n*QSTR + k0 + 8];
                    mma16(sacc[nt], af, bf);
                }
            }

            // --- online softmax ---
            float tm0 = -1e30f, tm1 = -1e30f;
            #pragma unroll
            for (int nt = 0; nt < 8; nt++){
                tm0 = fmaxf(tm0, fmaxf(sacc[nt][0], sacc[nt][1]));
                tm1 = fmaxf(tm1, fmaxf(sacc[nt][2], sacc[nt][3]));
            }
            tm0 = fmaxf(tm0, __shfl_xor_sync(0xffffffffu, tm0, 1));
            tm0 = fmaxf(tm0, __shfl_xor_sync(0xffffffffu, tm0, 2));
            tm1 = fmaxf(tm1, __shfl_xor_sync(0xffffffffu, tm1, 1));
            tm1 = fmaxf(tm1, __shfl_xor_sync(0xffffffffu, tm1, 2));
            tm0 *= 0.125f; tm1 *= 0.125f;
            const float m0n = fmaxf(m0, tm0), m1n = fmaxf(m1, tm1);
            const float f0 = __expf(m0 - m0n), f1 = __expf(m1 - m1n);
            m0 = m0n; m1 = m1n;
            l0 *= f0; l1 *= f1;
            #pragma unroll
            for (int dn = 0; dn < 8; dn++){
                oacc[dn][0] *= f0; oacc[dn][1] *= f0;
                oacc[dn][2] *= f1; oacc[dn][3] *= f1;
            }
            float rs0 = 0.f, rs1 = 0.f;
            #pragma unroll
            for (int nt = 0; nt < 8; nt++){
                const int j0 = jBase + nt*8 + 2*gq;
                const int j1 = j0 + 1;
                const float gj0 = gs[j0], gj1 = gs[j1];
                float t00 = penexp(om0, gi0, pi0, ri0, gj0, j0, sacc[nt][0]*0.125f - m0);
                float t01 = penexp(om0, gi0, pi0, ri0, gj1, j1, sacc[nt][1]*0.125f - m0);
                float t10 = penexp(om1, gi1, pi1, ri1, gj0, j0, sacc[nt][2]*0.125f - m1);
                float t11 = penexp(om1, gi1, pi1, ri1, gj1, j1, sacc[nt][3]*0.125f - m1);
                sacc[nt][0] = t00; sacc[nt][1] = t01;
                sacc[nt][2] = t10; sacc[nt][3] = t11;
                rs0 += t00 + t01; rs1 += t10 + t11;
            }
            rs0 += __shfl_xor_sync(0xffffffffu, rs0, 1);
            rs0 += __shfl_xor_sync(0xffffffffu, rs0, 2);
            rs1 += __shfl_xor_sync(0xffffffffu, rs1, 1);
            rs1 += __shfl_xor_sync(0xffffffffu, rs1, 2);
            l0 += rs0; l1 += rs1;

            // --- O += P V : C-frag pairs map directly onto fp16 A-frags ---
            #pragma unroll
            for (int kc = 0; kc < 4; kc++){
                uint32_t af[4];
                af[0] = packh2(sacc[2*kc][0],   sacc[2*kc][1]);
                af[1] = packh2(sacc[2*kc][2],   sacc[2*kc][3]);
                af[2] = packh2(sacc[2*kc+1][0], sacc[2*kc+1][1]);
                af[3] = packh2(sacc[2*kc+1][2], sacc[2*kc+1][3]);
                const int kb = kc*16 + 2*gq;
                #pragma unroll
                for (int dn = 0; dn < 8; dn++){
                    const int d0 = dn*8 + gr;
                    uint32_t bf[2];
                    bf[0] = *(const uint32_t*)&Vs[d0*QSTR + kb];
                    bf[1] = *(const uint32_t*)&Vs[d0*QSTR + kb + 8];
                    mma16(oacc[dn], af, bf);
                }
            }
        }
        __syncthreads();
    }

    // epilogue: scatter to original rows (fp32 output)
    const float inv0 = 1.f / l0, inv1 = 1.f / l1;
    float* op = out + (size_t)b*SS*HH + h*HD;
    #pragma unroll
    for (int dn = 0; dn < 8; dn++){
        const int c0 = dn*8 + 2*gq;
        float2 o0 = { oacc[dn][0]*inv0, oacc[dn][1]*inv0 };
        float2 o1 = { oacc[dn][2]*inv1, oacc[dn][3]*inv1 };
        *(float2*)(op + (size_t)ri0*HH + c0) = o0;
        *(float2*)(op + (size_t)ri1*HH + c0) = o1;
    }
}

// ---------------------------------------------------------------------------
extern "C" void kernel_launch(void* const* d_in, const int* in_sizes, int n_in,
                              void* d_out, int out_size) {
    const float* X  = (const float*)d_in[0];
    const float* Wq = (const float*)d_in[1];
    const float* bq = (const float*)d_in[2];
    const float* Wk = (const float*)d_in[3];
    const float* bk = (const float*)d_in[4];
    const float* Wv = (const float*)d_in[5];
    const float* bv = (const float*)d_in[6];
    const float* Wg = (const float*)d_in[7];
    const float* bg = (const float*)d_in[8];
    float* out = (float*)d_out;

    __half *q, *k, *vt, *x, *w;
    float *g, *p;
    int *perm;
    cudaGetSymbolAddress((void**)&q,  d_q);
    cudaGetSymbolAddress((void**)&k,  d_k);
    cudaGetSymbolAddress((void**)&vt, d_vt);
    cudaGetSymbolAddress((void**)&x,  d_x);
    cudaGetSymbolAddress((void**)&w,  d_w);
    cudaGetSymbolAddress((void**)&g,  d_g);
    cudaGetSymbolAddress((void**)&p,  d_p);
    cudaGetSymbolAddress((void**)&perm, d_perm);

    constexpr int SM_PROJ = 4*128*PSTR*2;                                    // 40960
    constexpr int SM_ATTN = (128*QSTR + 2*JT*QSTR + 2*JT*QSTR)*2 + SS*4;     // 63488
    cudaFuncSetAttribute(gemm_proj,
                         cudaFuncAttributeMaxDynamicSharedMemorySize, SM_PROJ);
    cudaFuncSetAttribute(attn_fused,
                         cudaFuncAttributeMaxDynamicSharedMemorySize, SM_ATTN);

    // prep: W transpose-convert + gate(+X convert) + ordering
    dim3 gt(HH/32, HH/32, 3);
    tconv_kernel<<<gt, dim3(32,8)>>>(Wq, Wk, Wv, w);
    gate_kernel<<<BS, 256>>>(X, Wg, bg, g, p, x);
    order_kernel<<<BB, 256>>>(p, perm);

    // merged QKV projection
    dim3 gp(HH/128, BS/128, 3);   // (8, 32, 3)
    gemm_proj<<<gp, 256, SM_PROJ>>>(x, w, bq, bk, bv, q, k, vt);

    dim3 ga(SS/128, BH);   // (16, 32)
    attn_fused<<<ga, 256, SM_ATTN>>>(q, k, vt, g, p, perm, out);
}

// round 10
// speedup vs baseline: 9.4674x; 1.1442x over previous
#include <cuda_runtime.h>
#include <cuda_fp16.h>
#include <math.h>
#include <stdint.h>

#define BB 2
#define SS 2048
#define HH 1024
#define NH 16
#define HD 64
#define BS (BB*SS)   // 4096
#define BH (BB*NH)   // 32

// Scratch (allocation-free: static device globals)
__device__ __half d_q[(size_t)BS*HH];
__device__ __half d_k[(size_t)BS*HH];
__device__ __half d_vt[(size_t)HH*BS];     // V transposed: [d][token]
__device__ __half d_x[(size_t)BS*HH];      // fp16 X
__device__ __half d_w[(size_t)3*HH*HH];    // fp16 W^T (per z: [n][k])
__device__ float  d_g[BS];
__device__ float  d_p[BS];
__device__ int    d_perm[BS];              // bucketed query order per batch

// ---------------------------------------------------------------------------
// helpers
// ---------------------------------------------------------------------------
__device__ __forceinline__ void cp16(uint32_t dst, const void* src){
    asm volatile("cp.async.cg.shared.global [%0], [%1], 16;" :: "r"(dst), "l"(src));
}
__device__ __forceinline__ void cp_commit(){ asm volatile("cp.async.commit_group;"); }
template<int N> __device__ __forceinline__ void cp_wait(){
    asm volatile("cp.async.wait_group %0;" :: "n"(N));
}
__device__ __forceinline__ void mma16(float* c, const uint32_t* a, const uint32_t* b){
    asm volatile("mma.sync.aligned.m16n8k16.row.col.f32.f16.f16.f32 "
        "{%0,%1,%2,%3}, {%4,%5,%6,%7}, {%8,%9}, {%0,%1,%2,%3};"
        : "+f"(c[0]),"+f"(c[1]),"+f"(c[2]),"+f"(c[3])
        : "r"(a[0]),"r"(a[1]),"r"(a[2]),"r"(a[3]), "r"(b[0]),"r"(b[1]));
}
__device__ __forceinline__ void ldsm4(uint32_t* d, uint32_t addr){
    asm volatile("ldmatrix.sync.aligned.m8n8.x4.shared.b16 {%0,%1,%2,%3}, [%4];"
        : "=r"(d[0]),"=r"(d[1]),"=r"(d[2]),"=r"(d[3]) : "r"(addr));
}
__device__ __forceinline__ uint32_t packh2(float a, float b){
    __half2 h = __floats2half2_rn(a, b);
    return *reinterpret_cast<uint32_t*>(&h);
}

// ---------------------------------------------------------------------------
// W fp32 [k][n] -> fp16 W^T [n][k], tiled; z selects source. block (32,8)
// ---------------------------------------------------------------------------
__global__ __launch_bounds__(256) void tconv_kernel(const float* __restrict__ s0,
                                                    const float* __restrict__ s1,
                                                    const float* __restrict__ s2,
                                                    __half* __restrict__ dst){
    const int z = blockIdx.z;
    const float* W = (z == 0) ? s0 : (z == 1) ? s1 : s2;
    __shared__ float ts[32][33];
    const int n0 = blockIdx.x*32, k0 = blockIdx.y*32;
    const int tx = threadIdx.x, ty = threadIdx.y;
    #pragma unroll
    for (int yy = 0; yy < 4; yy++){
        int k = k0 + ty + yy*8;
        ts[ty + yy*8][tx] = W[(size_t)k*HH + n0 + tx];
    }
    __syncthreads();
    #pragma unroll
    for (int yy = 0; yy < 4; yy++){
        int n = n0 + ty + yy*8;
        dst[(size_t)z*HH*HH + (size_t)n*HH + k0 + tx] = __float2half_rn(ts[tx][ty + yy*8]);
    }
}

// ---------------------------------------------------------------------------
// Gate + X convert: g = sigmoid(X @ Wg + bg), p = (S-2)^(1-g),
// plus fp16 copy of X (fused — gate already touches every element).
// ---------------------------------------------------------------------------
__global__ __launch_bounds__(256) void gate_kernel(const float* __restrict__ X,
                                                   const float* __restrict__ Wg,
                                                   const float* __restrict__ bg,
                                                   float* __restrict__ g,
                                                   float* __restrict__ p,
                                                   __half* __restrict__ xh) {
    int row = blockIdx.x;
    int tid = threadIdx.x;
    float4 xv = *(const float4*)(X + (size_t)row*HH + tid*4);
    float4 wv = *(const float4*)(Wg + tid*4);
    uint2 o = { packh2(xv.x, xv.y), packh2(xv.z, xv.w) };
    *(uint2*)(xh + (size_t)row*HH + tid*4) = o;

    float s = xv.x*wv.x + xv.y*wv.y + xv.z*wv.z + xv.w*wv.w;
    __shared__ float red[256];
    red[tid] = s; __syncthreads();
    for (int off = 128; off > 0; off >>= 1) {
        if (tid < off) red[tid] += red[tid+off];
        __syncthreads();
    }
    if (tid == 0) {
        float z = red[0] + bg[0];
        float gg = 1.f / (1.f + expf(-z));
        g[row] = gg;
        p[row] = powf((float)(SS-2), 1.f - gg);
    }
}

// ---------------------------------------------------------------------------
// Query ordering: stable counting sort into 4 pi-buckets per batch.
// ---------------------------------------------------------------------------
__global__ __launch_bounds__(256) void order_kernel(const float* __restrict__ p,
                                                    int* __restrict__ perm){
    const int b = blockIdx.x, tid = threadIdx.x;
    const float* pb = p + (size_t)b*SS;
    __shared__ uint8_t bk[SS];
    __shared__ int sc[1024];
    int myc[4] = {0,0,0,0};
    #pragma unroll
    for (int e = 0; e < 8; e++){
        int i = tid*8 + e;
        float pi = pb[i];
        int k = (pi < 96.f) ? 0 : (pi < 288.f) ? 1 : (pi < 800.f) ? 2 : 3;
        bk[i] = (uint8_t)k; myc[k]++;
    }
    #pragma unroll
    for (int k = 0; k < 4; k++) sc[k*256 + tid] = myc[k];
    __syncthreads();
    for (int off = 1; off < 1024; off <<= 1){
        int v[4];
        #pragma unroll
        for (int k = 0; k < 4; k++){
            int idx = k*256 + tid;
            v[k] = (idx >= off) ? sc[idx - off] : 0;
        }
        __syncthreads();
        #pragma unroll
        for (int k = 0; k < 4; k++) sc[k*256 + tid] += v[k];
        __syncthreads();
    }
    int base[4];
    #pragma unroll
    for (int k = 0; k < 4; k++) base[k] = sc[k*256 + tid] - myc[k];
    #pragma unroll
    for (int e = 0; e < 8; e++){
        int i = tid*8 + e;
        int k = bk[i];
        perm[(size_t)b*SS + base[k]++] = i;
    }
}

// ---------------------------------------------------------------------------
// Merged fp16 QKV projection with ldmatrix fragment loads, BK=64.
// z selects (W^T slice, bias, output). z=0,1: C [token][1024]; z=2: V^T.
// ---------------------------------------------------------------------------
#define PSTR 72   // smem row stride in halves (64 + 8 pad)

__global__ __launch_bounds__(256, 2) void gemm_proj(
    const __half* __restrict__ A, const __half* __restrict__ Wall,
    const float* __restrict__ b0, const float* __restrict__ b1,
    const float* __restrict__ b2,
    __half* __restrict__ C0, __half* __restrict__ C1, __half* __restrict__ Vt)
{
    const int z = blockIdx.z;
    const __half* Bp = Wall + (size_t)z*HH*HH;
    const float* bias = (z == 0) ? b0 : (z == 1) ? b1 : b2;

    extern __shared__ __half smh[];
    __half* Asm[2] = { smh, smh + 128*PSTR };
    __half* Bsm[2] = { smh + 2*128*PSTR, smh + 3*128*PSTR };

    const int tid = threadIdx.x, lane = tid & 31, wid = tid >> 5;
    const int wm = wid >> 2, wn = wid & 3;
    const int gq = lane & 3, gr = lane >> 2;

    const int iBase = blockIdx.y * 128;
    const int jBase = blockIdx.x * 128;

    float acc[4][4][4] = {};

    auto loadA = [&](int s, int kk){
        uint32_t base = (uint32_t)__cvta_generic_to_shared(Asm[s]);
        #pragma unroll
        for (int i = 0; i < 4; i++){
            int f = tid + i*256;
            int r = f >> 3, c8 = (f & 7) * 8;
            cp16(base + (uint32_t)(r*PSTR + c8)*2u, A + (size_t)(iBase + r)*HH + kk + c8);
        }
    };
    auto loadB = [&](int s, int kk){
        uint32_t base = (uint32_t)__cvta_generic_to_shared(Bsm[s]);
        #pragma unroll
        for (int i = 0; i < 4; i++){
            int f = tid + i*256;
            int n = f >> 3, c8 = (f & 7) * 8;
            cp16(base + (uint32_t)(n*PSTR + c8)*2u, Bp + (size_t)(jBase + n)*HH + kk + c8);
        }
    };

    // ldmatrix lane addressing
    const int arow = lane & 15;               // A: row within 16-row tile
    const int acol = (lane >> 4) * 8;         // A: 0/8 within 16-k chunk
    const int brow = lane & 7;                // B: row within 8-n tile
    const int bcol = (lane >> 3) * 8;         // B: 0/8/16/24 within 32-k span

    loadA(0, 0); loadB(0, 0); cp_commit();
    const int nK = HH / 64;   // 16
    for (int kt = 0; kt < nK; kt++){
        const int cur = kt & 1;
        if (kt + 1 < nK){
            loadA(cur ^ 1, (kt+1)*64); loadB(cur ^ 1, (kt+1)*64);
            cp_commit(); cp_wait<1>();
        } else {
            cp_wait<0>();
        }
        __syncthreads();
        uint32_t abase = (uint32_t)__cvta_generic_to_shared(Asm[cur]);
        uint32_t bbase = (uint32_t)__cvta_generic_to_shared(Bsm[cur]);
        #pragma unroll
        for (int kp = 0; kp < 2; kp++){       // 32-k spans
            uint32_t bfp[4][4];
            #pragma unroll
            for (int nt = 0; nt < 4; nt++){
                uint32_t addr = bbase +
                    (uint32_t)((wn*32 + nt*8 + brow)*PSTR + kp*32 + bcol)*2u;
                ldsm4(bfp[nt], addr);
            }
            #pragma unroll
            for (int k2 = 0; k2 < 2; k2++){   // 16-k chunks within span
                uint32_t af[4][4];
                #pragma unroll
                for (int mt = 0; mt < 4; mt++){
                    uint32_t addr = abase +
                        (uint32_t)((wm*64 + mt*16 + arow)*PSTR + kp*32 + k2*16 + acol)*2u;
                    ldsm4(af[mt], addr);
                }
                #pragma unroll
                for (int mt = 0; mt < 4; mt++)
                    #pragma unroll
                    for (int nt = 0; nt < 4; nt++)
                        mma16(acc[mt][nt], af[mt], &bfp[nt][2*k2]);
            }
        }
        __syncthreads();
    }

    // epilogue
    #pragma unroll
    for (int mt = 0; mt < 4; mt++){
        int r0 = iBase + wm*64 + mt*16 + gr;
        int r1 = r0 + 8;
        #pragma unroll
        for (int nt = 0; nt < 4; nt++){
            int c0 = jBase + wn*32 + nt*8 + 2*gq;
            float bb0 = __ldg(bias + c0), bb1 = __ldg(bias + c0 + 1);
            float v0 = acc[mt][nt][0] + bb0, v1 = acc[mt][nt][1] + bb1;
            float v2 = acc[mt][nt][2] + bb0, v3 = acc[mt][nt][3] + bb1;
            if (z == 2){
                Vt[(size_t)c0*BS + r0]     = __float2half_rn(v0);
                Vt[(size_t)(c0+1)*BS + r0] = __float2half_rn(v1);
                Vt[(size_t)c0*BS + r1]     = __float2half_rn(v2);
                Vt[(size_t)(c0+1)*BS + r1] = __float2half_rn(v3);
            } else {
                __half* C = (z == 0) ? C0 : C1;
                uint32_t p0 = packh2(v0, v1), p1 = packh2(v2, v3);
                *(uint32_t*)(C + (size_t)r0*HH + c0) = p0;
                *(uint32_t*)(C + (size_t)r1*HH + c0) = p1;
            }
        }
    }
}

// ---------------------------------------------------------------------------
// Fused fp16 flash attention: query reordering + CTA-band j-loop + per-warp skip.
// ---------------------------------------------------------------------------
#define QSTR 72   // halves
#define JT   64
#define NJT  (SS/JT)   // 32

__device__ __forceinline__ float penexp(float om, float gi, float pi, int i,
                                        float gj, int j, float se){
    float res = om * fmaxf(om - gj, 0.f) + gi * fminf(om + gj, 1.f);
    float scope = fminf(fmaxf(pi + 2.f - fabsf((float)(i - j)), 1e-32f), 1.f);
    float pen = fmaxf(res * scope, 1e-32f);
    return pen * __expf(se);
}

__global__ __launch_bounds__(256, 2) void attn_fused(
    const __half* __restrict__ Q, const __half* __restrict__ Kg,
    const __half* __restrict__ Vt, const float* __restrict__ g,
    const float* __restrict__ p, const int* __restrict__ perm,
    float* __restrict__ out)
{
    const int bh = blockIdx.y, b = bh >> 4, h = bh & 15;
    const int iBase = blockIdx.x * 128;
    const int tid = threadIdx.x, lane = tid & 31, wid = tid >> 5;

    extern __shared__ __half smh[];
    __half* Qs  = smh;                    // 128*72
    __half* Ks0 = Qs  + 128*QSTR;         // 2 x 64*72
    __half* Vs0 = Ks0 + 2*JT*QSTR;        // 2 x 64*72   ([d][j])
    float*  gs  = (float*)(Vs0 + 2*JT*QSTR);  // 2048 floats
    __shared__ int bandLo[8], bandHi[8];

    const __half* Qp = Q  + (size_t)b*SS*HH + h*HD;
    const __half* Kp = Kg + (size_t)b*SS*HH + h*HD;
    const int* pm = perm + (size_t)b*SS;

    // prologue: Q tile (gathered through perm) + g row   (group 0)
    {
        uint32_t qb = (uint32_t)__cvta_generic_to_shared(Qs);
        #pragma unroll
        for (int l = 0; l < 4; l++){
            int f = tid + l*256;
            int r = f >> 3, c8 = (f & 7) * 8;
            int pr = __ldg(pm + iBase + r);
            cp16(qb + (uint32_t)(r*QSTR + c8)*2u, Qp + (size_t)pr*HH + c8);
        }
        uint32_t gb = (uint32_t)__cvta_generic_to_shared(gs);
        #pragma unroll
        for (int l = 0; l < 2; l++){
            int f = tid + l*256;
            cp16(gb + (uint32_t)f*16u, g + (size_t)b*SS + f*4);
        }
        cp_commit();
    }
    auto loadK = [&](int s, int j0){
        uint32_t kb = (uint32_t)__cvta_generic_to_shared(Ks0 + s*JT*QSTR);
        #pragma unroll
        for (int l = 0; l < 2; l++){
            int f = tid + l*256;
            int r = f >> 3, c8 = (f & 7) * 8;
            cp16(kb + (uint32_t)(r*QSTR + c8)*2u, Kp + (size_t)(j0 + r)*HH + c8);
        }
    };
    auto loadV = [&](int s, int j0){
        uint32_t vb = (uint32_t)__cvta_generic_to_shared(Vs0 + s*JT*QSTR);
        #pragma unroll
        for (int l = 0; l < 2; l++){
            int f = tid + l*256;
            int d = f >> 3, c8 = (f & 7) * 8;
            cp16(vb + (uint32_t)(d*QSTR + c8)*2u,
                 Vt + (size_t)(h*HD + d)*BS + b*SS + j0 + c8);
        }
    };

    const int gq = lane & 3, gr = lane >> 2;
    const int lr0 = wid*16 + gr;
    const int lr1 = lr0 + 8;
    const int ri0 = __ldg(pm + iBase + lr0);
    const int ri1 = __ldg(pm + iBase + lr1);
    const float gi0 = __ldg(g + (size_t)b*SS + ri0);
    const float gi1 = __ldg(g + (size_t)b*SS + ri1);
    const float pi0 = __ldg(p + (size_t)b*SS + ri0);
    const float pi1 = __ldg(p + (size_t)b*SS + ri1);
    const float om0 = 1.f - gi0, om1 = 1.f - gi1;

    // per-warp band
    float wlo = fminf((float)ri0 - pi0, (float)ri1 - pi1);
    float whi = fmaxf((float)ri0 + pi0, (float)ri1 + pi1);
    #pragma unroll
    for (int off = 16; off > 0; off >>= 1){
        wlo = fminf(wlo, __shfl_xor_sync(0xffffffffu, wlo, off));
        whi = fmaxf(whi, __shfl_xor_sync(0xffffffffu, whi, off));
    }
    const int blo = (int)floorf(wlo) - 3;
    const int bhi = (int)ceilf(whi) + 3;

    // CTA band reduce
    if (lane == 0){ bandLo[wid] = blo; bandHi[wid] = bhi; }
    __syncthreads();
    int cLo = bandLo[0], cHi = bandHi[0];
    #pragma unroll
    for (int wI = 1; wI < 8; wI++){
        cLo = min(cLo, bandLo[wI]); cHi = max(cHi, bandHi[wI]);
    }
    const int jtLo = (cLo <= 0) ? 0 : min(NJT-1, cLo / JT);
    const int jtHi = min(NJT-1, max(0, cHi) / JT);

    loadK(0, jtLo*JT); loadV(0, jtLo*JT); cp_commit();   // group 1

    float m0 = -1e30f, m1 = -1e30f, l0 = 0.f, l1 = 0.f;
    float oacc[8][4] = {};

    for (int jt = jtLo; jt <= jtHi; jt++){
        const int cur = (jt - jtLo) & 1;
        if (jt + 1 <= jtHi){
            loadK(cur ^ 1, (jt+1)*JT); loadV(cur ^ 1, (jt+1)*JT);
            cp_commit(); cp_wait<1>();
        } else {
            cp_wait<0>();
        }
        __syncthreads();
        const int jBase = jt*JT;
        const bool active = (jBase + JT - 1 >= blo) && (jBase <= bhi);
        if (active){
            const __half* Ks = Ks0 + cur*JT*QSTR;
            const __half* Vs = Vs0 + cur*JT*QSTR;

            // --- S = Q K^T ---
            float sacc[8][4];
            #pragma unroll
            for (int nt = 0; nt < 8; nt++){
                sacc[nt][0]=0.f; sacc[nt][1]=0.f; sacc[nt][2]=0.f; sacc[nt][3]=0.f;
            }
            #pragma unroll
            for (int ks = 0; ks < 4; ks++){
                const int k0 = ks*16 + 2*gq;
                uint32_t af[4];
                af[0] = *(const uint32_t*)&Qs[lr0*QSTR + k0];
                af[1] = *(const uint32_t*)&Qs[lr1*QSTR + k0];
                af[2] = *(const uint32_t*)&Qs[lr0*QSTR + k0 + 8];
                af[3] = *(const uint32_t*)&Qs[lr1*QSTR + k0 + 8];
                #pragma unroll
                for (int nt = 0; nt < 8; nt++){
                    const int n = nt*8 + gr;
                    uint32_t bf[2];
                    bf[0] = *(const uint32_t*)&Ks[n*QSTR + k0];
                    bf[1] = *(const uint32_t*)&Ks[n*QSTR + k0 + 8];
                    mma16(sacc[nt], af, bf);
                }
            }

            // --- online softmax ---
            float tm0 = -1e30f, tm1 = -1e30f;
            #pragma unroll
            for (int nt = 0; nt < 8; nt++){
                tm0 = fmaxf(tm0, fmaxf(sacc[nt][0], sacc[nt][1]));
                tm1 = fmaxf(tm1, fmaxf(sacc[nt][2], sacc[nt][3]));
            }
            tm0 = fmaxf(tm0, __shfl_xor_sync(0xffffffffu, tm0, 1));
            tm0 = fmaxf(tm0, __shfl_xor_sync(0xffffffffu, tm0, 2));
            tm1 = fmaxf(tm1, __shfl_xor_sync(0xffffffffu, tm1, 1));
            tm1 = fmaxf(tm1, __shfl_xor_sync(0xffffffffu, tm1, 2));
            tm0 *= 0.125f; tm1 *= 0.125f;
            const float m0n = fmaxf(m0, tm0), m1n = fmaxf(m1, tm1);
            const float f0 = __expf(m0 - m0n), f1 = __expf(m1 - m1n);
            m0 = m0n; m1 = m1n;
            l0 *= f0; l1 *= f1;
            #pragma unroll
            for (int dn = 0; dn < 8; dn++){
                oacc[dn][0] *= f0; oacc[dn][1] *= f0;
                oacc[dn][2] *= f1; oacc[dn][3] *= f1;
            }
            float rs0 = 0.f, rs1 = 0.f;
            #pragma unroll
            for (int nt = 0; nt < 8; nt++){
                const int j0 = jBase + nt*8 + 2*gq;
                const int j1 = j0 + 1;
                const float gj0 = gs[j0], gj1 = gs[j1];
                float t00 = penexp(om0, gi0, pi0, ri0, gj0, j0, sacc[nt][0]*0.125f - m0);
                float t01 = penexp(om0, gi0, pi0, ri0, gj1, j1, sacc[nt][1]*0.125f - m0);
                float t10 = penexp(om1, gi1, pi1, ri1, gj0, j0, sacc[nt][2]*0.125f - m1);
                float t11 = penexp(om1, gi1, pi1, ri1, gj1, j1, sacc[nt][3]*0.125f - m1);
                sacc[nt][0] = t00; sacc[nt][1] = t01;
                sacc[nt][2] = t10; sacc[nt][3] = t11;
                rs0 += t00 + t01; rs1 += t10 + t11;
            }
            rs0 += __shfl_xor_sync(0xffffffffu, rs0, 1);
            rs0 += __shfl_xor_sync(0xffffffffu, rs0, 2);
            rs1 += __shfl_xor_sync(0xffffffffu, rs1, 1);
            rs1 += __shfl_xor_sync(0xffffffffu, rs1, 2);
            l0 += rs0; l1 += rs1;

            // --- O += P V : C-frag pairs map directly onto fp16 A-frags ---
            #pragma unroll
            for (int kc = 0; kc < 4; kc++){
                uint32_t af[4];
                af[0] = packh2(sacc[2*kc][0],   sacc[2*kc][1]);
                af[1] = packh2(sacc[2*kc][2],   sacc[2*kc][3]);
                af[2] = packh2(sacc[2*kc+1][0], sacc[2*kc+1][1]);
                af[3] = packh2(sacc[2*kc+1][2], sacc[2*kc+1][3]);
                const int kb = kc*16 + 2*gq;
                #pragma unroll
                for (int dn = 0; dn < 8; dn++){
                    const int d0 = dn*8 + gr;
                    uint32_t bf[2];
                    bf[0] = *(const uint32_t*)&Vs[d0*QSTR + kb];
                    bf[1] = *(const uint32_t*)&Vs[d0*QSTR + kb + 8];
                    mma16(oacc[dn], af, bf);
                }
            }
        }
        __syncthreads();
    }

    // epilogue: scatter to original rows (fp32 output)
    const float inv0 = 1.f / l0, inv1 = 1.f / l1;
    float* op = out + (size_t)b*SS*HH + h*HD;
    #pragma unroll
    for (int dn = 0; dn < 8; dn++){
        const int c0 = dn*8 + 2*gq;
        float2 o0 = { oacc[dn][0]*inv0, oacc[dn][1]*inv0 };
        float2 o1 = { oacc[dn][2]*inv1, oacc[dn][3]*inv1 };
        *(float2*)(op + (size_t)ri0*HH + c0) = o0;
        *(float2*)(op + (size_t)ri1*HH + c0) = o1;
    }
}

// ---------------------------------------------------------------------------
extern "C" void kernel_launch(void* const* d_in, const int* in_sizes, int n_in,
                              void* d_out, int out_size) {
    const float* X  = (const float*)d_in[0];
    const float* Wq = (const float*)d_in[1];
    const float* bq = (const float*)d_in[2];
    const float* Wk = (const float*)d_in[3];
    const float* bk = (const float*)d_in[4];
    const float* Wv = (const float*)d_in[5];
    const float* bv = (const float*)d_in[6];
    const float* Wg = (const float*)d_in[7];
    const float* bg = (const float*)d_in[8];
    float* out = (float*)d_out;

    __half *q, *k, *vt, *x, *w;
    float *g, *p;
    int *perm;
    cudaGetSymbolAddress((void**)&q,  d_q);
    cudaGetSymbolAddress((void**)&k,  d_k);
    cudaGetSymbolAddress((void**)&vt, d_vt);
    cudaGetSymbolAddress((void**)&x,  d_x);
    cudaGetSymbolAddress((void**)&w,  d_w);
    cudaGetSymbolAddress((void**)&g,  d_g);
    cudaGetSymbolAddress((void**)&p,  d_p);
    cudaGetSymbolAddress((void**)&perm, d_perm);

    constexpr int SM_PROJ = 4*128*PSTR*2;                                    // 73728
    constexpr int SM_ATTN = (128*QSTR + 2*JT*QSTR + 2*JT*QSTR)*2 + SS*4;     // 63488
    cudaFuncSetAttribute(gemm_proj,
                         cudaFuncAttributeMaxDynamicSharedMemorySize, SM_PROJ);
    cudaFuncSetAttribute(attn_fused,
                         cudaFuncAttributeMaxDynamicSharedMemorySize, SM_ATTN);

    // prep: W transpose-convert + gate(+X convert) + ordering
    dim3 gt(HH/32, HH/32, 3);
    tconv_kernel<<<gt, dim3(32,8)>>>(Wq, Wk, Wv, w);
    gate_kernel<<<BS, 256>>>(X, Wg, bg, g, p, x);
    order_kernel<<<BB, 256>>>(p, perm);

    // merged QKV projection
    dim3 gp(HH/128, BS/128, 3);   // (8, 32, 3)
    gemm_proj<<<gp, 256, SM_PROJ>>>(x, w, bq, bk, bv, q, k, vt);

    dim3 ga(SS/128, BH);   // (16, 32)
    attn_fused<<<ga, 256, SM_ATTN>>>(q, k, vt, g, p, perm, out);
}

// round 11
// speedup vs baseline: 11.0301x; 1.1651x over previous
#include <cuda_runtime.h>
#include <cuda_fp16.h>
#include <math.h>
#include <stdint.h>

#define BB 2
#define SS 2048
#define HH 1024
#define NH 16
#define HD 64
#define BS (BB*SS)   // 4096
#define BH (BB*NH)   // 32

// Scratch (allocation-free: static device globals)
__device__ __half d_q[(size_t)BS*HH];
__device__ __half d_k[(size_t)BS*HH];
__device__ __half d_vt[(size_t)HH*BS];     // V transposed: [d][token]
__device__ __half d_x[(size_t)BS*HH];      // fp16 X
__device__ __half d_w[(size_t)3*HH*HH];    // fp16 W^T (per z: [n][k])
__device__ float  d_g[BS];
__device__ float  d_p[BS];
__device__ int    d_perm[BS];              // wide-first query order per batch

// ---------------------------------------------------------------------------
// helpers
// ---------------------------------------------------------------------------
__device__ __forceinline__ void cp16(uint32_t dst, const void* src){
    asm volatile("cp.async.cg.shared.global [%0], [%1], 16;" :: "r"(dst), "l"(src));
}
__device__ __forceinline__ void cp_commit(){ asm volatile("cp.async.commit_group;"); }
template<int N> __device__ __forceinline__ void cp_wait(){
    asm volatile("cp.async.wait_group %0;" :: "n"(N));
}
__device__ __forceinline__ void mma16(float* c, const uint32_t* a, const uint32_t* b){
    asm volatile("mma.sync.aligned.m16n8k16.row.col.f32.f16.f16.f32 "
        "{%0,%1,%2,%3}, {%4,%5,%6,%7}, {%8,%9}, {%0,%1,%2,%3};"
        : "+f"(c[0]),"+f"(c[1]),"+f"(c[2]),"+f"(c[3])
        : "r"(a[0]),"r"(a[1]),"r"(a[2]),"r"(a[3]), "r"(b[0]),"r"(b[1]));
}
__device__ __forceinline__ void ldsm4(uint32_t* d, uint32_t addr){
    asm volatile("ldmatrix.sync.aligned.m8n8.x4.shared.b16 {%0,%1,%2,%3}, [%4];"
        : "=r"(d[0]),"=r"(d[1]),"=r"(d[2]),"=r"(d[3]) : "r"(addr));
}
__device__ __forceinline__ uint32_t packh2(float a, float b){
    __half2 h = __floats2half2_rn(a, b);
    return *reinterpret_cast<uint32_t*>(&h);
}

// ---------------------------------------------------------------------------
// W fp32 [k][n] -> fp16 W^T [n][k], tiled; z selects source. block (32,8)
// ---------------------------------------------------------------------------
__global__ __launch_bounds__(256) void tconv_kernel(const float* __restrict__ s0,
                                                    const float* __restrict__ s1,
                                                    const float* __restrict__ s2,
                                                    __half* __restrict__ dst){
    const int z = blockIdx.z;
    const float* W = (z == 0) ? s0 : (z == 1) ? s1 : s2;
    __shared__ float ts[32][33];
    const int n0 = blockIdx.x*32, k0 = blockIdx.y*32;
    const int tx = threadIdx.x, ty = threadIdx.y;
    #pragma unroll
    for (int yy = 0; yy < 4; yy++){
        int k = k0 + ty + yy*8;
        ts[ty + yy*8][tx] = W[(size_t)k*HH + n0 + tx];
    }
    __syncthreads();
    #pragma unroll
    for (int yy = 0; yy < 4; yy++){
        int n = n0 + ty + yy*8;
        dst[(size_t)z*HH*HH + (size_t)n*HH + k0 + tx] = __float2half_rn(ts[tx][ty + yy*8]);
    }
}

// ---------------------------------------------------------------------------
// Gate + X convert: g = sigmoid(X @ Wg + bg), p = (S-2)^(1-g),
// plus fp16 copy of X (fused — gate already touches every element).
// ---------------------------------------------------------------------------
__global__ __launch_bounds__(256) void gate_kernel(const float* __restrict__ X,
                                                   const float* __restrict__ Wg,
                                                   const float* __restrict__ bg,
                                                   float* __restrict__ g,
                                                   float* __restrict__ p,
                                                   __half* __restrict__ xh) {
    int row = blockIdx.x;
    int tid = threadIdx.x;
    float4 xv = *(const float4*)(X + (size_t)row*HH + tid*4);
    float4 wv = *(const float4*)(Wg + tid*4);
    uint2 o = { packh2(xv.x, xv.y), packh2(xv.z, xv.w) };
    *(uint2*)(xh + (size_t)row*HH + tid*4) = o;

    float s = xv.x*wv.x + xv.y*wv.y + xv.z*wv.z + xv.w*wv.w;
    __shared__ float red[256];
    red[tid] = s; __syncthreads();
    for (int off = 128; off > 0; off >>= 1) {
        if (tid < off) red[tid] += red[tid+off];
        __syncthreads();
    }
    if (tid == 0) {
        float z = red[0] + bg[0];
        float gg = 1.f / (1.f + expf(-z));
        g[row] = gg;
        p[row] = powf((float)(SS-2), 1.f - gg);
    }
}

// ---------------------------------------------------------------------------
// Query ordering: stable counting sort into 4 pi-buckets per batch,
// WIDE-FIRST (bucket 0 = widest band) so slow CTAs launch at t~0.
// ---------------------------------------------------------------------------
__global__ __launch_bounds__(256) void order_kernel(const float* __restrict__ p,
                                                    int* __restrict__ perm){
    const int b = blockIdx.x, tid = threadIdx.x;
    const float* pb = p + (size_t)b*SS;
    __shared__ uint8_t bk[SS];
    __shared__ int sc[1024];
    int myc[4] = {0,0,0,0};
    #pragma unroll
    for (int e = 0; e < 8; e++){
        int i = tid*8 + e;
        float pi = pb[i];
        int k = (pi >= 800.f) ? 0 : (pi >= 288.f) ? 1 : (pi >= 96.f) ? 2 : 3;
        bk[i] = (uint8_t)k; myc[k]++;
    }
    #pragma unroll
    for (int k = 0; k < 4; k++) sc[k*256 + tid] = myc[k];
    __syncthreads();
    for (int off = 1; off < 1024; off <<= 1){
        int v[4];
        #pragma unroll
        for (int k = 0; k < 4; k++){
            int idx = k*256 + tid;
            v[k] = (idx >= off) ? sc[idx - off] : 0;
        }
        __syncthreads();
        #pragma unroll
        for (int k = 0; k < 4; k++) sc[k*256 + tid] += v[k];
        __syncthreads();
    }
    int base[4];
    #pragma unroll
    for (int k = 0; k < 4; k++) base[k] = sc[k*256 + tid] - myc[k];
    #pragma unroll
    for (int e = 0; e < 8; e++){
        int i = tid*8 + e;
        int k = bk[i];
        perm[(size_t)b*SS + base[k]++] = i;
    }
}

// ---------------------------------------------------------------------------
// Merged fp16 QKV projection with ldmatrix fragment loads, BK=64.
// z selects (W^T slice, bias, output). z=0,1: C [token][1024]; z=2: V^T.
// ---------------------------------------------------------------------------
#define PSTR 72   // smem row stride in halves (64 + 8 pad)

__global__ __launch_bounds__(256, 2) void gemm_proj(
    const __half* __restrict__ A, const __half* __restrict__ Wall,
    const float* __restrict__ b0, const float* __restrict__ b1,
    const float* __restrict__ b2,
    __half* __restrict__ C0, __half* __restrict__ C1, __half* __restrict__ Vt)
{
    const int z = blockIdx.z;
    const __half* Bp = Wall + (size_t)z*HH*HH;
    const float* bias = (z == 0) ? b0 : (z == 1) ? b1 : b2;

    extern __shared__ __half smh[];
    __half* Asm[2] = { smh, smh + 128*PSTR };
    __half* Bsm[2] = { smh + 2*128*PSTR, smh + 3*128*PSTR };

    const int tid = threadIdx.x, lane = tid & 31, wid = tid >> 5;
    const int wm = wid >> 2, wn = wid & 3;
    const int gq = lane & 3, gr = lane >> 2;

    const int iBase = blockIdx.y * 128;
    const int jBase = blockIdx.x * 128;

    float acc[4][4][4] = {};

    auto loadA = [&](int s, int kk){
        uint32_t base = (uint32_t)__cvta_generic_to_shared(Asm[s]);
        #pragma unroll
        for (int i = 0; i < 4; i++){
            int f = tid + i*256;
            int r = f >> 3, c8 = (f & 7) * 8;
            cp16(base + (uint32_t)(r*PSTR + c8)*2u, A + (size_t)(iBase + r)*HH + kk + c8);
        }
    };
    auto loadB = [&](int s, int kk){
        uint32_t base = (uint32_t)__cvta_generic_to_shared(Bsm[s]);
        #pragma unroll
        for (int i = 0; i < 4; i++){
            int f = tid + i*256;
            int n = f >> 3, c8 = (f & 7) * 8;
            cp16(base + (uint32_t)(n*PSTR + c8)*2u, Bp + (size_t)(jBase + n)*HH + kk + c8);
        }
    };

    const int arow = lane & 15;
    const int acol = (lane >> 4) * 8;
    const int brow = lane & 7;
    const int bcol = (lane >> 3) * 8;

    loadA(0, 0); loadB(0, 0); cp_commit();
    const int nK = HH / 64;   // 16
    for (int kt = 0; kt < nK; kt++){
        const int cur = kt & 1;
        if (kt + 1 < nK){
            loadA(cur ^ 1, (kt+1)*64); loadB(cur ^ 1, (kt+1)*64);
            cp_commit(); cp_wait<1>();
        } else {
            cp_wait<0>();
        }
        __syncthreads();
        uint32_t abase = (uint32_t)__cvta_generic_to_shared(Asm[cur]);
        uint32_t bbase = (uint32_t)__cvta_generic_to_shared(Bsm[cur]);
        #pragma unroll
        for (int kp = 0; kp < 2; kp++){
            uint32_t bfp[4][4];
            #pragma unroll
            for (int nt = 0; nt < 4; nt++){
                uint32_t addr = bbase +
                    (uint32_t)((wn*32 + nt*8 + brow)*PSTR + kp*32 + bcol)*2u;
                ldsm4(bfp[nt], addr);
            }
            #pragma unroll
            for (int k2 = 0; k2 < 2; k2++){
                uint32_t af[4][4];
                #pragma unroll
                for (int mt = 0; mt < 4; mt++){
                    uint32_t addr = abase +
                        (uint32_t)((wm*64 + mt*16 + arow)*PSTR + kp*32 + k2*16 + acol)*2u;
                    ldsm4(af[mt], addr);
                }
                #pragma unroll
                for (int mt = 0; mt < 4; mt++)
                    #pragma unroll
                    for (int nt = 0; nt < 4; nt++)
                        mma16(acc[mt][nt], af[mt], &bfp[nt][2*k2]);
            }
        }
        __syncthreads();
    }

    // epilogue
    #pragma unroll
    for (int mt = 0; mt < 4; mt++){
        int r0 = iBase + wm*64 + mt*16 + gr;
        int r1 = r0 + 8;
        #pragma unroll
        for (int nt = 0; nt < 4; nt++){
            int c0 = jBase + wn*32 + nt*8 + 2*gq;
            float bb0 = __ldg(bias + c0), bb1 = __ldg(bias + c0 + 1);
            float v0 = acc[mt][nt][0] + bb0, v1 = acc[mt][nt][1] + bb1;
            float v2 = acc[mt][nt][2] + bb0, v3 = acc[mt][nt][3] + bb1;
            if (z == 2){
                Vt[(size_t)c0*BS + r0]     = __float2half_rn(v0);
                Vt[(size_t)(c0+1)*BS + r0] = __float2half_rn(v1);
                Vt[(size_t)c0*BS + r1]     = __float2half_rn(v2);
                Vt[(size_t)(c0+1)*BS + r1] = __float2half_rn(v3);
            } else {
                __half* C = (z == 0) ? C0 : C1;
                uint32_t p0 = packh2(v0, v1), p1 = packh2(v2, v3);
                *(uint32_t*)(C + (size_t)r0*HH + c0) = p0;
                *(uint32_t*)(C + (size_t)r1*HH + c0) = p1;
            }
        }
    }
}

// ---------------------------------------------------------------------------
// Fused fp16 flash attention: wide-first query ordering + CTA-band j-loop
// + per-warp skip. Grid (bh=32, itile=16): itile-major launch order puts
// the wide (slow) CTAs first across all heads.
// ---------------------------------------------------------------------------
#define QSTR 72   // halves
#define JT   64
#define NJT  (SS/JT)   // 32

__device__ __forceinline__ float penexp(float om, float gi, float pi, int i,
                                        float gj, int j, float se){
    float res = om * fmaxf(om - gj, 0.f) + gi * fminf(om + gj, 1.f);
    float scope = fminf(fmaxf(pi + 2.f - fabsf((float)(i - j)), 1e-32f), 1.f);
    float pen = fmaxf(res * scope, 1e-32f);
    return pen * __expf(se);
}

__global__ __launch_bounds__(256, 2) void attn_fused(
    const __half* __restrict__ Q, const __half* __restrict__ Kg,
    const __half* __restrict__ Vt, const float* __restrict__ g,
    const float* __restrict__ p, const int* __restrict__ perm,
    float* __restrict__ out)
{
    const int bh = blockIdx.x, b = bh >> 4, h = bh & 15;
    const int iBase = blockIdx.y * 128;
    const int tid = threadIdx.x, lane = tid & 31, wid = tid >> 5;

    extern __shared__ __half smh[];
    __half* Qs  = smh;                    // 128*72
    __half* Ks0 = Qs  + 128*QSTR;         // 2 x 64*72
    __half* Vs0 = Ks0 + 2*JT*QSTR;        // 2 x 64*72   ([d][j])
    float*  gs  = (float*)(Vs0 + 2*JT*QSTR);  // 2048 floats
    __shared__ int bandLo[8], bandHi[8];

    const __half* Qp = Q  + (size_t)b*SS*HH + h*HD;
    const __half* Kp = Kg + (size_t)b*SS*HH + h*HD;
    const int* pm = perm + (size_t)b*SS;

    // prologue: Q tile (gathered through perm) + g row   (group 0)
    {
        uint32_t qb = (uint32_t)__cvta_generic_to_shared(Qs);
        #pragma unroll
        for (int l = 0; l < 4; l++){
            int f = tid + l*256;
            int r = f >> 3, c8 = (f & 7) * 8;
            int pr = __ldg(pm + iBase + r);
            cp16(qb + (uint32_t)(r*QSTR + c8)*2u, Qp + (size_t)pr*HH + c8);
        }
        uint32_t gb = (uint32_t)__cvta_generic_to_shared(gs);
        #pragma unroll
        for (int l = 0; l < 2; l++){
            int f = tid + l*256;
            cp16(gb + (uint32_t)f*16u, g + (size_t)b*SS + f*4);
        }
        cp_commit();
    }
    auto loadK = [&](int s, int j0){
        uint32_t kb = (uint32_t)__cvta_generic_to_shared(Ks0 + s*JT*QSTR);
        #pragma unroll
        for (int l = 0; l < 2; l++){
            int f = tid + l*256;
            int r = f >> 3, c8 = (f & 7) * 8;
            cp16(kb + (uint32_t)(r*QSTR + c8)*2u, Kp + (size_t)(j0 + r)*HH + c8);
        }
    };
    auto loadV = [&](int s, int j0){
        uint32_t vb = (uint32_t)__cvta_generic_to_shared(Vs0 + s*JT*QSTR);
        #pragma unroll
        for (int l = 0; l < 2; l++){
            int f = tid + l*256;
            int d = f >> 3, c8 = (f & 7) * 8;
            cp16(vb + (uint32_t)(d*QSTR + c8)*2u,
                 Vt + (size_t)(h*HD + d)*BS + b*SS + j0 + c8);
        }
    };

    const int gq = lane & 3, gr = lane >> 2;
    const int lr0 = wid*16 + gr;
    const int lr1 = lr0 + 8;
    const int ri0 = __ldg(pm + iBase + lr0);
    const int ri1 = __ldg(pm + iBase + lr1);
    const float gi0 = __ldg(g + (size_t)b*SS + ri0);
    const float gi1 = __ldg(g + (size_t)b*SS + ri1);
    const float pi0 = __ldg(p + (size_t)b*SS + ri0);
    const float pi1 = __ldg(p + (size_t)b*SS + ri1);
    const float om0 = 1.f - gi0, om1 = 1.f - gi1;

    // per-warp band
    float wlo = fminf((float)ri0 - pi0, (float)ri1 - pi1);
    float whi = fmaxf((float)ri0 + pi0, (float)ri1 + pi1);
    #pragma unroll
    for (int off = 16; off > 0; off >>= 1){
        wlo = fminf(wlo, __shfl_xor_sync(0xffffffffu, wlo, off));
        whi = fmaxf(whi, __shfl_xor_sync(0xffffffffu, whi, off));
    }
    const int blo = (int)floorf(wlo) - 3;
    const int bhi = (int)ceilf(whi) + 3;

    // CTA band reduce
    if (lane == 0){ bandLo[wid] = blo; bandHi[wid] = bhi; }
    __syncthreads();
    int cLo = bandLo[0], cHi = bandHi[0];
    #pragma unroll
    for (int wI = 1; wI < 8; wI++){
        cLo = min(cLo, bandLo[wI]); cHi = max(cHi, bandHi[wI]);
    }
    const int jtLo = (cLo <= 0) ? 0 : min(NJT-1, cLo / JT);
    const int jtHi = min(NJT-1, max(0, cHi) / JT);

    loadK(0, jtLo*JT); loadV(0, jtLo*JT); cp_commit();   // group 1

    float m0 = -1e30f, m1 = -1e30f, l0 = 0.f, l1 = 0.f;
    float oacc[8][4] = {};

    for (int jt = jtLo; jt <= jtHi; jt++){
        const int cur = (jt - jtLo) & 1;
        if (jt + 1 <= jtHi){
            loadK(cur ^ 1, (jt+1)*JT); loadV(cur ^ 1, (jt+1)*JT);
            cp_commit(); cp_wait<1>();
        } else {
            cp_wait<0>();
        }
        __syncthreads();
        const int jBase = jt*JT;
        const bool active = (jBase + JT - 1 >= blo) && (jBase <= bhi);
        if (active){
            const __half* Ks = Ks0 + cur*JT*QSTR;
            const __half* Vs = Vs0 + cur*JT*QSTR;

            // --- S = Q K^T ---
            float sacc[8][4];
            #pragma unroll
            for (int nt = 0; nt < 8; nt++){
                sacc[nt][0]=0.f; sacc[nt][1]=0.f; sacc[nt][2]=0.f; sacc[nt][3]=0.f;
            }
            #pragma unroll
            for (int ks = 0; ks < 4; ks++){
                const int k0 = ks*16 + 2*gq;
                uint32_t af[4];
                af[0] = *(const uint32_t*)&Qs[lr0*QSTR + k0];
                af[1] = *(const uint32_t*)&Qs[lr1*QSTR + k0];
                af[2] = *(const uint32_t*)&Qs[lr0*QSTR + k0 + 8];
                af[3] = *(const uint32_t*)&Qs[lr1*QSTR + k0 + 8];
                #pragma unroll
                for (int nt = 0; nt < 8; nt++){
                    const int n = nt*8 + gr;
                    uint32_t bf[2];
                    bf[0] = *(const uint32_t*)&Ks[n*QSTR + k0];
                    bf[1] = *(const uint32_t*)&Ks[n*QSTR + k0 + 8];
                    mma16(sacc[nt], af, bf);
                }
            }

            // --- online softmax ---
            float tm0 = -1e30f, tm1 = -1e30f;
            #pragma unroll
            for (int nt = 0; nt < 8; nt++){
                tm0 = fmaxf(tm0, fmaxf(sacc[nt][0], sacc[nt][1]));
                tm1 = fmaxf(tm1, fmaxf(sacc[nt][2], sacc[nt][3]));
            }
            tm0 = fmaxf(tm0, __shfl_xor_sync(0xffffffffu, tm0, 1));
            tm0 = fmaxf(tm0, __shfl_xor_sync(0xffffffffu, tm0, 2));
            tm1 = fmaxf(tm1, __shfl_xor_sync(0xffffffffu, tm1, 1));
            tm1 = fmaxf(tm1, __shfl_xor_sync(0xffffffffu, tm1, 2));
            tm0 *= 0.125f; tm1 *= 0.125f;
            const float m0n = fmaxf(m0, tm0), m1n = fmaxf(m1, tm1);
            const float f0 = __expf(m0 - m0n), f1 = __expf(m1 - m1n);
            m0 = m0n; m1 = m1n;
            l0 *= f0; l1 *= f1;
            #pragma unroll
            for (int dn = 0; dn < 8; dn++){
                oacc[dn][0] *= f0; oacc[dn][1] *= f0;
                oacc[dn][2] *= f1; oacc[dn][3] *= f1;
            }
            float rs0 = 0.f, rs1 = 0.f;
            #pragma unroll
            for (int nt = 0; nt < 8; nt++){
                const int j0 = jBase + nt*8 + 2*gq;
                const int j1 = j0 + 1;
                const float gj0 = gs[j0], gj1 = gs[j1];
                float t00 = penexp(om0, gi0, pi0, ri0, gj0, j0, sacc[nt][0]*0.125f - m0);
                float t01 = penexp(om0, gi0, pi0, ri0, gj1, j1, sacc[nt][1]*0.125f - m0);
                float t10 = penexp(om1, gi1, pi1, ri1, gj0, j0, sacc[nt][2]*0.125f - m1);
                float t11 = penexp(om1, gi1, pi1, ri1, gj1, j1, sacc[nt][3]*0.125f - m1);
                sacc[nt][0] = t00; sacc[nt][1] = t01;
                sacc[nt][2] = t10; sacc[nt][3] = t11;
                rs0 += t00 + t01; rs1 += t10 + t11;
            }
            rs0 += __shfl_xor_sync(0xffffffffu, rs0, 1);
            rs0 += __shfl_xor_sync(0xffffffffu, rs0, 2);
            rs1 += __shfl_xor_sync(0xffffffffu, rs1, 1);
            rs1 += __shfl_xor_sync(0xffffffffu, rs1, 2);
            l0 += rs0; l1 += rs1;

            // --- O += P V : C-frag pairs map directly onto fp16 A-frags ---
            #pragma unroll
            for (int kc = 0; kc < 4; kc++){
                uint32_t af[4];
                af[0] = packh2(sacc[2*kc][0],   sacc[2*kc][1]);
                af[1] = packh2(sacc[2*kc][2],   sacc[2*kc][3]);
                af[2] = packh2(sacc[2*kc+1][0], sacc[2*kc+1][1]);
                af[3] = packh2(sacc[2*kc+1][2], sacc[2*kc+1][3]);
                const int kb = kc*16 + 2*gq;
                #pragma unroll
                for (int dn = 0; dn < 8; dn++){
                    const int d0 = dn*8 + gr;
                    uint32_t bf[2];
                    bf[0] = *(const uint32_t*)&Vs[d0*QSTR + kb];
                    bf[1] = *(const uint32_t*)&Vs[d0*QSTR + kb + 8];
                    mma16(oacc[dn], af, bf);
                }
            }
        }
        __syncthreads();
    }

    // epilogue: scatter to original rows (fp32 output)
    const float inv0 = 1.f / l0, inv1 = 1.f / l1;
    float* op = out + (size_t)b*SS*HH + h*HD;
    #pragma unroll
    for (int dn = 0; dn < 8; dn++){
        const int c0 = dn*8 + 2*gq;
        float2 o0 = { oacc[dn][0]*inv0, oacc[dn][1]*inv0 };
        float2 o1 = { oacc[dn][2]*inv1, oacc[dn][3]*inv1 };
        *(float2*)(op + (size_t)ri0*HH + c0) = o0;
        *(float2*)(op + (size_t)ri1*HH + c0) = o1;
    }
}

// ---------------------------------------------------------------------------
extern "C" void kernel_launch(void* const* d_in, const int* in_sizes, int n_in,
                              void* d_out, int out_size) {
    const float* X  = (const float*)d_in[0];
    const float* Wq = (const float*)d_in[1];
    const float* bq = (const float*)d_in[2];
    const float* Wk = (const float*)d_in[3];
    const float* bk = (const float*)d_in[4];
    const float* Wv = (const float*)d_in[5];
    const float* bv = (const float*)d_in[6];
    const float* Wg = (const float*)d_in[7];
    const float* bg = (const float*)d_in[8];
    float* out = (float*)d_out;

    __half *q, *k, *vt, *x, *w;
    float *g, *p;
    int *perm;
    cudaGetSymbolAddress((void**)&q,  d_q);
    cudaGetSymbolAddress((void**)&k,  d_k);
    cudaGetSymbolAddress((void**)&vt, d_vt);
    cudaGetSymbolAddress((void**)&x,  d_x);
    cudaGetSymbolAddress((void**)&w,  d_w);
    cudaGetSymbolAddress((void**)&g,  d_g);
    cudaGetSymbolAddress((void**)&p,  d_p);
    cudaGetSymbolAddress((void**)&perm, d_perm);

    constexpr int SM_PROJ = 4*128*PSTR*2;                                    // 73728
    constexpr int SM_ATTN = (128*QSTR + 2*JT*QSTR + 2*JT*QSTR)*2 + SS*4;     // 63488
    cudaFuncSetAttribute(gemm_proj,
                         cudaFuncAttributeMaxDynamicSharedMemorySize, SM_PROJ);
    cudaFuncSetAttribute(attn_fused,
                         cudaFuncAttributeMaxDynamicSharedMemorySize, SM_ATTN);

    // prep: W transpose-convert + gate(+X convert) + ordering
    dim3 gt(HH/32, HH/32, 3);
    tconv_kernel<<<gt, dim3(32,8)>>>(Wq, Wk, Wv, w);
    gate_kernel<<<BS, 256>>>(X, Wg, bg, g, p, x);
    order_kernel<<<BB, 256>>>(p, perm);

    // merged QKV projection
    dim3 gp(HH/128, BS/128, 3);   // (8, 32, 3)
    gemm_proj<<<gp, 256, SM_PROJ>>>(x, w, bq, bk, bv, q, k, vt);

    // attn: bh-fastest grid -> wide itiles (0,1,..) launch first for all heads
    dim3 ga(BH, SS/128);   // (32, 16)
    attn_fused<<<ga, 256, SM_ATTN>>>(q, k, vt, g, p, perm, out);
}

// round 13
// speedup vs baseline: 11.2469x; 1.0197x over previous
#include <cuda_runtime.h>
#include <cuda_fp16.h>
#include <math.h>
#include <stdint.h>

#define BB 2
#define SS 2048
#define HH 1024
#define NH 16
#define HD 64
#define BS (BB*SS)   // 4096
#define BH (BB*NH)   // 32

// Scratch (allocation-free: static device globals)
__device__ __half d_q[(size_t)BS*HH];
__device__ __half d_k[(size_t)BS*HH];
__device__ __half d_vt[(size_t)HH*BS];     // V transposed: [d][token]
__device__ __half d_x[(size_t)BS*HH];      // fp16 X
__device__ __half d_w[(size_t)3*HH*HH];    // fp16 W^T (per z: [n][k])
__device__ float  d_g[BS];
__device__ float  d_p[BS];
__device__ int    d_perm[BS];              // wide-first query order per batch

// ---------------------------------------------------------------------------
// helpers
// ---------------------------------------------------------------------------
__device__ __forceinline__ void cp16(uint32_t dst, const void* src){
    asm volatile("cp.async.cg.shared.global [%0], [%1], 16;" :: "r"(dst), "l"(src));
}
__device__ __forceinline__ void cp_commit(){ asm volatile("cp.async.commit_group;"); }
template<int N> __device__ __forceinline__ void cp_wait(){
    asm volatile("cp.async.wait_group %0;" :: "n"(N));
}
__device__ __forceinline__ void mma16(float* c, const uint32_t* a, const uint32_t* b){
    asm volatile("mma.sync.aligned.m16n8k16.row.col.f32.f16.f16.f32 "
        "{%0,%1,%2,%3}, {%4,%5,%6,%7}, {%8,%9}, {%0,%1,%2,%3};"
        : "+f"(c[0]),"+f"(c[1]),"+f"(c[2]),"+f"(c[3])
        : "r"(a[0]),"r"(a[1]),"r"(a[2]),"r"(a[3]), "r"(b[0]),"r"(b[1]));
}
__device__ __forceinline__ void ldsm4(uint32_t* d, uint32_t addr){
    asm volatile("ldmatrix.sync.aligned.m8n8.x4.shared.b16 {%0,%1,%2,%3}, [%4];"
        : "=r"(d[0]),"=r"(d[1]),"=r"(d[2]),"=r"(d[3]) : "r"(addr));
}
__device__ __forceinline__ uint32_t packh2(float a, float b){
    __half2 h = __floats2half2_rn(a, b);
    return *reinterpret_cast<uint32_t*>(&h);
}

// ---------------------------------------------------------------------------
// W fp32 [k][n] -> fp16 W^T [n][k], tiled; z selects source. block (32,8)
// ---------------------------------------------------------------------------
__global__ __launch_bounds__(256) void tconv_kernel(const float* __restrict__ s0,
                                                    const float* __restrict__ s1,
                                                    const float* __restrict__ s2,
                                                    __half* __restrict__ dst){
    const int z = blockIdx.z;
    const float* W = (z == 0) ? s0 : (z == 1) ? s1 : s2;
    __shared__ float ts[32][33];
    const int n0 = blockIdx.x*32, k0 = blockIdx.y*32;
    const int tx = threadIdx.x, ty = threadIdx.y;
    #pragma unroll
    for (int yy = 0; yy < 4; yy++){
        int k = k0 + ty + yy*8;
        ts[ty + yy*8][tx] = W[(size_t)k*HH + n0 + tx];
    }
    __syncthreads();
    #pragma unroll
    for (int yy = 0; yy < 4; yy++){
        int n = n0 + ty + yy*8;
        dst[(size_t)z*HH*HH + (size_t)n*HH + k0 + tx] = __float2half_rn(ts[tx][ty + yy*8]);
    }
}

// ---------------------------------------------------------------------------
// Gate + X convert: g = sigmoid(X @ Wg + bg), p = (S-2)^(1-g),
// plus fp16 copy of X (fused — gate already touches every element).
// ---------------------------------------------------------------------------
__global__ __launch_bounds__(256) void gate_kernel(const float* __restrict__ X,
                                                   const float* __restrict__ Wg,
                                                   const float* __restrict__ bg,
                                                   float* __restrict__ g,
                                                   float* __restrict__ p,
                                                   __half* __restrict__ xh) {
    int row = blockIdx.x;
    int tid = threadIdx.x;
    float4 xv = *(const float4*)(X + (size_t)row*HH + tid*4);
    float4 wv = *(const float4*)(Wg + tid*4);
    uint2 o = { packh2(xv.x, xv.y), packh2(xv.z, xv.w) };
    *(uint2*)(xh + (size_t)row*HH + tid*4) = o;

    float s = xv.x*wv.x + xv.y*wv.y + xv.z*wv.z + xv.w*wv.w;
    __shared__ float red[256];
    red[tid] = s; __syncthreads();
    for (int off = 128; off > 0; off >>= 1) {
        if (tid < off) red[tid] += red[tid+off];
        __syncthreads();
    }
    if (tid == 0) {
        float z = red[0] + bg[0];
        float gg = 1.f / (1.f + expf(-z));
        g[row] = gg;
        p[row] = powf((float)(SS-2), 1.f - gg);
    }
}

// ---------------------------------------------------------------------------
// Query ordering: WIDE-FIRST stable counting sort into 4 pi-buckets per batch.
// ---------------------------------------------------------------------------
__global__ __launch_bounds__(256) void order_kernel(const float* __restrict__ p,
                                                    int* __restrict__ perm){
    const int b = blockIdx.x, tid = threadIdx.x;
    const float* pb = p + (size_t)b*SS;
    __shared__ uint8_t bk[SS];
    __shared__ int sc[1024];
    int myc[4] = {0,0,0,0};
    #pragma unroll
    for (int e = 0; e < 8; e++){
        int i = tid*8 + e;
        float pi = pb[i];
        int k = (pi >= 800.f) ? 0 : (pi >= 288.f) ? 1 : (pi >= 96.f) ? 2 : 3;
        bk[i] = (uint8_t)k; myc[k]++;
    }
    #pragma unroll
    for (int k = 0; k < 4; k++) sc[k*256 + tid] = myc[k];
    __syncthreads();
    for (int off = 1; off < 1024; off <<= 1){
        int v[4];
        #pragma unroll
        for (int k = 0; k < 4; k++){
            int idx = k*256 + tid;
            v[k] = (idx >= off) ? sc[idx - off] : 0;
        }
        __syncthreads();
        #pragma unroll
        for (int k = 0; k < 4; k++) sc[k*256 + tid] += v[k];
        __syncthreads();
    }
    int base[4];
    #pragma unroll
    for (int k = 0; k < 4; k++) base[k] = sc[k*256 + tid] - myc[k];
    #pragma unroll
    for (int e = 0; e < 8; e++){
        int i = tid*8 + e;
        int k = bk[i];
        perm[(size_t)b*SS + base[k]++] = i;
    }
}

// ---------------------------------------------------------------------------
// Merged fp16 QKV projection: ldmatrix fragments, BK=64, 3-stage cp.async
// pipeline with ONE barrier per k-iteration.
// z selects (W^T slice, bias, output). z=0,1: C [token][1024]; z=2: V^T.
// ---------------------------------------------------------------------------
#define PSTR 72   // smem row stride in halves (64 + 8 pad)
#define NSTG 3

__global__ __launch_bounds__(256, 2) void gemm_proj(
    const __half* __restrict__ A, const __half* __restrict__ Wall,
    const float* __restrict__ b0, const float* __restrict__ b1,
    const float* __restrict__ b2,
    __half* __restrict__ C0, __half* __restrict__ C1, __half* __restrict__ Vt)
{
    const int z = blockIdx.z;
    const __half* Bp = Wall + (size_t)z*HH*HH;
    const float* bias = (z == 0) ? b0 : (z == 1) ? b1 : b2;

    extern __shared__ __half smh[];
    // stage s: A at smh + s*2*128*PSTR, B right after A
    const int tid = threadIdx.x, lane = tid & 31, wid = tid >> 5;
    const int wm = wid >> 2, wn = wid & 3;
    const int gq = lane & 3, gr = lane >> 2;

    const int iBase = blockIdx.y * 128;
    const int jBase = blockIdx.x * 128;

    float acc[4][4][4] = {};

    auto loadTile = [&](int s, int kk){
        __half* As = smh + (size_t)s*2*128*PSTR;
        __half* Bs = As + 128*PSTR;
        uint32_t ab = (uint32_t)__cvta_generic_to_shared(As);
        uint32_t bb = (uint32_t)__cvta_generic_to_shared(Bs);
        #pragma unroll
        for (int i = 0; i < 4; i++){
            int f = tid + i*256;
            int r = f >> 3, c8 = (f & 7) * 8;
            cp16(ab + (uint32_t)(r*PSTR + c8)*2u, A + (size_t)(iBase + r)*HH + kk + c8);
        }
        #pragma unroll
        for (int i = 0; i < 4; i++){
            int f = tid + i*256;
            int n = f >> 3, c8 = (f & 7) * 8;
            cp16(bb + (uint32_t)(n*PSTR + c8)*2u, Bp + (size_t)(jBase + n)*HH + kk + c8);
        }
    };

    const int arow = lane & 15;
    const int acol = (lane >> 4) * 8;
    const int brow = lane & 7;
    const int bcol = (lane >> 3) * 8;

    loadTile(0, 0); cp_commit();
    loadTile(1, 64); cp_commit();

    const int nK = HH / 64;   // 16
    for (int kt = 0; kt < nK; kt++){
        const int cur = kt % NSTG;
        if (kt + 1 < nK) cp_wait<1>(); else cp_wait<0>();
        __syncthreads();
        // prefetch stage (kt+2)%NSTG == stage read at kt-1; barrier above makes it safe
        if (kt + 2 < nK){ loadTile((kt + 2) % NSTG, (kt + 2)*64); cp_commit(); }

        uint32_t abase = (uint32_t)__cvta_generic_to_shared(smh + (size_t)cur*2*128*PSTR);
        uint32_t bbase = abase + 128*PSTR*2;   // bytes: 128*PSTR halves
        #pragma unroll
        for (int kp = 0; kp < 2; kp++){
            uint32_t bfp[4][4];
            #pragma unroll
            for (int nt = 0; nt < 4; nt++){
                uint32_t addr = bbase +
                    (uint32_t)((wn*32 + nt*8 + brow)*PSTR + kp*32 + bcol)*2u;
                ldsm4(bfp[nt], addr);
            }
            #pragma unroll
            for (int k2 = 0; k2 < 2; k2++){
                uint32_t af[4][4];
                #pragma unroll
                for (int mt = 0; mt < 4; mt++){
                    uint32_t addr = abase +
                        (uint32_t)((wm*64 + mt*16 + arow)*PSTR + kp*32 + k2*16 + acol)*2u;
                    ldsm4(af[mt], addr);
                }
                #pragma unroll
                for (int mt = 0; mt < 4; mt++)
                    #pragma unroll
                    for (int nt = 0; nt < 4; nt++)
                        mma16(acc[mt][nt], af[mt], &bfp[nt][2*k2]);
            }
        }
    }

    // epilogue
    #pragma unroll
    for (int mt = 0; mt < 4; mt++){
        int r0 = iBase + wm*64 + mt*16 + gr;
        int r1 = r0 + 8;
        #pragma unroll
        for (int nt = 0; nt < 4; nt++){
            int c0 = jBase + wn*32 + nt*8 + 2*gq;
            float bb0 = __ldg(bias + c0), bb1 = __ldg(bias + c0 + 1);
            float v0 = acc[mt][nt][0] + bb0, v1 = acc[mt][nt][1] + bb1;
            float v2 = acc[mt][nt][2] + bb0, v3 = acc[mt][nt][3] + bb1;
            if (z == 2){
                Vt[(size_t)c0*BS + r0]     = __float2half_rn(v0);
                Vt[(size_t)(c0+1)*BS + r0] = __float2half_rn(v1);
                Vt[(size_t)c0*BS + r1]     = __float2half_rn(v2);
                Vt[(size_t)(c0+1)*BS + r1] = __float2half_rn(v3);
            } else {
                __half* C = (z == 0) ? C0 : C1;
                uint32_t p0 = packh2(v0, v1), p1 = packh2(v2, v3);
                *(uint32_t*)(C + (size_t)r0*HH + c0) = p0;
                *(uint32_t*)(C + (size_t)r1*HH + c0) = p1;
            }
        }
    }
}

// ---------------------------------------------------------------------------
// Fused fp16 flash attention: wide-first query ordering + CTA-band j-loop
// + per-warp skip. Grid (bh=32, itile=16): itile-major launch order puts
// the wide (slow) CTAs first across all heads.
// ---------------------------------------------------------------------------
#define QSTR 72   // halves
#define JT   64
#define NJT  (SS/JT)   // 32

__device__ __forceinline__ float penexp(float om, float gi, float pi, int i,
                                        float gj, int j, float se){
    float res = om * fmaxf(om - gj, 0.f) + gi * fminf(om + gj, 1.f);
    float scope = fminf(fmaxf(pi + 2.f - fabsf((float)(i - j)), 1e-32f), 1.f);
    float pen = fmaxf(res * scope, 1e-32f);
    return pen * __expf(se);
}

__global__ __launch_bounds__(256, 2) void attn_fused(
    const __half* __restrict__ Q, const __half* __restrict__ Kg,
    const __half* __restrict__ Vt, const float* __restrict__ g,
    const float* __restrict__ p, const int* __restrict__ perm,
    float* __restrict__ out)
{
    const int bh = blockIdx.x, b = bh >> 4, h = bh & 15;
    const int iBase = blockIdx.y * 128;
    const int tid = threadIdx.x, lane = tid & 31, wid = tid >> 5;

    extern __shared__ __half smh[];
    __half* Qs  = smh;
    __half* Ks0 = Qs  + 128*QSTR;
    __half* Vs0 = Ks0 + 2*JT*QSTR;
    float*  gs  = (float*)(Vs0 + 2*JT*QSTR);
    __shared__ int bandLo[8], bandHi[8];

    const __half* Qp = Q  + (size_t)b*SS*HH + h*HD;
    const __half* Kp = Kg + (size_t)b*SS*HH + h*HD;
    const int* pm = perm + (size_t)b*SS;

    {
        uint32_t qb = (uint32_t)__cvta_generic_to_shared(Qs);
        #pragma unroll
        for (int l = 0; l < 4; l++){
            int f = tid + l*256;
            int r = f >> 3, c8 = (f & 7) * 8;
            int pr = __ldg(pm + iBase + r);
            cp16(qb + (uint32_t)(r*QSTR + c8)*2u, Qp + (size_t)pr*HH + c8);
        }
        uint32_t gb = (uint32_t)__cvta_generic_to_shared(gs);
        #pragma unroll
        for (int l = 0; l < 2; l++){
            int f = tid + l*256;
            cp16(gb + (uint32_t)f*16u, g + (size_t)b*SS + f*4);
        }
        cp_commit();
    }
    auto loadK = [&](int s, int j0){
        uint32_t kb = (uint32_t)__cvta_generic_to_shared(Ks0 + s*JT*QSTR);
        #pragma unroll
        for (int l = 0; l < 2; l++){
            int f = tid + l*256;
            int r = f >> 3, c8 = (f & 7) * 8;
            cp16(kb + (uint32_t)(r*QSTR + c8)*2u, Kp + (size_t)(j0 + r)*HH + c8);
        }
    };
    auto loadV = [&](int s, int j0){
        uint32_t vb = (uint32_t)__cvta_generic_to_shared(Vs0 + s*JT*QSTR);
        #pragma unroll
        for (int l = 0; l < 2; l++){
            int f = tid + l*256;
            int d = f >> 3, c8 = (f & 7) * 8;
            cp16(vb + (uint32_t)(d*QSTR + c8)*2u,
                 Vt + (size_t)(h*HD + d)*BS + b*SS + j0 + c8);
        }
    };

    const int gq = lane & 3, gr = lane >> 2;
    const int lr0 = wid*16 + gr;
    const int lr1 = lr0 + 8;
    const int ri0 = __ldg(pm + iBase + lr0);
    const int ri1 = __ldg(pm + iBase + lr1);
    const float gi0 = __ldg(g + (size_t)b*SS + ri0);
    const float gi1 = __ldg(g + (size_t)b*SS + ri1);
    const float pi0 = __ldg(p + (size_t)b*SS + ri0);
    const float pi1 = __ldg(p + (size_t)b*SS + ri1);
    const float om0 = 1.f - gi0, om1 = 1.f - gi1;

    float wlo = fminf((float)ri0 - pi0, (float)ri1 - pi1);
    float whi = fmaxf((float)ri0 + pi0, (float)ri1 + pi1);
    #pragma unroll
    for (int off = 16; off > 0; off >>= 1){
        wlo = fminf(wlo, __shfl_xor_sync(0xffffffffu, wlo, off));
        whi = fmaxf(whi, __shfl_xor_sync(0xffffffffu, whi, off));
    }
    const int blo = (int)floorf(wlo) - 3;
    const int bhi = (int)ceilf(whi) + 3;

    if (lane == 0){ bandLo[wid] = blo; bandHi[wid] = bhi; }
    __syncthreads();
    int cLo = bandLo[0], cHi = bandHi[0];
    #pragma unroll
    for (int wI = 1; wI < 8; wI++){
        cLo = min(cLo, bandLo[wI]); cHi = max(cHi, bandHi[wI]);
    }
    const int jtLo = (cLo <= 0) ? 0 : min(NJT-1, cLo / JT);
    const int jtHi = min(NJT-1, max(0, cHi) / JT);

    loadK(0, jtLo*JT); loadV(0, jtLo*JT); cp_commit();

    float m0 = -1e30f, m1 = -1e30f, l0 = 0.f, l1 = 0.f;
    float oacc[8][4] = {};

    for (int jt = jtLo; jt <= jtHi; jt++){
        const int cur = (jt - jtLo) & 1;
        if (jt + 1 <= jtHi){
            loadK(cur ^ 1, (jt+1)*JT); loadV(cur ^ 1, (jt+1)*JT);
            cp_commit(); cp_wait<1>();
        } else {
            cp_wait<0>();
        }
        __syncthreads();
        const int jBase = jt*JT;
        const bool active = (jBase + JT - 1 >= blo) && (jBase <= bhi);
        if (active){
            const __half* Ks = Ks0 + cur*JT*QSTR;
            const __half* Vs = Vs0 + cur*JT*QSTR;

            float sacc[8][4];
            #pragma unroll
            for (int nt = 0; nt < 8; nt++){
                sacc[nt][0]=0.f; sacc[nt][1]=0.f; sacc[nt][2]=0.f; sacc[nt][3]=0.f;
            }
            #pragma unroll
            for (int ks = 0; ks < 4; ks++){
                const int k0 = ks*16 + 2*gq;
                uint32_t af[4];
                af[0] = *(const uint32_t*)&Qs[lr0*QSTR + k0];
                af[1] = *(const uint32_t*)&Qs[lr1*QSTR + k0];
                af[2] = *(const uint32_t*)&Qs[lr0*QSTR + k0 + 8];
                af[3] = *(const uint32_t*)&Qs[lr1*QSTR + k0 + 8];
                #pragma unroll
                for (int nt = 0; nt < 8; nt++){
                    const int n = nt*8 + gr;
                    uint32_t bf[2];
                    bf[0] = *(const uint32_t*)&Ks[n*QSTR + k0];
                    bf[1] = *(const uint32_t*)&Ks[n*QSTR + k0 + 8];
                    mma16(sacc[nt], af, bf);
                }
            }

            float tm0 = -1e30f, tm1 = -1e30f;
            #pragma unroll
            for (int nt = 0; nt < 8; nt++){
                tm0 = fmaxf(tm0, fmaxf(sacc[nt][0], sacc[nt][1]));
                tm1 = fmaxf(tm1, fmaxf(sacc[nt][2], sacc[nt][3]));
            }
            tm0 = fmaxf(tm0, __shfl_xor_sync(0xffffffffu, tm0, 1));
            tm0 = fmaxf(tm0, __shfl_xor_sync(0xffffffffu, tm0, 2));
            tm1 = fmaxf(tm1, __shfl_xor_sync(0xffffffffu, tm1, 1));
            tm1 = fmaxf(tm1, __shfl_xor_sync(0xffffffffu, tm1, 2));
            tm0 *= 0.125f; tm1 *= 0.125f;
            const float m0n = fmaxf(m0, tm0), m1n = fmaxf(m1, tm1);
            const float f0 = __expf(m0 - m0n), f1 = __expf(m1 - m1n);
            m0 = m0n; m1 = m1n;
            l0 *= f0; l1 *= f1;
            #pragma unroll
            for (int dn = 0; dn < 8; dn++){
                oacc[dn][0] *= f0; oacc[dn][1] *= f0;
                oacc[dn][2] *= f1; oacc[dn][3] *= f1;
            }
            float rs0 = 0.f, rs1 = 0.f;
            #pragma unroll
            for (int nt = 0; nt < 8; nt++){
                const int j0 = jBase + nt*8 + 2*gq;
                const int j1 = j0 + 1;
                const float gj0 = gs[j0], gj1 = gs[j1];
                float t00 = penexp(om0, gi0, pi0, ri0, gj0, j0, sacc[nt][0]*0.125f - m0);
                float t01 = penexp(om0, gi0, pi0, ri0, gj1, j1, sacc[nt][1]*0.125f - m0);
                float t10 = penexp(om1, gi1, pi1, ri1, gj0, j0, sacc[nt][2]*0.125f - m1);
                float t11 = penexp(om1, gi1, pi1, ri1, gj1, j1, sacc[nt][3]*0.125f - m1);
                sacc[nt][0] = t00; sacc[nt][1] = t01;
                sacc[nt][2] = t10; sacc[nt][3] = t11;
                rs0 += t00 + t01; rs1 += t10 + t11;
            }
            rs0 += __shfl_xor_sync(0xffffffffu, rs0, 1);
            rs0 += __shfl_xor_sync(0xffffffffu, rs0, 2);
            rs1 += __shfl_xor_sync(0xffffffffu, rs1, 1);
            rs1 += __shfl_xor_sync(0xffffffffu, rs1, 2);
            l0 += rs0; l1 += rs1;

            #pragma unroll
            for (int kc = 0; kc < 4; kc++){
                uint32_t af[4];
                af[0] = packh2(sacc[2*kc][0],   sacc[2*kc][1]);
                af[1] = packh2(sacc[2*kc][2],   sacc[2*kc][3]);
                af[2] = packh2(sacc[2*kc+1][0], sacc[2*kc+1][1]);
                af[3] = packh2(sacc[2*kc+1][2], sacc[2*kc+1][3]);
                const int kb = kc*16 + 2*gq;
                #pragma unroll
                for (int dn = 0; dn < 8; dn++){
                    const int d0 = dn*8 + gr;
                    uint32_t bf[2];
                    bf[0] = *(const uint32_t*)&Vs[d0*QSTR + kb];
                    bf[1] = *(const uint32_t*)&Vs[d0*QSTR + kb + 8];
                    mma16(oacc[dn], af, bf);
                }
            }
        }
        __syncthreads();
    }

    const float inv0 = 1.f / l0, inv1 = 1.f / l1;
    float* op = out + (size_t)b*SS*HH + h*HD;
    #pragma unroll
    for (int dn = 0; dn < 8; dn++){
        const int c0 = dn*8 + 2*gq;
        float2 o0 = { oacc[dn][0]*inv0, oacc[dn][1]*inv0 };
        float2 o1 = { oacc[dn][2]*inv1, oacc[dn][3]*inv1 };
        *(float2*)(op + (size_t)ri0*HH + c0) = o0;
        *(float2*)(op + (size_t)ri1*HH + c0) = o1;
    }
}

// ---------------------------------------------------------------------------
extern "C" void kernel_launch(void* const* d_in, const int* in_sizes, int n_in,
                              void* d_out, int out_size) {
    const float* X  = (const float*)d_in[0];
    const float* Wq = (const float*)d_in[1];
    const float* bq = (const float*)d_in[2];
    const float* Wk = (const float*)d_in[3];
    const float* bk = (const float*)d_in[4];
    const float* Wv = (const float*)d_in[5];
    const float* bv = (const float*)d_in[6];
    const float* Wg = (const float*)d_in[7];
    const float* bg = (const float*)d_in[8];
    float* out = (float*)d_out;

    __half *q, *k, *vt, *x, *w;
    float *g, *p;
    int *perm;
    cudaGetSymbolAddress((void**)&q,  d_q);
    cudaGetSymbolAddress((void**)&k,  d_k);
    cudaGetSymbolAddress((void**)&vt, d_vt);
    cudaGetSymbolAddress((void**)&x,  d_x);
    cudaGetSymbolAddress((void**)&w,  d_w);
    cudaGetSymbolAddress((void**)&g,  d_g);
    cudaGetSymbolAddress((void**)&p,  d_p);
    cudaGetSymbolAddress((void**)&perm, d_perm);

    constexpr int SM_PROJ = NSTG*2*128*PSTR*2;                               // 110592
    constexpr int SM_ATTN = (128*QSTR + 2*JT*QSTR + 2*JT*QSTR)*2 + SS*4;     // 63488
    cudaFuncSetAttribute(gemm_proj,
                         cudaFuncAttributeMaxDynamicSharedMemorySize, SM_PROJ);
    cudaFuncSetAttribute(attn_fused,
                         cudaFuncAttributeMaxDynamicSharedMemorySize, SM_ATTN);

    // prep: W transpose-convert + gate(+X convert) + ordering
    dim3 gt(HH/32, HH/32, 3);
    tconv_kernel<<<gt, dim3(32,8)>>>(Wq, Wk, Wv, w);
    gate_kernel<<<BS, 256>>>(X, Wg, bg, g, p, x);
    order_kernel<<<BB, 256>>>(p, perm);

    // merged QKV projection
    dim3 gp(HH/128, BS/128, 3);   // (8, 32, 3)
    gemm_proj<<<gp, 256, SM_PROJ>>>(x, w, bq, bk, bv, q, k, vt);

    // attn: bh-fastest grid -> wide itiles launch first
    dim3 ga(BH, SS/128);   // (32, 16)
    attn_fused<<<ga, 256, SM_ATTN>>>(q, k, vt, g, p, perm, out);
}

// round 14
// speedup vs baseline: 11.3783x; 1.0117x over previous
#include <cuda_runtime.h>
#include <cuda_fp16.h>
#include <math.h>
#include <stdint.h>

#define BB 2
#define SS 2048
#define HH 1024
#define NH 16
#define HD 64
#define BS (BB*SS)   // 4096
#define BH (BB*NH)   // 32

// Scratch (allocation-free: static device globals)
__device__ __half d_q[(size_t)BS*HH];
__device__ __half d_k[(size_t)BS*HH];
__device__ __half d_vt[(size_t)HH*BS];     // V transposed: [d][token]
__device__ __half d_x[(size_t)BS*HH];      // fp16 X
__device__ __half d_w[(size_t)3*HH*HH];    // fp16 W^T (per z: [n][k])
__device__ float  d_g[BS];
__device__ float  d_p[BS];
__device__ int    d_perm[BS];              // wide-first query order per batch
__device__ float  d_po[(size_t)2*BH*SS*HD];  // split-j partial O (unnormalized)
__device__ float  d_pm[(size_t)2*BH*SS];     // split-j partial max
__device__ float  d_pl[(size_t)2*BH*SS];     // split-j partial sum

// ---------------------------------------------------------------------------
// helpers
// ---------------------------------------------------------------------------
__device__ __forceinline__ void cp16(uint32_t dst, const void* src){
    asm volatile("cp.async.cg.shared.global [%0], [%1], 16;" :: "r"(dst), "l"(src));
}
__device__ __forceinline__ void cp_commit(){ asm volatile("cp.async.commit_group;"); }
template<int N> __device__ __forceinline__ void cp_wait(){
    asm volatile("cp.async.wait_group %0;" :: "n"(N));
}
__device__ __forceinline__ void mma16(float* c, const uint32_t* a, const uint32_t* b){
    asm volatile("mma.sync.aligned.m16n8k16.row.col.f32.f16.f16.f32 "
        "{%0,%1,%2,%3}, {%4,%5,%6,%7}, {%8,%9}, {%0,%1,%2,%3};"
        : "+f"(c[0]),"+f"(c[1]),"+f"(c[2]),"+f"(c[3])
        : "r"(a[0]),"r"(a[1]),"r"(a[2]),"r"(a[3]), "r"(b[0]),"r"(b[1]));
}
__device__ __forceinline__ void ldsm4(uint32_t* d, uint32_t addr){
    asm volatile("ldmatrix.sync.aligned.m8n8.x4.shared.b16 {%0,%1,%2,%3}, [%4];"
        : "=r"(d[0]),"=r"(d[1]),"=r"(d[2]),"=r"(d[3]) : "r"(addr));
}
__device__ __forceinline__ uint32_t packh2(float a, float b){
    __half2 h = __floats2half2_rn(a, b);
    return *reinterpret_cast<uint32_t*>(&h);
}

// ---------------------------------------------------------------------------
// Merged prep: blocks [0,3072) transpose-convert Wq|Wk|Wv to fp16 W^T;
// blocks [3072,7168) run the gate (+fp16 X convert). Independent work,
// one launch, parallel across SMs.
// ---------------------------------------------------------------------------
__global__ __launch_bounds__(256) void prep_kernel(
    const float* __restrict__ Wq, const float* __restrict__ Wk,
    const float* __restrict__ Wv, __half* __restrict__ w,
    const float* __restrict__ X, const float* __restrict__ Wg,
    const float* __restrict__ bg,
    float* __restrict__ g, float* __restrict__ p, __half* __restrict__ xh)
{
    __shared__ float ts[32][33];
    __shared__ float red[256];
    const int bid = blockIdx.x;
    const int tid = threadIdx.x;
    if (bid < 3*1024){
        const int z = bid >> 10, rem = bid & 1023;
        const int n0 = (rem & 31)*32, k0 = (rem >> 5)*32;
        const float* W = (z == 0) ? Wq : (z == 1) ? Wk : Wv;
        const int tx = tid & 31, ty = tid >> 5;
        #pragma unroll
        for (int yy = 0; yy < 4; yy++){
            int k = k0 + ty + yy*8;
            ts[ty + yy*8][tx] = W[(size_t)k*HH + n0 + tx];
        }
        __syncthreads();
        #pragma unroll
        for (int yy = 0; yy < 4; yy++){
            int n = n0 + ty + yy*8;
            w[(size_t)z*HH*HH + (size_t)n*HH + k0 + tx] = __float2half_rn(ts[tx][ty + yy*8]);
        }
    } else {
        const int row = bid - 3072;
        float4 xv = *(const float4*)(X + (size_t)row*HH + tid*4);
        float4 wv = *(const float4*)(Wg + tid*4);
        uint2 o = { packh2(xv.x, xv.y), packh2(xv.z, xv.w) };
        *(uint2*)(xh + (size_t)row*HH + tid*4) = o;
        float s = xv.x*wv.x + xv.y*wv.y + xv.z*wv.z + xv.w*wv.w;
        red[tid] = s; __syncthreads();
        for (int off = 128; off > 0; off >>= 1){
            if (tid < off) red[tid] += red[tid+off];
            __syncthreads();
        }
        if (tid == 0){
            float z2 = red[0] + bg[0];
            float gg = 1.f / (1.f + expf(-z2));
            g[row] = gg;
            p[row] = powf((float)(SS-2), 1.f - gg);
        }
    }
}

// ---------------------------------------------------------------------------
// Query ordering: WIDE-FIRST stable counting sort into 4 pi-buckets per batch.
// ---------------------------------------------------------------------------
__global__ __launch_bounds__(256) void order_kernel(const float* __restrict__ p,
                                                    int* __restrict__ perm){
    const int b = blockIdx.x, tid = threadIdx.x;
    const float* pb = p + (size_t)b*SS;
    __shared__ uint8_t bk[SS];
    __shared__ int sc[1024];
    int myc[4] = {0,0,0,0};
    #pragma unroll
    for (int e = 0; e < 8; e++){
        int i = tid*8 + e;
        float pi = pb[i];
        int k = (pi >= 800.f) ? 0 : (pi >= 288.f) ? 1 : (pi >= 96.f) ? 2 : 3;
        bk[i] = (uint8_t)k; myc[k]++;
    }
    #pragma unroll
    for (int k = 0; k < 4; k++) sc[k*256 + tid] = myc[k];
    __syncthreads();
    for (int off = 1; off < 1024; off <<= 1){
        int v[4];
        #pragma unroll
        for (int k = 0; k < 4; k++){
            int idx = k*256 + tid;
            v[k] = (idx >= off) ? sc[idx - off] : 0;
        }
        __syncthreads();
        #pragma unroll
        for (int k = 0; k < 4; k++) sc[k*256 + tid] += v[k];
        __syncthreads();
    }
    int base[4];
    #pragma unroll
    for (int k = 0; k < 4; k++) base[k] = sc[k*256 + tid] - myc[k];
    #pragma unroll
    for (int e = 0; e < 8; e++){
        int i = tid*8 + e;
        int k = bk[i];
        perm[(size_t)b*SS + base[k]++] = i;
    }
}

// ---------------------------------------------------------------------------
// Merged fp16 QKV projection: ldmatrix fragments, BK=64, 3-stage pipeline.
// ---------------------------------------------------------------------------
#define PSTR 72
#define NSTG 3

__global__ __launch_bounds__(256, 2) void gemm_proj(
    const __half* __restrict__ A, const __half* __restrict__ Wall,
    const float* __restrict__ b0, const float* __restrict__ b1,
    const float* __restrict__ b2,
    __half* __restrict__ C0, __half* __restrict__ C1, __half* __restrict__ Vt)
{
    const int z = blockIdx.z;
    const __half* Bp = Wall + (size_t)z*HH*HH;
    const float* bias = (z == 0) ? b0 : (z == 1) ? b1 : b2;

    extern __shared__ __half smh[];
    const int tid = threadIdx.x, lane = tid & 31, wid = tid >> 5;
    const int wm = wid >> 2, wn = wid & 3;
    const int gq = lane & 3, gr = lane >> 2;

    const int iBase = blockIdx.y * 128;
    const int jBase = blockIdx.x * 128;

    float acc[4][4][4] = {};

    auto loadTile = [&](int s, int kk){
        __half* As = smh + (size_t)s*2*128*PSTR;
        __half* Bs = As + 128*PSTR;
        uint32_t ab = (uint32_t)__cvta_generic_to_shared(As);
        uint32_t bb = (uint32_t)__cvta_generic_to_shared(Bs);
        #pragma unroll
        for (int i = 0; i < 4; i++){
            int f = tid + i*256;
            int r = f >> 3, c8 = (f & 7) * 8;
            cp16(ab + (uint32_t)(r*PSTR + c8)*2u, A + (size_t)(iBase + r)*HH + kk + c8);
        }
        #pragma unroll
        for (int i = 0; i < 4; i++){
            int f = tid + i*256;
            int n = f >> 3, c8 = (f & 7) * 8;
            cp16(bb + (uint32_t)(n*PSTR + c8)*2u, Bp + (size_t)(jBase + n)*HH + kk + c8);
        }
    };

    const int arow = lane & 15;
    const int acol = (lane >> 4) * 8;
    const int brow = lane & 7;
    const int bcol = (lane >> 3) * 8;

    loadTile(0, 0); cp_commit();
    loadTile(1, 64); cp_commit();

    const int nK = HH / 64;
    for (int kt = 0; kt < nK; kt++){
        const int cur = kt % NSTG;
        if (kt + 1 < nK) cp_wait<1>(); else cp_wait<0>();
        __syncthreads();
        if (kt + 2 < nK){ loadTile((kt + 2) % NSTG, (kt + 2)*64); cp_commit(); }

        uint32_t abase = (uint32_t)__cvta_generic_to_shared(smh + (size_t)cur*2*128*PSTR);
        uint32_t bbase = abase + 128*PSTR*2;
        #pragma unroll
        for (int kp = 0; kp < 2; kp++){
            uint32_t bfp[4][4];
            #pragma unroll
            for (int nt = 0; nt < 4; nt++){
                uint32_t addr = bbase +
                    (uint32_t)((wn*32 + nt*8 + brow)*PSTR + kp*32 + bcol)*2u;
                ldsm4(bfp[nt], addr);
            }
            #pragma unroll
            for (int k2 = 0; k2 < 2; k2++){
                uint32_t af[4][4];
                #pragma unroll
                for (int mt = 0; mt < 4; mt++){
                    uint32_t addr = abase +
                        (uint32_t)((wm*64 + mt*16 + arow)*PSTR + kp*32 + k2*16 + acol)*2u;
                    ldsm4(af[mt], addr);
                }
                #pragma unroll
                for (int mt = 0; mt < 4; mt++)
                    #pragma unroll
                    for (int nt = 0; nt < 4; nt++)
                        mma16(acc[mt][nt], af[mt], &bfp[nt][2*k2]);
            }
        }
    }

    #pragma unroll
    for (int mt = 0; mt < 4; mt++){
        int r0 = iBase + wm*64 + mt*16 + gr;
        int r1 = r0 + 8;
        #pragma unroll
        for (int nt = 0; nt < 4; nt++){
            int c0 = jBase + wn*32 + nt*8 + 2*gq;
            float bb0 = __ldg(bias + c0), bb1 = __ldg(bias + c0 + 1);
            float v0 = acc[mt][nt][0] + bb0, v1 = acc[mt][nt][1] + bb1;
            float v2 = acc[mt][nt][2] + bb0, v3 = acc[mt][nt][3] + bb1;
            if (z == 2){
                Vt[(size_t)c0*BS + r0]     = __float2half_rn(v0);
                Vt[(size_t)(c0+1)*BS + r0] = __float2half_rn(v1);
                Vt[(size_t)c0*BS + r1]     = __float2half_rn(v2);
                Vt[(size_t)(c0+1)*BS + r1] = __float2half_rn(v3);
            } else {
                __half* C = (z == 0) ? C0 : C1;
                uint32_t p0 = packh2(v0, v1), p1 = packh2(v2, v3);
                *(uint32_t*)(C + (size_t)r0*HH + c0) = p0;
                *(uint32_t*)(C + (size_t)r1*HH + c0) = p1;
            }
        }
    }
}

// ---------------------------------------------------------------------------
// Split-KV fused attention: each CTA handles HALF of its band's j-tiles,
// writing unnormalized partial O + per-row (m, l). Grid (bh, half, itile)
// so wide itiles (both halves) launch first. combine_kernel merges halves.
// ---------------------------------------------------------------------------
#define QSTR 72
#define JT   64
#define NJT  (SS/JT)

__device__ __forceinline__ float penexp(float om, float gi, float pi, int i,
                                        float gj, int j, float se){
    float res = om * fmaxf(om - gj, 0.f) + gi * fminf(om + gj, 1.f);
    float scope = fminf(fmaxf(pi + 2.f - fabsf((float)(i - j)), 1e-32f), 1.f);
    float pen = fmaxf(res * scope, 1e-32f);
    return pen * __expf(se);
}

__global__ __launch_bounds__(256, 2) void attn_fused(
    const __half* __restrict__ Q, const __half* __restrict__ Kg,
    const __half* __restrict__ Vt, const float* __restrict__ g,
    const float* __restrict__ p, const int* __restrict__ perm,
    float* __restrict__ po, float* __restrict__ pm, float* __restrict__ pl)
{
    const int bh = blockIdx.x, b = bh >> 4, h = bh & 15;
    const int half = blockIdx.y;
    const int iBase = blockIdx.z * 128;
    const int tid = threadIdx.x, lane = tid & 31, wid = tid >> 5;

    extern __shared__ __half smh[];
    __half* Qs  = smh;
    __half* Ks0 = Qs  + 128*QSTR;
    __half* Vs0 = Ks0 + 2*JT*QSTR;
    float*  gs  = (float*)(Vs0 + 2*JT*QSTR);
    __shared__ int bandLo[8], bandHi[8];

    const __half* Qp = Q  + (size_t)b*SS*HH + h*HD;
    const __half* Kp = Kg + (size_t)b*SS*HH + h*HD;
    const int* pmr = perm + (size_t)b*SS;

    {
        uint32_t qb = (uint32_t)__cvta_generic_to_shared(Qs);
        #pragma unroll
        for (int l = 0; l < 4; l++){
            int f = tid + l*256;
            int r = f >> 3, c8 = (f & 7) * 8;
            int pr = __ldg(pmr + iBase + r);
            cp16(qb + (uint32_t)(r*QSTR + c8)*2u, Qp + (size_t)pr*HH + c8);
        }
        uint32_t gb = (uint32_t)__cvta_generic_to_shared(gs);
        #pragma unroll
        for (int l = 0; l < 2; l++){
            int f = tid + l*256;
            cp16(gb + (uint32_t)f*16u, g + (size_t)b*SS + f*4);
        }
        cp_commit();
    }
    auto loadK = [&](int s, int j0){
        uint32_t kb = (uint32_t)__cvta_generic_to_shared(Ks0 + s*JT*QSTR);
        #pragma unroll
        for (int l = 0; l < 2; l++){
            int f = tid + l*256;
            int r = f >> 3, c8 = (f & 7) * 8;
            cp16(kb + (uint32_t)(r*QSTR + c8)*2u, Kp + (size_t)(j0 + r)*HH + c8);
        }
    };
    auto loadV = [&](int s, int j0){
        uint32_t vb = (uint32_t)__cvta_generic_to_shared(Vs0 + s*JT*QSTR);
        #pragma unroll
        for (int l = 0; l < 2; l++){
            int f = tid + l*256;
            int d = f >> 3, c8 = (f & 7) * 8;
            cp16(vb + (uint32_t)(d*QSTR + c8)*2u,
                 Vt + (size_t)(h*HD + d)*BS + b*SS + j0 + c8);
        }
    };

    const int gq = lane & 3, gr = lane >> 2;
    const int lr0 = wid*16 + gr;
    const int lr1 = lr0 + 8;
    const int ri0 = __ldg(pmr + iBase + lr0);
    const int ri1 = __ldg(pmr + iBase + lr1);
    const float gi0 = __ldg(g + (size_t)b*SS + ri0);
    const float gi1 = __ldg(g + (size_t)b*SS + ri1);
    const float pi0 = __ldg(p + (size_t)b*SS + ri0);
    const float pi1 = __ldg(p + (size_t)b*SS + ri1);
    const float om0 = 1.f - gi0, om1 = 1.f - gi1;

    // per-warp band
    float wlo = fminf((float)ri0 - pi0, (float)ri1 - pi1);
    float whi = fmaxf((float)ri0 + pi0, (float)ri1 + pi1);
    #pragma unroll
    for (int off = 16; off > 0; off >>= 1){
        wlo = fminf(wlo, __shfl_xor_sync(0xffffffffu, wlo, off));
        whi = fmaxf(whi, __shfl_xor_sync(0xffffffffu, whi, off));
    }
    const int blo = (int)floorf(wlo) - 3;
    const int bhi = (int)ceilf(whi) + 3;

    // CTA band -> tile range -> this CTA's half
    if (lane == 0){ bandLo[wid] = blo; bandHi[wid] = bhi; }
    __syncthreads();
    int cLo = bandLo[0], cHi = bandHi[0];
    #pragma unroll
    for (int wI = 1; wI < 8; wI++){
        cLo = min(cLo, bandLo[wI]); cHi = max(cHi, bandHi[wI]);
    }
    const int jtLo = (cLo <= 0) ? 0 : min(NJT-1, cLo / JT);
    const int jtHi = min(NJT-1, max(0, cHi) / JT);
    const int nTiles = jtHi - jtLo + 1;
    const int jtMid = jtLo + (nTiles + 1) / 2;    // ceil split; half0 nonempty
    const int myLo  = (half == 0) ? jtLo  : jtMid;
    const int myEnd = (half == 0) ? jtMid : jtHi + 1;

    float m0 = -1e30f, m1 = -1e30f, l0 = 0.f, l1 = 0.f;
    float oacc[8][4] = {};

    if (myLo < myEnd){
        loadK(0, myLo*JT); loadV(0, myLo*JT); cp_commit();

        for (int jt = myLo; jt < myEnd; jt++){
            const int cur = (jt - myLo) & 1;
            if (jt + 1 < myEnd){
                loadK(cur ^ 1, (jt+1)*JT); loadV(cur ^ 1, (jt+1)*JT);
                cp_commit(); cp_wait<1>();
            } else {
                cp_wait<0>();
            }
            __syncthreads();
            const int jBase = jt*JT;
            const bool active = (jBase + JT - 1 >= blo) && (jBase <= bhi);
            if (active){
                const __half* Ks = Ks0 + cur*JT*QSTR;
                const __half* Vs = Vs0 + cur*JT*QSTR;

                float sacc[8][4];
                #pragma unroll
                for (int nt = 0; nt < 8; nt++){
                    sacc[nt][0]=0.f; sacc[nt][1]=0.f; sacc[nt][2]=0.f; sacc[nt][3]=0.f;
                }
                #pragma unroll
                for (int ks = 0; ks < 4; ks++){
                    const int k0 = ks*16 + 2*gq;
                    uint32_t af[4];
                    af[0] = *(const uint32_t*)&Qs[lr0*QSTR + k0];
                    af[1] = *(const uint32_t*)&Qs[lr1*QSTR + k0];
                    af[2] = *(const uint32_t*)&Qs[lr0*QSTR + k0 + 8];
                    af[3] = *(const uint32_t*)&Qs[lr1*QSTR + k0 + 8];
                    #pragma unroll
                    for (int nt = 0; nt < 8; nt++){
                        const int n = nt*8 + gr;
                        uint32_t bf[2];
                        bf[0] = *(const uint32_t*)&Ks[n*QSTR + k0];
                        bf[1] = *(const uint32_t*)&Ks[n*QSTR + k0 + 8];
                        mma16(sacc[nt], af, bf);
                    }
                }

                float tm0 = -1e30f, tm1 = -1e30f;
                #pragma unroll
                for (int nt = 0; nt < 8; nt++){
                    tm0 = fmaxf(tm0, fmaxf(sacc[nt][0], sacc[nt][1]));
                    tm1 = fmaxf(tm1, fmaxf(sacc[nt][2], sacc[nt][3]));
                }
                tm0 = fmaxf(tm0, __shfl_xor_sync(0xffffffffu, tm0, 1));
                tm0 = fmaxf(tm0, __shfl_xor_sync(0xffffffffu, tm0, 2));
                tm1 = fmaxf(tm1, __shfl_xor_sync(0xffffffffu, tm1, 1));
                tm1 = fmaxf(tm1, __shfl_xor_sync(0xffffffffu, tm1, 2));
                tm0 *= 0.125f; tm1 *= 0.125f;
                const float m0n = fmaxf(m0, tm0), m1n = fmaxf(m1, tm1);
                const float f0 = __expf(m0 - m0n), f1 = __expf(m1 - m1n);
                m0 = m0n; m1 = m1n;
                l0 *= f0; l1 *= f1;
                #pragma unroll
                for (int dn = 0; dn < 8; dn++){
                    oacc[dn][0] *= f0; oacc[dn][1] *= f0;
                    oacc[dn][2] *= f1; oacc[dn][3] *= f1;
                }
                float rs0 = 0.f, rs1 = 0.f;
                #pragma unroll
                for (int nt = 0; nt < 8; nt++){
                    const int j0 = jBase + nt*8 + 2*gq;
                    const int j1 = j0 + 1;
                    const float gj0 = gs[j0], gj1 = gs[j1];
                    float t00 = penexp(om0, gi0, pi0, ri0, gj0, j0, sacc[nt][0]*0.125f - m0);
                    float t01 = penexp(om0, gi0, pi0, ri0, gj1, j1, sacc[nt][1]*0.125f - m0);
                    float t10 = penexp(om1, gi1, pi1, ri1, gj0, j0, sacc[nt][2]*0.125f - m1);
                    float t11 = penexp(om1, gi1, pi1, ri1, gj1, j1, sacc[nt][3]*0.125f - m1);
                    sacc[nt][0] = t00; sacc[nt][1] = t01;
                    sacc[nt][2] = t10; sacc[nt][3] = t11;
                    rs0 += t00 + t01; rs1 += t10 + t11;
                }
                rs0 += __shfl_xor_sync(0xffffffffu, rs0, 1);
                rs0 += __shfl_xor_sync(0xffffffffu, rs0, 2);
                rs1 += __shfl_xor_sync(0xffffffffu, rs1, 1);
                rs1 += __shfl_xor_sync(0xffffffffu, rs1, 2);
                l0 += rs0; l1 += rs1;

                #pragma unroll
                for (int kc = 0; kc < 4; kc++){
                    uint32_t af[4];
                    af[0] = packh2(sacc[2*kc][0],   sacc[2*kc][1]);
                    af[1] = packh2(sacc[2*kc][2],   sacc[2*kc][3]);
                    af[2] = packh2(sacc[2*kc+1][0], sacc[2*kc+1][1]);
                    af[3] = packh2(sacc[2*kc+1][2], sacc[2*kc+1][3]);
                    const int kb = kc*16 + 2*gq;
                    #pragma unroll
                    for (int dn = 0; dn < 8; dn++){
                        const int d0 = dn*8 + gr;
                        uint32_t bf[2];
                        bf[0] = *(const uint32_t*)&Vs[d0*QSTR + kb];
                        bf[1] = *(const uint32_t*)&Vs[d0*QSTR + kb + 8];
                        mma16(oacc[dn], af, bf);
                    }
                }
            }
            __syncthreads();
        }
    } else {
        cp_wait<0>();   // drain prologue Q/gs group
    }

    // epilogue: unnormalized partials + (m, l), indexed by original row
    const size_t base = (size_t)(half*BH + bh)*SS;
    #pragma unroll
    for (int dn = 0; dn < 8; dn++){
        const int c0 = dn*8 + 2*gq;
        *(float2*)(po + (base + ri0)*HD + c0) = make_float2(oacc[dn][0], oacc[dn][1]);
        *(float2*)(po + (base + ri1)*HD + c0) = make_float2(oacc[dn][2], oacc[dn][3]);
    }
    if (gq == 0){
        pm[base + ri0] = m0; pl[base + ri0] = l0;
        pm[base + ri1] = m1; pl[base + ri1] = l1;
    }
}

// ---------------------------------------------------------------------------
// Combine: out = (e^{m0-M} O0 + e^{m1-M} O1) / (e^{m0-M} l0 + e^{m1-M} l1)
// One warp per (bh, row); 8 rows per block.
// ---------------------------------------------------------------------------
__global__ __launch_bounds__(256) void combine_kernel(
    const float* __restrict__ po, const float* __restrict__ pm,
    const float* __restrict__ pl, float* __restrict__ out)
{
    const int idx = blockIdx.x*8 + (threadIdx.x >> 5);   // [0, BH*SS)
    const int lane = threadIdx.x & 31;
    const int bh = idx >> 11, i = idx & (SS - 1);
    const int b = bh >> 4, h = bh & 15;
    const float m0 = pm[idx],            m1 = pm[BH*SS + idx];
    const float l0 = pl[idx],            l1 = pl[BH*SS + idx];
    const float M  = fmaxf(m0, m1);
    const float w0 = __expf(m0 - M), w1 = __expf(m1 - M);
    const float inv = 1.f / fmaxf(w0*l0 + w1*l1, 1e-37f);
    float2 a = *(const float2*)(po + (size_t)idx*HD + lane*2);
    float2 c = *(const float2*)(po + (size_t)(BH*SS + idx)*HD + lane*2);
    float* op = out + ((size_t)b*SS + i)*HH + h*HD + lane*2;
    float2 r = { (w0*a.x + w1*c.x)*inv, (w0*a.y + w1*c.y)*inv };
    *(float2*)op = r;
}

// ---------------------------------------------------------------------------
extern "C" void kernel_launch(void* const* d_in, const int* in_sizes, int n_in,
                              void* d_out, int out_size) {
    const float* X  = (const float*)d_in[0];
    const float* Wq = (const float*)d_in[1];
    const float* bq = (const float*)d_in[2];
    const float* Wk = (const float*)d_in[3];
    const float* bk = (const float*)d_in[4];
    const float* Wv = (const float*)d_in[5];
    const float* bv = (const float*)d_in[6];
    const float* Wg = (const float*)d_in[7];
    const float* bg = (const float*)d_in[8];
    float* out = (float*)d_out;

    __half *q, *k, *vt, *x, *w;
    float *g, *p, *po, *pmb, *plb;
    int *perm;
    cudaGetSymbolAddress((void**)&q,  d_q);
    cudaGetSymbolAddress((void**)&k,  d_k);
    cudaGetSymbolAddress((void**)&vt, d_vt);
    cudaGetSymbolAddress((void**)&x,  d_x);
    cudaGetSymbolAddress((void**)&w,  d_w);
    cudaGetSymbolAddress((void**)&g,  d_g);
    cudaGetSymbolAddress((void**)&p,  d_p);
    cudaGetSymbolAddress((void**)&perm, d_perm);
    cudaGetSymbolAddress((void**)&po,  d_po);
    cudaGetSymbolAddress((void**)&pmb, d_pm);
    cudaGetSymbolAddress((void**)&plb, d_pl);

    constexpr int SM_PROJ = NSTG*2*128*PSTR*2;                               // 110592
    constexpr int SM_ATTN = (128*QSTR + 2*JT*QSTR + 2*JT*QSTR)*2 + SS*4;     // 63488
    cudaFuncSetAttribute(gemm_proj,
                         cudaFuncAttributeMaxDynamicSharedMemorySize, SM_PROJ);
    cudaFuncSetAttribute(attn_fused,
                         cudaFuncAttributeMaxDynamicSharedMemorySize, SM_ATTN);

    // merged prep (tconv + gate), then ordering
    prep_kernel<<<3*1024 + BS, 256>>>(Wq, Wk, Wv, w, X, Wg, bg, g, p, x);
    order_kernel<<<BB, 256>>>(p, perm);

    // merged QKV projection
    dim3 gp(HH/128, BS/128, 3);   // (8, 32, 3)
    gemm_proj<<<gp, 256, SM_PROJ>>>(x, w, bq, bk, bv, q, k, vt);

    // split-KV attn: (bh, half, itile) -> wide itiles (both halves) first
    dim3 ga(BH, 2, SS/128);       // (32, 2, 16)
    attn_fused<<<ga, 256, SM_ATTN>>>(q, k, vt, g, p, perm, po, pmb, plb);

    // merge halves
    combine_kernel<<<BH*SS/8, 256>>>(po, pmb, plb, out);
}